// round 14
// speedup vs baseline: 5.6115x; 1.1762x over previous
#include <cuda_runtime.h>
#include <cuda_fp16.h>
#include <math.h>
#include <stdint.h>

// Problem constants
#define NL 4
#define B_ 2
#define L_ 2048
#define S_ 256
#define D_ 1024
#define F_ 4096
#define H_ 16
#define HD_ 64
#define M_ (B_*L_)          // 4096 token rows

// Weight region sizes (elements) and offsets in the concatenated split buffer
#define SZ_WQKV ((size_t)3*D_*D_)
#define SZ_WO   ((size_t)D_*D_)
#define SZ_WQC  ((size_t)D_*D_)
#define SZ_WKVC ((size_t)2*D_*D_)
#define SZ_WOC  ((size_t)D_*D_)
#define SZ_WGU  ((size_t)2*F_*D_)     // interleaved [g0,u0,g1,u1,...] per layer
#define SZ_WD   ((size_t)D_*F_)
static const size_t O_WQKV = 0;
static const size_t O_WO   = O_WQKV + NL*SZ_WQKV;
static const size_t O_WQC  = O_WO   + NL*SZ_WO;
static const size_t O_WKVC = O_WQC  + NL*SZ_WQC;
static const size_t O_WOC  = O_WKVC + NL*SZ_WKVC;
static const size_t O_WGU  = O_WOC  + NL*SZ_WOC;
static const size_t O_WD   = O_WGU  + NL*SZ_WGU;
#define WTOT (O_WD + NL*SZ_WD)

// ---------------------------------------------------------------------------
// Scratch (device globals; no allocations allowed)
// ---------------------------------------------------------------------------
__device__ float g_x  [M_*D_];
__device__ float g_cos[L_*32];
__device__ float g_sin[L_*32];

__device__ __half g_h_hi [M_*D_],  g_h_lo [M_*D_];
__device__ __half g_at_hi[M_*D_],  g_at_lo[M_*D_];
__device__ __half g_co_hi[M_*D_],  g_co_lo[M_*D_];
__device__ __half g_gs_hi[M_*F_],  g_gs_lo[M_*F_];
__device__ __half g_m_hi [B_*S_*D_], g_m_lo[B_*S_*D_];
__device__ __half g_w_hi[WTOT], g_w_lo[WTOT];

// attention-layout split buffers: [B][H][L][64] (self q/k/v; cross q reuses q)
#define ATN ((size_t)B_*H_*L_*HD_)
__device__ __half g_sqh[ATN], g_sql[ATN];
__device__ __half g_skh[ATN], g_skl[ATN];
__device__ __half g_svh[ATN], g_svl[ATN];

// per-layer cross K/V: [NL][B][H][S][64]
#define CATN ((size_t)B_*H_*S_*HD_)
__device__ __half g_ckh[NL*CATN], g_ckl[NL*CATN];
__device__ __half g_cvh[NL*CATN], g_cvl[NL*CATN];

// ---------------------------------------------------------------------------
// f16 split helpers (residual 2^-22 relative vs bf16's 2^-18)
// ---------------------------------------------------------------------------
__device__ __forceinline__ void split1(float v, unsigned short& h, unsigned short& l) {
    __half hb = __float2half_rn(v);
    float r = v - __half2float(hb);
    __half lb = __float2half_rn(r);
    h = __half_as_ushort(hb);
    l = __half_as_ushort(lb);
}
__device__ __forceinline__ void split_pack4(float4 v, uint2& ph, uint2& pl) {
    unsigned short h0,h1,h2,h3,l0,l1,l2,l3;
    split1(v.x,h0,l0); split1(v.y,h1,l1); split1(v.z,h2,l2); split1(v.w,h3,l3);
    ph.x = (uint32_t)h0 | ((uint32_t)h1 << 16);
    ph.y = (uint32_t)h2 | ((uint32_t)h3 << 16);
    pl.x = (uint32_t)l0 | ((uint32_t)l1 << 16);
    pl.y = (uint32_t)l2 | ((uint32_t)l3 << 16);
}

// 4-quad ILP split (exact grids: n4 multiple of 1024)
__global__ void split_k(const float* __restrict__ in, __half* __restrict__ hi,
                        __half* __restrict__ lo) {
    int i = blockIdx.x * 1024 + threadIdx.x;
    float4 v[4];
    #pragma unroll
    for (int j = 0; j < 4; j++) v[j] = ((const float4*)in)[i + 256*j];
    #pragma unroll
    for (int j = 0; j < 4; j++) {
        uint2 ph, pl; split_pack4(v[j], ph, pl);
        ((uint2*)hi)[i + 256*j] = ph;
        ((uint2*)lo)[i + 256*j] = pl;
    }
}

// Interleaving split for GU weights: src row r (256 quads/row) -> dst row 2r+off
__global__ void split_ilv_k(const float* __restrict__ in, __half* __restrict__ hi,
                            __half* __restrict__ lo, int off) {
    int i0 = blockIdx.x * 1024 + threadIdx.x;
    float4 v[4];
    #pragma unroll
    for (int j = 0; j < 4; j++) v[j] = ((const float4*)in)[i0 + 256*j];
    #pragma unroll
    for (int j = 0; j < 4; j++) {
        int i = i0 + 256*j;
        int r = i >> 8, c = i & 255;
        uint2 ph, pl; split_pack4(v[j], ph, pl);
        size_t oi = (size_t)(2*r + off) * 256 + c;
        ((uint2*)hi)[oi] = ph;
        ((uint2*)lo)[oi] = pl;
    }
}

// ---------------------------------------------------------------------------
// RoPE cache
// ---------------------------------------------------------------------------
__global__ void rope_cache_k() {
    int idx = blockIdx.x * blockDim.x + threadIdx.x;
    int l = idx >> 5, i = idx & 31;
    double inv = exp(-log(10000.0) * (double)i / 32.0);
    double f = (double)l * inv;
    g_cos[idx] = (float)cos(f);
    g_sin[idx] = (float)sin(f);
}

// ---------------------------------------------------------------------------
// RMSNorm kernels
// ---------------------------------------------------------------------------
__global__ void rmsnorm_split_k(const float* __restrict__ x, const float* __restrict__ w,
                                __half* __restrict__ hi, __half* __restrict__ lo) {
    int row = blockIdx.x;
    int t = threadIdx.x;
    const float4* xr = (const float4*)(x + (size_t)row * D_);
    float4 v = xr[t];
    float ss = v.x*v.x + v.y*v.y + v.z*v.z + v.w*v.w;
    #pragma unroll
    for (int off = 16; off; off >>= 1) ss += __shfl_xor_sync(0xffffffffu, ss, off);
    __shared__ float red[8];
    if ((t & 31) == 0) red[t >> 5] = ss;
    __syncthreads();
    float tot = red[0]+red[1]+red[2]+red[3]+red[4]+red[5]+red[6]+red[7];
    float rs = rsqrtf(tot * (1.0f / (float)D_) + 1e-6f);
    float4 wv = ((const float4*)w)[t];
    float4 o;
    o.x = v.x * rs * wv.x; o.y = v.y * rs * wv.y;
    o.z = v.z * rs * wv.z; o.w = v.w * rs * wv.w;
    uint2 ph, pl; split_pack4(o, ph, pl);
    ((uint2*)hi)[(size_t)row * 256 + t] = ph;
    ((uint2*)lo)[(size_t)row * 256 + t] = pl;
}

__global__ void rmsnorm_k(const float* __restrict__ x, const float* __restrict__ w,
                          float* __restrict__ o) {
    int row = blockIdx.x;
    int t = threadIdx.x;
    const float4* xr = (const float4*)(x + (size_t)row * D_);
    float4 v = xr[t];
    float ss = v.x*v.x + v.y*v.y + v.z*v.z + v.w*v.w;
    #pragma unroll
    for (int off = 16; off; off >>= 1) ss += __shfl_xor_sync(0xffffffffu, ss, off);
    __shared__ float red[8];
    if ((t & 31) == 0) red[t >> 5] = ss;
    __syncthreads();
    float tot = red[0]+red[1]+red[2]+red[3]+red[4]+red[5]+red[6]+red[7];
    float rs = rsqrtf(tot * (1.0f / (float)D_) + 1e-6f);
    float4 wv = ((const float4*)w)[t];
    float4 out;
    out.x = v.x * rs * wv.x; out.y = v.y * rs * wv.y;
    out.z = v.z * rs * wv.z; out.w = v.w * rs * wv.w;
    ((float4*)(o + (size_t)row * D_))[t] = out;
}

// ---------------------------------------------------------------------------
// mma / ldmatrix helpers (f16)
// ---------------------------------------------------------------------------
__device__ __forceinline__ void mma_f16(float* c, const uint32_t* a, const uint32_t* b) {
    asm volatile(
        "mma.sync.aligned.m16n8k16.row.col.f32.f16.f16.f32 "
        "{%0,%1,%2,%3}, {%4,%5,%6,%7}, {%8,%9}, {%0,%1,%2,%3};"
        : "+f"(c[0]), "+f"(c[1]), "+f"(c[2]), "+f"(c[3])
        : "r"(a[0]), "r"(a[1]), "r"(a[2]), "r"(a[3]), "r"(b[0]), "r"(b[1]));
}
__device__ __forceinline__ void ldsm_x4(uint32_t* r, uint32_t addr) {
    asm volatile("ldmatrix.sync.aligned.m8n8.x4.shared.b16 {%0,%1,%2,%3}, [%4];"
        : "=r"(r[0]), "=r"(r[1]), "=r"(r[2]), "=r"(r[3]) : "r"(addr));
}
__device__ __forceinline__ void ldsm_x4_t(uint32_t* r, uint32_t addr) {
    asm volatile("ldmatrix.sync.aligned.m8n8.x4.trans.shared.b16 {%0,%1,%2,%3}, [%4];"
        : "=r"(r[0]), "=r"(r[1]), "=r"(r[2]), "=r"(r[3]) : "r"(addr));
}
__device__ __forceinline__ uint32_t pack_h16x2(float lo, float hi) {
    return (uint32_t)__half_as_ushort(__float2half_rn(lo)) |
           ((uint32_t)__half_as_ushort(__float2half_rn(hi)) << 16);
}

// ---------------------------------------------------------------------------
// f16 split GEMM (NT), 256x128 CTA tile, warp tile 64x64 (8 warps, 4x2).
// THREE=true:  C = AhWh + AhWl + AlWh  (residual 2^-22)
// THREE=false: C = AhWh + AhWl         (error ~2^-11 of A; GU/Wd only)
// MODE 1: +bias +residual(Rsrc) -> fp32 C   (Wo)
// MODE 2: +residual(Rsrc)       -> fp32 C   (Wo_c 3t, Wd 2t)
// MODE 3: swiglu (interleaved g|u cols) -> f16 hi/lo [M][F]
// MODE 4: attn-q layout, x0.125         -> f16 hi/lo [B][H][L][64]
// MODE 6: QKV: +bias, RoPE on q/k, q x0.125 -> q/k/v f16 hi/lo [B][H][L][64]
// MODE 7: multi-layer cross-KV           -> per-layer k/v [NL][B][H][S][64]
// ---------------------------------------------------------------------------
#define G2STAGE 61440
#define G2_AL   20480
#define G2_B0   40960
#define G2_B1   51200
#define GSMEM   (3*G2STAGE)

template <int MODE, bool THREE>
__global__ void __launch_bounds__(256, 1)
gemm_f16s(const __half* __restrict__ Ah, const __half* __restrict__ Al,
          const __half* __restrict__ Wh, const __half* __restrict__ Wl,
          const float* __restrict__ bias, float* __restrict__ C,
          const float* __restrict__ Rsrc,
          __half* __restrict__ o1h, __half* __restrict__ o1l,
          __half* __restrict__ o2h, __half* __restrict__ o2l,
          __half* __restrict__ o3h, __half* __restrict__ o3l,
          int N, int K) {
    extern __shared__ char smem[];
    const uint32_t sbase = (uint32_t)__cvta_generic_to_shared(smem);
    const int tid  = threadIdx.x;
    const int warp = tid >> 5, lane = tid & 31;
    const int wr = warp >> 1;      // 0..3 : 64-row slab
    const int wc = warp & 1;       // 0..1 : 64-col slab
    const int g  = lane >> 2;
    const int t  = lane & 3;
    const int bm = blockIdx.y, bn = blockIdx.x;

    // cp.async chunk tables: 3072 16B-chunks per stage, 12 per thread
    // chunks i=4..7 are the A-lo array (skipped when !THREE)
    const __half* src[12];
    uint32_t dst[12];
    #pragma unroll
    for (int i = 0; i < 12; i++) {
        int id = tid + (i << 8);
        const __half* bp;
        int grow; uint32_t off; int kc;
        if (id < 2048) {
            int arr = id >> 10, rem = id & 1023;
            int row = rem >> 2; kc = rem & 3;
            bp = arr ? Al : Ah;
            grow = bm * 256 + row;
            off = (uint32_t)(arr * G2_AL + row * 80 + kc * 16);
        } else {
            int id2 = id - 2048;
            int arr = id2 >> 9, rem = id2 & 511;
            int row = rem >> 2; kc = rem & 3;
            bp = arr ? Wl : Wh;
            grow = bn * 128 + row;
            off = (uint32_t)(G2_B0 + arr * 10240 + row * 80 + kc * 16);
        }
        src[i] = bp + (size_t)grow * K + kc * 8;
        dst[i] = off;
    }

    const uint32_t arow = (uint32_t)((wr * 64 + (lane & 15)) * 80 + (lane >> 4) * 16);
    const uint32_t brow = (uint32_t)((wc * 64 + (lane & 7) + ((lane >> 4) << 3)) * 80
                                     + (((lane >> 3) & 1) << 4));

    float acc[4][8][4];
    #pragma unroll
    for (int i = 0; i < 4; i++)
        #pragma unroll
        for (int j = 0; j < 8; j++)
            #pragma unroll
            for (int r = 0; r < 4; r++) acc[i][j][r] = 0.f;

    const int nk = K >> 5;

    #pragma unroll
    for (int st = 0; st < 2; st++) {
        uint32_t s = sbase + st * G2STAGE;
        #pragma unroll
        for (int i = 0; i < 12; i++) {
            if (!THREE && i >= 4 && i < 8) continue;
            const void* p = src[i] + st * 32;
            asm volatile("cp.async.cg.shared.global [%0], [%1], 16;"
                         :: "r"(s + dst[i]), "l"(p) : "memory");
        }
        asm volatile("cp.async.commit_group;" ::: "memory");
    }

    for (int it = 0; it < nk; it++) {
        asm volatile("cp.async.wait_group 1;" ::: "memory");
        __syncthreads();
        uint32_t s = sbase + (uint32_t)(it % 3) * G2STAGE;

        #pragma unroll
        for (int ks = 0; ks < 2; ks++) {
            const uint32_t ko = ks * 32;
            uint32_t af[16], bh[16], bl[16];
            #pragma unroll
            for (int mt = 0; mt < 4; mt++) ldsm_x4(af + 4*mt, s + arow + mt*1280 + ko);
            #pragma unroll
            for (int p = 0; p < 4; p++) ldsm_x4(bh + 4*p, s + G2_B0 + brow + p*1280 + ko);
            #pragma unroll
            for (int p = 0; p < 4; p++) ldsm_x4(bl + 4*p, s + G2_B1 + brow + p*1280 + ko);
            #pragma unroll
            for (int mt = 0; mt < 4; mt++)
                #pragma unroll
                for (int nt = 0; nt < 8; nt++) mma_f16(acc[mt][nt], af + 4*mt, bh + 2*nt);
            #pragma unroll
            for (int mt = 0; mt < 4; mt++)
                #pragma unroll
                for (int nt = 0; nt < 8; nt++) mma_f16(acc[mt][nt], af + 4*mt, bl + 2*nt);
            if (THREE) {
                #pragma unroll
                for (int mt = 0; mt < 4; mt++) ldsm_x4(af + 4*mt, s + G2_AL + arow + mt*1280 + ko);
                #pragma unroll
                for (int mt = 0; mt < 4; mt++)
                    #pragma unroll
                    for (int nt = 0; nt < 8; nt++) mma_f16(acc[mt][nt], af + 4*mt, bh + 2*nt);
            }
        }

        if (it + 2 < nk) {
            uint32_t s2 = sbase + (uint32_t)((it + 2) % 3) * G2STAGE;
            int k0 = (it + 2) * 32;
            #pragma unroll
            for (int i = 0; i < 12; i++) {
                if (!THREE && i >= 4 && i < 8) continue;
                const void* p = src[i] + k0;
                asm volatile("cp.async.cg.shared.global [%0], [%1], 16;"
                             :: "r"(s2 + dst[i]), "l"(p) : "memory");
            }
        }
        asm volatile("cp.async.commit_group;" ::: "memory");
    }

    if (MODE == 6) {
        // QKV epilogue: bias + RoPE (q,k) + split into attention layout.
        const int part = (bn * 128 + wc * 64) >> 10;
        #pragma unroll
        for (int mt = 0; mt < 4; mt++) {
            #pragma unroll
            for (int half = 0; half < 2; half++) {
                int row = bm * 256 + wr * 64 + mt * 16 + g + half * 8;
                int b = row >> 11, ltok = row & (L_ - 1);
                if (part < 2) {
                    #pragma unroll
                    for (int np = 0; np < 4; np++) {
                        int col = bn*128 + wc*64 + np*8 + 2*t;
                        int pcol = col & 1023;
                        int head = pcol >> 6;
                        int i = pcol & 31;
                        float c0 = g_cos[ltok*32 + i],     s0 = g_sin[ltok*32 + i];
                        float c1 = g_cos[ltok*32 + i + 1], s1 = g_sin[ltok*32 + i + 1];
                        float x1a = acc[mt][np  ][half*2+0] + bias[col];
                        float x1b = acc[mt][np  ][half*2+1] + bias[col+1];
                        float x2a = acc[mt][np+4][half*2+0] + bias[col+32];
                        float x2b = acc[mt][np+4][half*2+1] + bias[col+33];
                        float r1a = x1a*c0 - x2a*s0, r2a = x2a*c0 + x1a*s0;
                        float r1b = x1b*c1 - x2b*s1, r2b = x2b*c1 + x1b*s1;
                        __half *oh, *ol;
                        if (part == 0) {
                            r1a *= 0.125f; r1b *= 0.125f; r2a *= 0.125f; r2b *= 0.125f;
                            oh = o1h; ol = o1l;
                        } else { oh = o2h; ol = o2l; }
                        size_t oi = (((size_t)(b*H_ + head)) * L_ + ltok) * HD_ + i;
                        unsigned short h0, l0, h1, l1;
                        split1(r1a, h0, l0); split1(r1b, h1, l1);
                        *(uint32_t*)(oh + oi) = (uint32_t)h0 | ((uint32_t)h1 << 16);
                        *(uint32_t*)(ol + oi) = (uint32_t)l0 | ((uint32_t)l1 << 16);
                        split1(r2a, h0, l0); split1(r2b, h1, l1);
                        *(uint32_t*)(oh + oi + 32) = (uint32_t)h0 | ((uint32_t)h1 << 16);
                        *(uint32_t*)(ol + oi + 32) = (uint32_t)l0 | ((uint32_t)l1 << 16);
                    }
                } else {
                    #pragma unroll
                    for (int nt = 0; nt < 8; nt++) {
                        int col = bn*128 + wc*64 + nt*8 + 2*t;
                        int pcol = col & 1023;
                        int head = pcol >> 6, d = pcol & 63;
                        float c0 = acc[mt][nt][half*2+0] + bias[col];
                        float c1 = acc[mt][nt][half*2+1] + bias[col+1];
                        size_t oi = (((size_t)(b*H_ + head)) * L_ + ltok) * HD_ + d;
                        unsigned short h0, l0, h1, l1;
                        split1(c0, h0, l0); split1(c1, h1, l1);
                        *(uint32_t*)(o3h + oi) = (uint32_t)h0 | ((uint32_t)h1 << 16);
                        *(uint32_t*)(o3l + oi) = (uint32_t)l0 | ((uint32_t)l1 << 16);
                    }
                }
            }
        }
        return;
    }

    #pragma unroll
    for (int mt = 0; mt < 4; mt++) {
        #pragma unroll
        for (int half = 0; half < 2; half++) {
            int row = bm * 256 + wr * 64 + mt * 16 + g + half * 8;
            #pragma unroll
            for (int nt = 0; nt < 8; nt++) {
                int col = bn * 128 + wc * 64 + nt * 8 + 2 * t;
                float c0 = acc[mt][nt][half * 2 + 0];
                float c1 = acc[mt][nt][half * 2 + 1];
                if (MODE <= 2) {
                    float* dstp = C + (size_t)row * N + col;
                    const float* rp = Rsrc + (size_t)row * N + col;
                    if (MODE == 1) { c0 += bias[col]; c1 += bias[col + 1]; }
                    float2 r = *(const float2*)rp;
                    c0 += r.x; c1 += r.y;
                    *(float2*)dstp = make_float2(c0, c1);
                } else if (MODE == 3) {
                    float sg = c0 / (1.0f + expf(-c0)) * c1;
                    unsigned short hh, ll; split1(sg, hh, ll);
                    size_t oi = (size_t)row * F_ + (col >> 1);
                    o1h[oi] = __ushort_as_half(hh);
                    o1l[oi] = __ushort_as_half(ll);
                } else if (MODE == 4) {
                    int b = row >> 11, ltok = row & (L_ - 1);
                    int hd = col >> 6, d = col & 63;
                    size_t oi = (((size_t)(b*H_ + hd)) * L_ + ltok) * HD_ + d;
                    unsigned short h0, l0, h1, l1;
                    split1(c0 * 0.125f, h0, l0); split1(c1 * 0.125f, h1, l1);
                    *(uint32_t*)(o1h + oi) = (uint32_t)h0 | ((uint32_t)h1 << 16);
                    *(uint32_t*)(o1l + oi) = (uint32_t)l0 | ((uint32_t)l1 << 16);
                } else { // MODE 7: multi-layer cross-KV
                    int layer = col >> 11;
                    int c2 = col & 2047;
                    int kv = c2 >> 10;
                    int hd = (c2 >> 6) & 15, d = c2 & 63;
                    int b = row >> 8, stok = row & (S_ - 1);
                    size_t oi = (size_t)layer * CATN
                              + (((size_t)(b*H_ + hd)) * S_ + stok) * HD_ + d;
                    unsigned short h0, l0, h1, l1;
                    split1(c0, h0, l0); split1(c1, h1, l1);
                    __half* ph = kv ? o2h : o1h;
                    __half* pl = kv ? o2l : o1l;
                    *(uint32_t*)(ph + oi) = (uint32_t)h0 | ((uint32_t)h1 << 16);
                    *(uint32_t*)(pl + oi) = (uint32_t)l0 | ((uint32_t)l1 << 16);
                }
            }
        }
    }
}

// ---------------------------------------------------------------------------
// mma.sync flash self-attention (f16). P packed f16 (err 2^-11); P·V uses
// Ph·Vh + Ph·Vl.
// ---------------------------------------------------------------------------
#define AT_ROW  144
#define AT_ARR  (64*AT_ROW)
#define AT_KV0  (2*AT_ARR)
#define AT_STG  (4*AT_ARR)
#define AT_SMEM (2*AT_ARR + 2*AT_STG)

__global__ void __launch_bounds__(128, 2)
self_attn_mma(const __half* __restrict__ Qh, const __half* __restrict__ Ql,
              const __half* __restrict__ Kh, const __half* __restrict__ Kl,
              const __half* __restrict__ Vh, const __half* __restrict__ Vl,
              __half* __restrict__ out_hi, __half* __restrict__ out_lo) {
    extern __shared__ char smraw[];
    const uint32_t sb = (uint32_t)__cvta_generic_to_shared(smraw);
    const int tid = threadIdx.x, warp = tid >> 5, lane = tid & 31;
    const int h = blockIdx.y, b = blockIdx.z;
    const int qbi = (int)(gridDim.x - 1 - blockIdx.x);
    const int qb = qbi * 64;
    const int ntiles = qbi + 1;
    const size_t hb = ((size_t)(b*H_ + h)) * L_;

    #pragma unroll
    for (int i = 0; i < 8; i++) {
        int id = tid + i * 128;
        int arr = id >> 9;
        int rem = id & 511;
        int row = rem >> 3, kc = rem & 7;
        const __half* p = (arr ? Ql : Qh) + (hb + qb + row) * HD_ + kc * 8;
        uint32_t d = sb + (uint32_t)(arr * AT_ARR + row * AT_ROW + kc * 16);
        asm volatile("cp.async.cg.shared.global [%0], [%1], 16;" :: "r"(d), "l"(p) : "memory");
    }
    auto load_kv = [&](int t, int slot) {
        uint32_t base = sb + AT_KV0 + (uint32_t)(slot & 1) * AT_STG;
        int k0 = t * 64;
        #pragma unroll
        for (int i = 0; i < 16; i++) {
            int id = tid + i * 128;
            int arr = id >> 9;
            int rem = id & 511;
            int row = rem >> 3, kc = rem & 7;
            const __half* p = (arr==0?Kh:arr==1?Kl:arr==2?Vh:Vl) + (hb + k0 + row) * HD_ + kc * 8;
            uint32_t d = base + (uint32_t)(arr * AT_ARR + row * AT_ROW + kc * 16);
            asm volatile("cp.async.cg.shared.global [%0], [%1], 16;" :: "r"(d), "l"(p) : "memory");
        }
        asm volatile("cp.async.commit_group;" ::: "memory");
    };
    load_kv(0, 0);
    if (ntiles > 1) load_kv(1, 1);

    uint32_t qh[4][4], ql[4][4];
    float o[8][4];
    #pragma unroll
    for (int i = 0; i < 8; i++)
        #pragma unroll
        for (int j = 0; j < 4; j++) o[i][j] = 0.f;
    float mA = -1e30f, mB = -1e30f, lA = 0.f, lB = 0.f;

    for (int t = 0; t < ntiles; t++) {
        if (t + 1 < ntiles) { asm volatile("cp.async.wait_group 1;" ::: "memory"); }
        else                { asm volatile("cp.async.wait_group 0;" ::: "memory"); }
        __syncthreads();
        if (t == 0) {
            #pragma unroll
            for (int ks = 0; ks < 4; ks++) {
                uint32_t a = sb + (uint32_t)((warp*16 + (lane & 15)) * AT_ROW + ks*32 + (lane >> 4) * 16);
                ldsm_x4(qh[ks], a);
                ldsm_x4(ql[ks], a + AT_ARR);
            }
        }
        const uint32_t kvb = sb + AT_KV0 + (uint32_t)(t & 1) * AT_STG;

        float s[8][4];
        #pragma unroll
        for (int i = 0; i < 8; i++)
            #pragma unroll
            for (int j = 0; j < 4; j++) s[i][j] = 0.f;
        #pragma unroll
        for (int ks = 0; ks < 4; ks++) {
            uint32_t kh4[4][4], kl4[4][4];
            #pragma unroll
            for (int ntp = 0; ntp < 4; ntp++) {
                uint32_t a = kvb + (uint32_t)((ntp*16 + (lane & 7) + ((lane >> 4) << 3)) * AT_ROW
                                              + ks*32 + (((lane >> 3) & 1) << 4));
                ldsm_x4(kh4[ntp], a);
                ldsm_x4(kl4[ntp], a + AT_ARR);
            }
            #pragma unroll
            for (int ntp = 0; ntp < 4; ntp++) {
                mma_f16(s[2*ntp],   qh[ks], kh4[ntp]);
                mma_f16(s[2*ntp+1], qh[ks], kh4[ntp] + 2);
                mma_f16(s[2*ntp],   qh[ks], kl4[ntp]);
                mma_f16(s[2*ntp+1], qh[ks], kl4[ntp] + 2);
                mma_f16(s[2*ntp],   ql[ks], kh4[ntp]);
                mma_f16(s[2*ntp+1], ql[ks], kh4[ntp] + 2);
            }
        }
        if (t == ntiles - 1) {
            int rA = qb + warp*16 + (lane >> 2);
            int cbase = t*64 + 2*(lane & 3);
            #pragma unroll
            for (int nt = 0; nt < 8; nt++) {
                int c0 = cbase + nt*8, c1 = c0 + 1;
                if (c0 > rA)     s[nt][0] = -1e30f;
                if (c1 > rA)     s[nt][1] = -1e30f;
                if (c0 > rA + 8) s[nt][2] = -1e30f;
                if (c1 > rA + 8) s[nt][3] = -1e30f;
            }
        }
        float tmA = -1e30f, tmB = -1e30f;
        #pragma unroll
        for (int nt = 0; nt < 8; nt++) {
            tmA = fmaxf(tmA, fmaxf(s[nt][0], s[nt][1]));
            tmB = fmaxf(tmB, fmaxf(s[nt][2], s[nt][3]));
        }
        tmA = fmaxf(tmA, __shfl_xor_sync(0xffffffffu, tmA, 1));
        tmA = fmaxf(tmA, __shfl_xor_sync(0xffffffffu, tmA, 2));
        tmB = fmaxf(tmB, __shfl_xor_sync(0xffffffffu, tmB, 1));
        tmB = fmaxf(tmB, __shfl_xor_sync(0xffffffffu, tmB, 2));
        float nmA = fmaxf(mA, tmA), nmB = fmaxf(mB, tmB);
        float scA = __expf(mA - nmA), scB = __expf(mB - nmB);
        float tsA = 0.f, tsB = 0.f;
        #pragma unroll
        for (int nt = 0; nt < 8; nt++) {
            s[nt][0] = __expf(s[nt][0] - nmA);
            s[nt][1] = __expf(s[nt][1] - nmA);
            s[nt][2] = __expf(s[nt][2] - nmB);
            s[nt][3] = __expf(s[nt][3] - nmB);
            tsA += s[nt][0] + s[nt][1];
            tsB += s[nt][2] + s[nt][3];
        }
        tsA += __shfl_xor_sync(0xffffffffu, tsA, 1);
        tsA += __shfl_xor_sync(0xffffffffu, tsA, 2);
        tsB += __shfl_xor_sync(0xffffffffu, tsB, 1);
        tsB += __shfl_xor_sync(0xffffffffu, tsB, 2);
        lA = lA * scA + tsA;
        lB = lB * scB + tsB;
        #pragma unroll
        for (int nt = 0; nt < 8; nt++) {
            o[nt][0] *= scA; o[nt][1] *= scA;
            o[nt][2] *= scB; o[nt][3] *= scB;
        }
        mA = nmA; mB = nmB;
        #pragma unroll
        for (int kk = 0; kk < 4; kk++) {
            uint32_t ph[4];
            ph[0] = pack_h16x2(s[2*kk][0],   s[2*kk][1]);
            ph[1] = pack_h16x2(s[2*kk][2],   s[2*kk][3]);
            ph[2] = pack_h16x2(s[2*kk+1][0], s[2*kk+1][1]);
            ph[3] = pack_h16x2(s[2*kk+1][2], s[2*kk+1][3]);
            #pragma unroll
            for (int ntp = 0; ntp < 4; ntp++) {
                uint32_t vh4[4], vl4[4];
                uint32_t a = kvb + 2*AT_ARR + (uint32_t)((kk*16 + (lane & 15)) * AT_ROW
                                                        + ntp*32 + ((lane >> 4) << 4));
                ldsm_x4_t(vh4, a);
                ldsm_x4_t(vl4, a + AT_ARR);
                mma_f16(o[2*ntp],   ph, vh4);
                mma_f16(o[2*ntp+1], ph, vh4 + 2);
                mma_f16(o[2*ntp],   ph, vl4);
                mma_f16(o[2*ntp+1], ph, vl4 + 2);
            }
        }
        __syncthreads();
        if (t + 2 < ntiles) load_kv(t + 2, t + 2);
    }

    float iA = 1.0f / lA, iB = 1.0f / lB;
    int qA = qb + warp*16 + (lane >> 2);
    size_t rowA = ((size_t)(b*L_ + qA)) * D_;
    size_t rowB = rowA + 8 * D_;
    int cb = h*HD_ + 2*(lane & 3);
    #pragma unroll
    for (int nt = 0; nt < 8; nt++) {
        int c = cb + nt*8;
        float a0 = o[nt][0]*iA, a1 = o[nt][1]*iA;
        float b0 = o[nt][2]*iB, b1 = o[nt][3]*iB;
        unsigned short h0,l0,h1,l1;
        split1(a0,h0,l0); split1(a1,h1,l1);
        *(uint32_t*)(out_hi + rowA + c) = (uint32_t)h0 | ((uint32_t)h1 << 16);
        *(uint32_t*)(out_lo + rowA + c) = (uint32_t)l0 | ((uint32_t)l1 << 16);
        split1(b0,h0,l0); split1(b1,h1,l1);
        *(uint32_t*)(out_hi + rowB + c) = (uint32_t)h0 | ((uint32_t)h1 << 16);
        *(uint32_t*)(out_lo + rowB + c) = (uint32_t)l0 | ((uint32_t)l1 << 16);
    }
}

// ---------------------------------------------------------------------------
// mma.sync cross-attention with tile-range skipping (seg_ids sorted), f16.
// ---------------------------------------------------------------------------
__global__ void __launch_bounds__(128, 2)
cross_attn_mma(const __half* __restrict__ Qh, const __half* __restrict__ Ql,
               const __half* __restrict__ Kh, const __half* __restrict__ Kl,
               const __half* __restrict__ Vh, const __half* __restrict__ Vl,
               const int* __restrict__ seg_ids,
               __half* __restrict__ out_hi, __half* __restrict__ out_lo) {
    extern __shared__ char smraw[];
    const uint32_t sb = (uint32_t)__cvta_generic_to_shared(smraw);
    const int tid = threadIdx.x, warp = tid >> 5, lane = tid & 31;
    const int h = blockIdx.y, b = blockIdx.z;
    const int qb = (int)blockIdx.x * 64;
    const size_t hbQ = ((size_t)(b*H_ + h)) * L_;
    const size_t hbK = ((size_t)(b*H_ + h)) * S_;

    const int rA = qb + warp*16 + (lane >> 2);
    const int segA = seg_ids[b*L_ + rA];
    const int segB = seg_ids[b*L_ + rA + 8];

    const int segF = seg_ids[b*L_ + qb];
    const int segL = seg_ids[b*L_ + qb + 63];
    int t0 = (segF - 127) >> 6; if (t0 < 0) t0 = 0;
    int t1 = segL >> 6;
    const int nte = t1 - t0 + 1;

    #pragma unroll
    for (int i = 0; i < 8; i++) {
        int id = tid + i * 128;
        int arr = id >> 9;
        int rem = id & 511;
        int row = rem >> 3, kc = rem & 7;
        const __half* p = (arr ? Ql : Qh) + (hbQ + qb + row) * HD_ + kc * 8;
        uint32_t d = sb + (uint32_t)(arr * AT_ARR + row * AT_ROW + kc * 16);
        asm volatile("cp.async.cg.shared.global [%0], [%1], 16;" :: "r"(d), "l"(p) : "memory");
    }
    auto load_kv = [&](int t, int slot) {
        uint32_t base = sb + AT_KV0 + (uint32_t)(slot & 1) * AT_STG;
        int k0 = t * 64;
        #pragma unroll
        for (int i = 0; i < 16; i++) {
            int id = tid + i * 128;
            int arr = id >> 9;
            int rem = id & 511;
            int row = rem >> 3, kc = rem & 7;
            const __half* p = (arr==0?Kh:arr==1?Kl:arr==2?Vh:Vl) + (hbK + k0 + row) * HD_ + kc * 8;
            uint32_t d = base + (uint32_t)(arr * AT_ARR + row * AT_ROW + kc * 16);
            asm volatile("cp.async.cg.shared.global [%0], [%1], 16;" :: "r"(d), "l"(p) : "memory");
        }
        asm volatile("cp.async.commit_group;" ::: "memory");
    };
    load_kv(t0, 0);
    if (nte > 1) load_kv(t0 + 1, 1);

    uint32_t qh[4][4], ql[4][4];
    float o[8][4];
    #pragma unroll
    for (int i = 0; i < 8; i++)
        #pragma unroll
        for (int j = 0; j < 4; j++) o[i][j] = 0.f;
    float mA = -1e30f, mB = -1e30f, lA = 0.f, lB = 0.f;

    for (int tt = 0; tt < nte; tt++) {
        const int t = t0 + tt;
        if (tt + 1 < nte) { asm volatile("cp.async.wait_group 1;" ::: "memory"); }
        else              { asm volatile("cp.async.wait_group 0;" ::: "memory"); }
        __syncthreads();
        if (tt == 0) {
            #pragma unroll
            for (int ks = 0; ks < 4; ks++) {
                uint32_t a = sb + (uint32_t)((warp*16 + (lane & 15)) * AT_ROW + ks*32 + (lane >> 4) * 16);
                ldsm_x4(qh[ks], a);
                ldsm_x4(ql[ks], a + AT_ARR);
            }
        }
        const uint32_t kvb = sb + AT_KV0 + (uint32_t)(tt & 1) * AT_STG;

        float s[8][4];
        #pragma unroll
        for (int i = 0; i < 8; i++)
            #pragma unroll
            for (int j = 0; j < 4; j++) s[i][j] = 0.f;
        #pragma unroll
        for (int ks = 0; ks < 4; ks++) {
            uint32_t kh4[4][4], kl4[4][4];
            #pragma unroll
            for (int ntp = 0; ntp < 4; ntp++) {
                uint32_t a = kvb + (uint32_t)((ntp*16 + (lane & 7) + ((lane >> 4) << 3)) * AT_ROW
                                              + ks*32 + (((lane >> 3) & 1) << 4));
                ldsm_x4(kh4[ntp], a);
                ldsm_x4(kl4[ntp], a + AT_ARR);
            }
            #pragma unroll
            for (int ntp = 0; ntp < 4; ntp++) {
                mma_f16(s[2*ntp],   qh[ks], kh4[ntp]);
                mma_f16(s[2*ntp+1], qh[ks], kh4[ntp] + 2);
                mma_f16(s[2*ntp],   qh[ks], kl4[ntp]);
                mma_f16(s[2*ntp+1], qh[ks], kl4[ntp] + 2);
                mma_f16(s[2*ntp],   ql[ks], kh4[ntp]);
                mma_f16(s[2*ntp+1], ql[ks], kh4[ntp] + 2);
            }
        }
        {
            int cbase = t*64 + 2*(lane & 3);
            #pragma unroll
            for (int nt = 0; nt < 8; nt++) {
                int c0 = cbase + nt*8, c1 = c0 + 1;
                if (c0 > segA || c0 <= segA - 128) s[nt][0] = -1e30f;
                if (c1 > segA || c1 <= segA - 128) s[nt][1] = -1e30f;
                if (c0 > segB || c0 <= segB - 128) s[nt][2] = -1e30f;
                if (c1 > segB || c1 <= segB - 128) s[nt][3] = -1e30f;
            }
        }
        float tmA = -1e30f, tmB = -1e30f;
        #pragma unroll
        for (int nt = 0; nt < 8; nt++) {
            tmA = fmaxf(tmA, fmaxf(s[nt][0], s[nt][1]));
            tmB = fmaxf(tmB, fmaxf(s[nt][2], s[nt][3]));
        }
        tmA = fmaxf(tmA, __shfl_xor_sync(0xffffffffu, tmA, 1));
        tmA = fmaxf(tmA, __shfl_xor_sync(0xffffffffu, tmA, 2));
        tmB = fmaxf(tmB, __shfl_xor_sync(0xffffffffu, tmB, 1));
        tmB = fmaxf(tmB, __shfl_xor_sync(0xffffffffu, tmB, 2));
        float nmA = fmaxf(mA, tmA), nmB = fmaxf(mB, tmB);
        float scA = __expf(mA - nmA), scB = __expf(mB - nmB);
        float tsA = 0.f, tsB = 0.f;
        #pragma unroll
        for (int nt = 0; nt < 8; nt++) {
            s[nt][0] = __expf(s[nt][0] - nmA);
            s[nt][1] = __expf(s[nt][1] - nmA);
            s[nt][2] = __expf(s[nt][2] - nmB);
            s[nt][3] = __expf(s[nt][3] - nmB);
            tsA += s[nt][0] + s[nt][1];
            tsB += s[nt][2] + s[nt][3];
        }
        tsA += __shfl_xor_sync(0xffffffffu, tsA, 1);
        tsA += __shfl_xor_sync(0xffffffffu, tsA, 2);
        tsB += __shfl_xor_sync(0xffffffffu, tsB, 1);
        tsB += __shfl_xor_sync(0xffffffffu, tsB, 2);
        lA = lA * scA + tsA;
        lB = lB * scB + tsB;
        #pragma unroll
        for (int nt = 0; nt < 8; nt++) {
            o[nt][0] *= scA; o[nt][1] *= scA;
            o[nt][2] *= scB; o[nt][3] *= scB;
        }
        mA = nmA; mB = nmB;
        #pragma unroll
        for (int kk = 0; kk < 4; kk++) {
            uint32_t ph[4];
            ph[0] = pack_h16x2(s[2*kk][0],   s[2*kk][1]);
            ph[1] = pack_h16x2(s[2*kk][2],   s[2*kk][3]);
            ph[2] = pack_h16x2(s[2*kk+1][0], s[2*kk+1][1]);
            ph[3] = pack_h16x2(s[2*kk+1][2], s[2*kk+1][3]);
            #pragma unroll
            for (int ntp = 0; ntp < 4; ntp++) {
                uint32_t vh4[4], vl4[4];
                uint32_t a = kvb + 2*AT_ARR + (uint32_t)((kk*16 + (lane & 15)) * AT_ROW
                                                        + ntp*32 + ((lane >> 4) << 4));
                ldsm_x4_t(vh4, a);
                ldsm_x4_t(vl4, a + AT_ARR);
                mma_f16(o[2*ntp],   ph, vh4);
                mma_f16(o[2*ntp+1], ph, vh4 + 2);
                mma_f16(o[2*ntp],   ph, vl4);
                mma_f16(o[2*ntp+1], ph, vl4 + 2);
            }
        }
        __syncthreads();
        if (tt + 2 < nte) load_kv(t0 + tt + 2, tt + 2);
    }

    float iA = 1.0f / lA, iB = 1.0f / lB;
    size_t rowA = ((size_t)(b*L_ + rA)) * D_;
    size_t rowB = rowA + 8 * D_;
    int cb = h*HD_ + 2*(lane & 3);
    #pragma unroll
    for (int nt = 0; nt < 8; nt++) {
        int c = cb + nt*8;
        float a0 = o[nt][0]*iA, a1 = o[nt][1]*iA;
        float b0 = o[nt][2]*iB, b1 = o[nt][3]*iB;
        unsigned short h0,l0,h1,l1;
        split1(a0,h0,l0); split1(a1,h1,l1);
        *(uint32_t*)(out_hi + rowA + c) = (uint32_t)h0 | ((uint32_t)h1 << 16);
        *(uint32_t*)(out_lo + rowA + c) = (uint32_t)l0 | ((uint32_t)l1 << 16);
        split1(b0,h0,l0); split1(b1,h1,l1);
        *(uint32_t*)(out_hi + rowB + c) = (uint32_t)h0 | ((uint32_t)h1 << 16);
        *(uint32_t*)(out_lo + rowB + c) = (uint32_t)l0 | ((uint32_t)l1 << 16);
    }
}

// ---------------------------------------------------------------------------
// Launch
// ---------------------------------------------------------------------------
static inline void split_launch(const float* src, __half* hi, __half* lo, size_t n) {
    int n4 = (int)(n / 4);
    split_k<<<n4 / 1024, 256>>>(src, hi, lo);
}

extern "C" void kernel_launch(void* const* d_in, const int* in_sizes, int n_in,
                              void* d_out, int out_size) {
    const float* x      = (const float*)d_in[0];
    const float* memory = (const float*)d_in[1];
    const int*   seg    = (const int*)  d_in[2];
    const float* Wqkv   = (const float*)d_in[3];
    const float* bqkv   = (const float*)d_in[4];
    const float* Wo     = (const float*)d_in[5];
    const float* bo     = (const float*)d_in[6];
    const float* Wq_c   = (const float*)d_in[7];
    const float* Wkv_c  = (const float*)d_in[8];
    const float* Wo_c   = (const float*)d_in[9];
    const float* Wg     = (const float*)d_in[10];
    const float* Wu     = (const float*)d_in[11];
    const float* Wd     = (const float*)d_in[12];
    const float* n1     = (const float*)d_in[13];
    const float* n2     = (const float*)d_in[14];
    const float* n3     = (const float*)d_in[15];
    const float* nf     = (const float*)d_in[16];

    cudaFuncSetAttribute(gemm_f16s<1,true >, cudaFuncAttributeMaxDynamicSharedMemorySize, GSMEM);
    cudaFuncSetAttribute(gemm_f16s<2,true >, cudaFuncAttributeMaxDynamicSharedMemorySize, GSMEM);
    cudaFuncSetAttribute(gemm_f16s<2,false>, cudaFuncAttributeMaxDynamicSharedMemorySize, GSMEM);
    cudaFuncSetAttribute(gemm_f16s<3,false>, cudaFuncAttributeMaxDynamicSharedMemorySize, GSMEM);
    cudaFuncSetAttribute(gemm_f16s<4,true >, cudaFuncAttributeMaxDynamicSharedMemorySize, GSMEM);
    cudaFuncSetAttribute(gemm_f16s<6,true >, cudaFuncAttributeMaxDynamicSharedMemorySize, GSMEM);
    cudaFuncSetAttribute(gemm_f16s<7,true >, cudaFuncAttributeMaxDynamicSharedMemorySize, GSMEM);
    cudaFuncSetAttribute(self_attn_mma,  cudaFuncAttributeMaxDynamicSharedMemorySize, AT_SMEM);
    cudaFuncSetAttribute(cross_attn_mma, cudaFuncAttributeMaxDynamicSharedMemorySize, AT_SMEM);

    float *xb;
    __half *hhi, *hlo, *ahi, *alo, *chi, *clo, *gshi, *gslo, *mhi, *mlo, *whi, *wlo;
    __half *sqh, *sql, *skh, *skl, *svh, *svl;
    __half *ckh, *ckl, *cvh, *cvl;
    cudaGetSymbolAddress((void**)&xb,   g_x);
    cudaGetSymbolAddress((void**)&hhi,  g_h_hi);  cudaGetSymbolAddress((void**)&hlo,  g_h_lo);
    cudaGetSymbolAddress((void**)&ahi,  g_at_hi); cudaGetSymbolAddress((void**)&alo,  g_at_lo);
    cudaGetSymbolAddress((void**)&chi,  g_co_hi); cudaGetSymbolAddress((void**)&clo,  g_co_lo);
    cudaGetSymbolAddress((void**)&gshi, g_gs_hi); cudaGetSymbolAddress((void**)&gslo, g_gs_lo);
    cudaGetSymbolAddress((void**)&mhi,  g_m_hi);  cudaGetSymbolAddress((void**)&mlo,  g_m_lo);
    cudaGetSymbolAddress((void**)&whi,  g_w_hi);  cudaGetSymbolAddress((void**)&wlo,  g_w_lo);
    cudaGetSymbolAddress((void**)&sqh,  g_sqh);   cudaGetSymbolAddress((void**)&sql,  g_sql);
    cudaGetSymbolAddress((void**)&skh,  g_skh);   cudaGetSymbolAddress((void**)&skl,  g_skl);
    cudaGetSymbolAddress((void**)&svh,  g_svh);   cudaGetSymbolAddress((void**)&svl,  g_svl);
    cudaGetSymbolAddress((void**)&ckh,  g_ckh);   cudaGetSymbolAddress((void**)&ckl,  g_ckl);
    cudaGetSymbolAddress((void**)&cvh,  g_cvh);   cudaGetSymbolAddress((void**)&cvl,  g_cvl);

    rope_cache_k<<<256, 256>>>();

    split_launch(Wqkv,  whi + O_WQKV, wlo + O_WQKV, NL*SZ_WQKV);
    split_launch(Wo,    whi + O_WO,   wlo + O_WO,   NL*SZ_WO);
    split_launch(Wq_c,  whi + O_WQC,  wlo + O_WQC,  NL*SZ_WQC);
    split_launch(Wkv_c, whi + O_WKVC, wlo + O_WKVC, NL*SZ_WKVC);
    split_launch(Wo_c,  whi + O_WOC,  wlo + O_WOC,  NL*SZ_WOC);
    for (int l = 0; l < NL; l++) {
        int blocks = (int)((size_t)F_*D_/4/1024);
        split_ilv_k<<<blocks, 256>>>(Wg + (size_t)l*F_*D_,
            whi + O_WGU + l*SZ_WGU, wlo + O_WGU + l*SZ_WGU, 0);
        split_ilv_k<<<blocks, 256>>>(Wu + (size_t)l*F_*D_,
            whi + O_WGU + l*SZ_WGU, wlo + O_WGU + l*SZ_WGU, 1);
    }
    split_launch(Wd,    whi + O_WD,   wlo + O_WD,   NL*SZ_WD);
    split_launch(memory, mhi, mlo, (size_t)B_*S_*D_);

    // upfront: all 4 layers' cross K/V in one GEMM (layer-independent)
    gemm_f16s<7,true><<<dim3(NL*2*D_/128, (B_*S_)/256), 256, GSMEM>>>(
        mhi, mlo, whi + O_WKVC, wlo + O_WKVC, nullptr, nullptr, nullptr,
        ckh, ckl, cvh, cvl, nullptr, nullptr, NL*2*D_, D_);

    const dim3 self_grid(L_/64, H_, B_);
    const dim3 cross_grid(L_/64, H_, B_);

    for (int l = 0; l < NL; l++) {
        const __half* wqkv_h = whi + O_WQKV + l*SZ_WQKV;
        const __half* wqkv_l = wlo + O_WQKV + l*SZ_WQKV;
        const __half* wo_h   = whi + O_WO   + l*SZ_WO;
        const __half* wo_l   = wlo + O_WO   + l*SZ_WO;
        const __half* wqc_h  = whi + O_WQC  + l*SZ_WQC;
        const __half* wqc_l  = wlo + O_WQC  + l*SZ_WQC;
        const __half* woc_h  = whi + O_WOC  + l*SZ_WOC;
        const __half* woc_l  = wlo + O_WOC  + l*SZ_WOC;
        const __half* wgu_h  = whi + O_WGU  + l*SZ_WGU;
        const __half* wgu_l  = wlo + O_WGU  + l*SZ_WGU;
        const __half* wd_h   = whi + O_WD   + l*SZ_WD;
        const __half* wd_l   = wlo + O_WD   + l*SZ_WD;

        const float* xsrc = (l == 0) ? x : xb;    // residual stream source

        // --- self attention block (QKV GEMM fuses bias+RoPE+split) ---
        rmsnorm_split_k<<<M_, 256>>>(xsrc, n1 + l*D_, hhi, hlo);
        gemm_f16s<6,true><<<dim3(3*D_/128, M_/256), 256, GSMEM>>>(
            hhi, hlo, wqkv_h, wqkv_l, bqkv + l*3*D_, nullptr, nullptr,
            sqh, sql, skh, skl, svh, svl, 3*D_, D_);
        self_attn_mma<<<self_grid, 128, AT_SMEM>>>(sqh, sql, skh, skl, svh, svl, ahi, alo);
        gemm_f16s<1,true><<<dim3(D_/128, M_/256), 256, GSMEM>>>(
            ahi, alo, wo_h, wo_l, bo + l*D_, xb, xsrc,
            nullptr, nullptr, nullptr, nullptr, nullptr, nullptr, D_, D_);

        // --- cross attention block ---
        rmsnorm_split_k<<<M_, 256>>>(xb, n2 + l*D_, hhi, hlo);
        gemm_f16s<4,true><<<dim3(D_/128, M_/256), 256, GSMEM>>>(
            hhi, hlo, wqc_h, wqc_l, nullptr, nullptr, nullptr,
            sqh, sql, nullptr, nullptr, nullptr, nullptr, D_, D_);
        cross_attn_mma<<<cross_grid, 128, AT_SMEM>>>(
            sqh, sql, ckh + l*CATN, ckl + l*CATN, cvh + l*CATN, cvl + l*CATN,
            seg, chi, clo);
        gemm_f16s<2,true><<<dim3(D_/128, M_/256), 256, GSMEM>>>(
            chi, clo, woc_h, woc_l, nullptr, xb, xb,
            nullptr, nullptr, nullptr, nullptr, nullptr, nullptr, D_, D_);

        // --- MLP block (2-term f16: err ~2^-11 of activations, budget-checked) ---
        rmsnorm_split_k<<<M_, 256>>>(xb, n3 + l*D_, hhi, hlo);
        gemm_f16s<3,false><<<dim3(2*F_/128, M_/256), 256, GSMEM>>>(
            hhi, hlo, wgu_h, wgu_l, nullptr, nullptr, nullptr,
            gshi, gslo, nullptr, nullptr, nullptr, nullptr, 2*F_, D_);
        gemm_f16s<2,false><<<dim3(D_/128, M_/256), 256, GSMEM>>>(
            gshi, gslo, wd_h, wd_l, nullptr, xb, xb,
            nullptr, nullptr, nullptr, nullptr, nullptr, nullptr, D_, F_);
    }

    rmsnorm_k<<<M_, 256>>>(xb, nf, (float*)d_out);
}

// round 15
// speedup vs baseline: 5.8181x; 1.0368x over previous
#include <cuda_runtime.h>
#include <cuda_fp16.h>
#include <math.h>
#include <stdint.h>

// Problem constants
#define NL 4
#define B_ 2
#define L_ 2048
#define S_ 256
#define D_ 1024
#define F_ 4096
#define H_ 16
#define HD_ 64
#define M_ (B_*L_)          // 4096 token rows

// Weight region sizes (elements) and offsets in the concatenated split buffer
#define SZ_WQKV ((size_t)3*D_*D_)
#define SZ_WO   ((size_t)D_*D_)
#define SZ_WQC  ((size_t)D_*D_)
#define SZ_WKVC ((size_t)2*D_*D_)
#define SZ_WOC  ((size_t)D_*D_)
#define SZ_WGU  ((size_t)2*F_*D_)     // interleaved [g0,u0,g1,u1,...] per layer
#define SZ_WD   ((size_t)D_*F_)
static const size_t O_WQKV = 0;
static const size_t O_WO   = O_WQKV + NL*SZ_WQKV;
static const size_t O_WQC  = O_WO   + NL*SZ_WO;
static const size_t O_WKVC = O_WQC  + NL*SZ_WQC;
static const size_t O_WOC  = O_WKVC + NL*SZ_WKVC;
static const size_t O_WGU  = O_WOC  + NL*SZ_WOC;
static const size_t O_WD   = O_WGU  + NL*SZ_WGU;
#define WTOT (O_WD + NL*SZ_WD)

// ---------------------------------------------------------------------------
// Scratch (device globals; no allocations allowed)
// ---------------------------------------------------------------------------
__device__ float g_x  [M_*D_];
__device__ float g_cos[L_*32];
__device__ float g_sin[L_*32];

__device__ __half g_h_hi [M_*D_],  g_h_lo [M_*D_];
__device__ __half g_at_hi[M_*D_],  g_at_lo[M_*D_];
__device__ __half g_co_hi[M_*D_],  g_co_lo[M_*D_];
__device__ __half g_gs_hi[M_*F_],  g_gs_lo[M_*F_];
__device__ __half g_m_hi [B_*S_*D_], g_m_lo[B_*S_*D_];
__device__ __half g_w_hi[WTOT], g_w_lo[WTOT];

// attention-layout split buffers: [B][H][L][64] (self q/k/v; cross q reuses q)
#define ATN ((size_t)B_*H_*L_*HD_)
__device__ __half g_sqh[ATN], g_sql[ATN];
__device__ __half g_skh[ATN], g_skl[ATN];
__device__ __half g_svh[ATN], g_svl[ATN];

// per-layer cross K/V: [NL][B][H][S][64]
#define CATN ((size_t)B_*H_*S_*HD_)
__device__ __half g_ckh[NL*CATN], g_ckl[NL*CATN];
__device__ __half g_cvh[NL*CATN], g_cvl[NL*CATN];

// ---------------------------------------------------------------------------
// f16 split helpers
// ---------------------------------------------------------------------------
__device__ __forceinline__ void split1(float v, unsigned short& h, unsigned short& l) {
    __half hb = __float2half_rn(v);
    float r = v - __half2float(hb);
    __half lb = __float2half_rn(r);
    h = __half_as_ushort(hb);
    l = __half_as_ushort(lb);
}
__device__ __forceinline__ void split_pack4(float4 v, uint2& ph, uint2& pl) {
    unsigned short h0,h1,h2,h3,l0,l1,l2,l3;
    split1(v.x,h0,l0); split1(v.y,h1,l1); split1(v.z,h2,l2); split1(v.w,h3,l3);
    ph.x = (uint32_t)h0 | ((uint32_t)h1 << 16);
    ph.y = (uint32_t)h2 | ((uint32_t)h3 << 16);
    pl.x = (uint32_t)l0 | ((uint32_t)l1 << 16);
    pl.y = (uint32_t)l2 | ((uint32_t)l3 << 16);
}

// 4-quad ILP split (exact grids: n4 multiple of 1024)
__global__ void split_k(const float* __restrict__ in, __half* __restrict__ hi,
                        __half* __restrict__ lo) {
    int i = blockIdx.x * 1024 + threadIdx.x;
    float4 v[4];
    #pragma unroll
    for (int j = 0; j < 4; j++) v[j] = ((const float4*)in)[i + 256*j];
    #pragma unroll
    for (int j = 0; j < 4; j++) {
        uint2 ph, pl; split_pack4(v[j], ph, pl);
        ((uint2*)hi)[i + 256*j] = ph;
        ((uint2*)lo)[i + 256*j] = pl;
    }
}

// Interleaving split for GU weights: src row r (256 quads/row) -> dst row 2r+off
__global__ void split_ilv_k(const float* __restrict__ in, __half* __restrict__ hi,
                            __half* __restrict__ lo, int off) {
    int i0 = blockIdx.x * 1024 + threadIdx.x;
    float4 v[4];
    #pragma unroll
    for (int j = 0; j < 4; j++) v[j] = ((const float4*)in)[i0 + 256*j];
    #pragma unroll
    for (int j = 0; j < 4; j++) {
        int i = i0 + 256*j;
        int r = i >> 8, c = i & 255;
        uint2 ph, pl; split_pack4(v[j], ph, pl);
        size_t oi = (size_t)(2*r + off) * 256 + c;
        ((uint2*)hi)[oi] = ph;
        ((uint2*)lo)[oi] = pl;
    }
}

// ---------------------------------------------------------------------------
// RoPE cache
// ---------------------------------------------------------------------------
__global__ void rope_cache_k() {
    int idx = blockIdx.x * blockDim.x + threadIdx.x;
    int l = idx >> 5, i = idx & 31;
    double inv = exp(-log(10000.0) * (double)i / 32.0);
    double f = (double)l * inv;
    g_cos[idx] = (float)cos(f);
    g_sin[idx] = (float)sin(f);
}

// ---------------------------------------------------------------------------
// RMSNorm kernels
// ---------------------------------------------------------------------------
__global__ void rmsnorm_split_k(const float* __restrict__ x, const float* __restrict__ w,
                                __half* __restrict__ hi, __half* __restrict__ lo) {
    int row = blockIdx.x;
    int t = threadIdx.x;
    const float4* xr = (const float4*)(x + (size_t)row * D_);
    float4 v = xr[t];
    float ss = v.x*v.x + v.y*v.y + v.z*v.z + v.w*v.w;
    #pragma unroll
    for (int off = 16; off; off >>= 1) ss += __shfl_xor_sync(0xffffffffu, ss, off);
    __shared__ float red[8];
    if ((t & 31) == 0) red[t >> 5] = ss;
    __syncthreads();
    float tot = red[0]+red[1]+red[2]+red[3]+red[4]+red[5]+red[6]+red[7];
    float rs = rsqrtf(tot * (1.0f / (float)D_) + 1e-6f);
    float4 wv = ((const float4*)w)[t];
    float4 o;
    o.x = v.x * rs * wv.x; o.y = v.y * rs * wv.y;
    o.z = v.z * rs * wv.z; o.w = v.w * rs * wv.w;
    uint2 ph, pl; split_pack4(o, ph, pl);
    ((uint2*)hi)[(size_t)row * 256 + t] = ph;
    ((uint2*)lo)[(size_t)row * 256 + t] = pl;
}

__global__ void rmsnorm_k(const float* __restrict__ x, const float* __restrict__ w,
                          float* __restrict__ o) {
    int row = blockIdx.x;
    int t = threadIdx.x;
    const float4* xr = (const float4*)(x + (size_t)row * D_);
    float4 v = xr[t];
    float ss = v.x*v.x + v.y*v.y + v.z*v.z + v.w*v.w;
    #pragma unroll
    for (int off = 16; off; off >>= 1) ss += __shfl_xor_sync(0xffffffffu, ss, off);
    __shared__ float red[8];
    if ((t & 31) == 0) red[t >> 5] = ss;
    __syncthreads();
    float tot = red[0]+red[1]+red[2]+red[3]+red[4]+red[5]+red[6]+red[7];
    float rs = rsqrtf(tot * (1.0f / (float)D_) + 1e-6f);
    float4 wv = ((const float4*)w)[t];
    float4 out;
    out.x = v.x * rs * wv.x; out.y = v.y * rs * wv.y;
    out.z = v.z * rs * wv.z; out.w = v.w * rs * wv.w;
    ((float4*)(o + (size_t)row * D_))[t] = out;
}

// ---------------------------------------------------------------------------
// mma / ldmatrix helpers (f16)
// ---------------------------------------------------------------------------
__device__ __forceinline__ void mma_f16(float* c, const uint32_t* a, const uint32_t* b) {
    asm volatile(
        "mma.sync.aligned.m16n8k16.row.col.f32.f16.f16.f32 "
        "{%0,%1,%2,%3}, {%4,%5,%6,%7}, {%8,%9}, {%0,%1,%2,%3};"
        : "+f"(c[0]), "+f"(c[1]), "+f"(c[2]), "+f"(c[3])
        : "r"(a[0]), "r"(a[1]), "r"(a[2]), "r"(a[3]), "r"(b[0]), "r"(b[1]));
}
__device__ __forceinline__ void ldsm_x4(uint32_t* r, uint32_t addr) {
    asm volatile("ldmatrix.sync.aligned.m8n8.x4.shared.b16 {%0,%1,%2,%3}, [%4];"
        : "=r"(r[0]), "=r"(r[1]), "=r"(r[2]), "=r"(r[3]) : "r"(addr));
}
__device__ __forceinline__ void ldsm_x4_t(uint32_t* r, uint32_t addr) {
    asm volatile("ldmatrix.sync.aligned.m8n8.x4.trans.shared.b16 {%0,%1,%2,%3}, [%4];"
        : "=r"(r[0]), "=r"(r[1]), "=r"(r[2]), "=r"(r[3]) : "r"(addr));
}
__device__ __forceinline__ uint32_t pack_h16x2(float lo, float hi) {
    return (uint32_t)__half_as_ushort(__float2half_rn(lo)) |
           ((uint32_t)__half_as_ushort(__float2half_rn(hi)) << 16);
}

// ---------------------------------------------------------------------------
// f16 split GEMM (NT), 256x128 CTA tile, warp tile 64x64 (8 warps, 4x2).
// THREE=true:  C = AhWh + AhWl + AlWh  (exp-feeding paths: QKV, Wqc, crossKV)
// THREE=false: C = AhWh + AhWl         (linear paths: Wo, Wo_c, GU, Wd;
//                                       calibrated ~1e-5 rel_err per site)
// MODE 1: +bias +residual(Rsrc) -> fp32 C   (Wo)
// MODE 2: +residual(Rsrc)       -> fp32 C   (Wo_c, Wd)
// MODE 3: swiglu (interleaved g|u cols) -> f16 hi/lo [M][F]
// MODE 4: attn-q layout, x0.125         -> f16 hi/lo [B][H][L][64]
// MODE 6: QKV: +bias, RoPE on q/k, q x0.125 -> q/k/v f16 hi/lo [B][H][L][64]
// MODE 7: multi-layer cross-KV           -> per-layer k/v [NL][B][H][S][64]
// ---------------------------------------------------------------------------
#define G2STAGE 61440
#define G2_AL   20480
#define G2_B0   40960
#define G2_B1   51200
#define GSMEM   (3*G2STAGE)

template <int MODE, bool THREE>
__global__ void __launch_bounds__(256, 1)
gemm_f16s(const __half* __restrict__ Ah, const __half* __restrict__ Al,
          const __half* __restrict__ Wh, const __half* __restrict__ Wl,
          const float* __restrict__ bias, float* __restrict__ C,
          const float* __restrict__ Rsrc,
          __half* __restrict__ o1h, __half* __restrict__ o1l,
          __half* __restrict__ o2h, __half* __restrict__ o2l,
          __half* __restrict__ o3h, __half* __restrict__ o3l,
          int N, int K) {
    extern __shared__ char smem[];
    const uint32_t sbase = (uint32_t)__cvta_generic_to_shared(smem);
    const int tid  = threadIdx.x;
    const int warp = tid >> 5, lane = tid & 31;
    const int wr = warp >> 1;      // 0..3 : 64-row slab
    const int wc = warp & 1;       // 0..1 : 64-col slab
    const int g  = lane >> 2;
    const int t  = lane & 3;
    const int bm = blockIdx.y, bn = blockIdx.x;

    // cp.async chunk tables: 3072 16B-chunks per stage, 12 per thread
    // chunks i=4..7 are the A-lo array (skipped when !THREE)
    const __half* src[12];
    uint32_t dst[12];
    #pragma unroll
    for (int i = 0; i < 12; i++) {
        int id = tid + (i << 8);
        const __half* bp;
        int grow; uint32_t off; int kc;
        if (id < 2048) {
            int arr = id >> 10, rem = id & 1023;
            int row = rem >> 2; kc = rem & 3;
            bp = arr ? Al : Ah;
            grow = bm * 256 + row;
            off = (uint32_t)(arr * G2_AL + row * 80 + kc * 16);
        } else {
            int id2 = id - 2048;
            int arr = id2 >> 9, rem = id2 & 511;
            int row = rem >> 2; kc = rem & 3;
            bp = arr ? Wl : Wh;
            grow = bn * 128 + row;
            off = (uint32_t)(G2_B0 + arr * 10240 + row * 80 + kc * 16);
        }
        src[i] = bp + (size_t)grow * K + kc * 8;
        dst[i] = off;
    }

    const uint32_t arow = (uint32_t)((wr * 64 + (lane & 15)) * 80 + (lane >> 4) * 16);
    const uint32_t brow = (uint32_t)((wc * 64 + (lane & 7) + ((lane >> 4) << 3)) * 80
                                     + (((lane >> 3) & 1) << 4));

    float acc[4][8][4];
    #pragma unroll
    for (int i = 0; i < 4; i++)
        #pragma unroll
        for (int j = 0; j < 8; j++)
            #pragma unroll
            for (int r = 0; r < 4; r++) acc[i][j][r] = 0.f;

    const int nk = K >> 5;

    #pragma unroll
    for (int st = 0; st < 2; st++) {
        uint32_t s = sbase + st * G2STAGE;
        #pragma unroll
        for (int i = 0; i < 12; i++) {
            if (!THREE && i >= 4 && i < 8) continue;
            const void* p = src[i] + st * 32;
            asm volatile("cp.async.cg.shared.global [%0], [%1], 16;"
                         :: "r"(s + dst[i]), "l"(p) : "memory");
        }
        asm volatile("cp.async.commit_group;" ::: "memory");
    }

    for (int it = 0; it < nk; it++) {
        asm volatile("cp.async.wait_group 1;" ::: "memory");
        __syncthreads();
        uint32_t s = sbase + (uint32_t)(it % 3) * G2STAGE;

        #pragma unroll
        for (int ks = 0; ks < 2; ks++) {
            const uint32_t ko = ks * 32;
            uint32_t af[16], bh[16], bl[16];
            #pragma unroll
            for (int mt = 0; mt < 4; mt++) ldsm_x4(af + 4*mt, s + arow + mt*1280 + ko);
            #pragma unroll
            for (int p = 0; p < 4; p++) ldsm_x4(bh + 4*p, s + G2_B0 + brow + p*1280 + ko);
            #pragma unroll
            for (int p = 0; p < 4; p++) ldsm_x4(bl + 4*p, s + G2_B1 + brow + p*1280 + ko);
            #pragma unroll
            for (int mt = 0; mt < 4; mt++)
                #pragma unroll
                for (int nt = 0; nt < 8; nt++) mma_f16(acc[mt][nt], af + 4*mt, bh + 2*nt);
            #pragma unroll
            for (int mt = 0; mt < 4; mt++)
                #pragma unroll
                for (int nt = 0; nt < 8; nt++) mma_f16(acc[mt][nt], af + 4*mt, bl + 2*nt);
            if (THREE) {
                #pragma unroll
                for (int mt = 0; mt < 4; mt++) ldsm_x4(af + 4*mt, s + G2_AL + arow + mt*1280 + ko);
                #pragma unroll
                for (int mt = 0; mt < 4; mt++)
                    #pragma unroll
                    for (int nt = 0; nt < 8; nt++) mma_f16(acc[mt][nt], af + 4*mt, bh + 2*nt);
            }
        }

        if (it + 2 < nk) {
            uint32_t s2 = sbase + (uint32_t)((it + 2) % 3) * G2STAGE;
            int k0 = (it + 2) * 32;
            #pragma unroll
            for (int i = 0; i < 12; i++) {
                if (!THREE && i >= 4 && i < 8) continue;
                const void* p = src[i] + k0;
                asm volatile("cp.async.cg.shared.global [%0], [%1], 16;"
                             :: "r"(s2 + dst[i]), "l"(p) : "memory");
            }
        }
        asm volatile("cp.async.commit_group;" ::: "memory");
    }

    if (MODE == 6) {
        // QKV epilogue: bias + RoPE (q,k) + split into attention layout.
        const int part = (bn * 128 + wc * 64) >> 10;
        #pragma unroll
        for (int mt = 0; mt < 4; mt++) {
            #pragma unroll
            for (int half = 0; half < 2; half++) {
                int row = bm * 256 + wr * 64 + mt * 16 + g + half * 8;
                int b = row >> 11, ltok = row & (L_ - 1);
                if (part < 2) {
                    #pragma unroll
                    for (int np = 0; np < 4; np++) {
                        int col = bn*128 + wc*64 + np*8 + 2*t;
                        int pcol = col & 1023;
                        int head = pcol >> 6;
                        int i = pcol & 31;
                        float c0 = g_cos[ltok*32 + i],     s0 = g_sin[ltok*32 + i];
                        float c1 = g_cos[ltok*32 + i + 1], s1 = g_sin[ltok*32 + i + 1];
                        float x1a = acc[mt][np  ][half*2+0] + bias[col];
                        float x1b = acc[mt][np  ][half*2+1] + bias[col+1];
                        float x2a = acc[mt][np+4][half*2+0] + bias[col+32];
                        float x2b = acc[mt][np+4][half*2+1] + bias[col+33];
                        float r1a = x1a*c0 - x2a*s0, r2a = x2a*c0 + x1a*s0;
                        float r1b = x1b*c1 - x2b*s1, r2b = x2b*c1 + x1b*s1;
                        __half *oh, *ol;
                        if (part == 0) {
                            r1a *= 0.125f; r1b *= 0.125f; r2a *= 0.125f; r2b *= 0.125f;
                            oh = o1h; ol = o1l;
                        } else { oh = o2h; ol = o2l; }
                        size_t oi = (((size_t)(b*H_ + head)) * L_ + ltok) * HD_ + i;
                        unsigned short h0, l0, h1, l1;
                        split1(r1a, h0, l0); split1(r1b, h1, l1);
                        *(uint32_t*)(oh + oi) = (uint32_t)h0 | ((uint32_t)h1 << 16);
                        *(uint32_t*)(ol + oi) = (uint32_t)l0 | ((uint32_t)l1 << 16);
                        split1(r2a, h0, l0); split1(r2b, h1, l1);
                        *(uint32_t*)(oh + oi + 32) = (uint32_t)h0 | ((uint32_t)h1 << 16);
                        *(uint32_t*)(ol + oi + 32) = (uint32_t)l0 | ((uint32_t)l1 << 16);
                    }
                } else {
                    #pragma unroll
                    for (int nt = 0; nt < 8; nt++) {
                        int col = bn*128 + wc*64 + nt*8 + 2*t;
                        int pcol = col & 1023;
                        int head = pcol >> 6, d = pcol & 63;
                        float c0 = acc[mt][nt][half*2+0] + bias[col];
                        float c1 = acc[mt][nt][half*2+1] + bias[col+1];
                        size_t oi = (((size_t)(b*H_ + head)) * L_ + ltok) * HD_ + d;
                        unsigned short h0, l0, h1, l1;
                        split1(c0, h0, l0); split1(c1, h1, l1);
                        *(uint32_t*)(o3h + oi) = (uint32_t)h0 | ((uint32_t)h1 << 16);
                        *(uint32_t*)(o3l + oi) = (uint32_t)l0 | ((uint32_t)l1 << 16);
                    }
                }
            }
        }
        return;
    }

    #pragma unroll
    for (int mt = 0; mt < 4; mt++) {
        #pragma unroll
        for (int half = 0; half < 2; half++) {
            int row = bm * 256 + wr * 64 + mt * 16 + g + half * 8;
            #pragma unroll
            for (int nt = 0; nt < 8; nt++) {
                int col = bn * 128 + wc * 64 + nt * 8 + 2 * t;
                float c0 = acc[mt][nt][half * 2 + 0];
                float c1 = acc[mt][nt][half * 2 + 1];
                if (MODE <= 2) {
                    float* dstp = C + (size_t)row * N + col;
                    const float* rp = Rsrc + (size_t)row * N + col;
                    if (MODE == 1) { c0 += bias[col]; c1 += bias[col + 1]; }
                    float2 r = *(const float2*)rp;
                    c0 += r.x; c1 += r.y;
                    *(float2*)dstp = make_float2(c0, c1);
                } else if (MODE == 3) {
                    float sg = c0 / (1.0f + expf(-c0)) * c1;
                    unsigned short hh, ll; split1(sg, hh, ll);
                    size_t oi = (size_t)row * F_ + (col >> 1);
                    o1h[oi] = __ushort_as_half(hh);
                    o1l[oi] = __ushort_as_half(ll);
                } else if (MODE == 4) {
                    int b = row >> 11, ltok = row & (L_ - 1);
                    int hd = col >> 6, d = col & 63;
                    size_t oi = (((size_t)(b*H_ + hd)) * L_ + ltok) * HD_ + d;
                    unsigned short h0, l0, h1, l1;
                    split1(c0 * 0.125f, h0, l0); split1(c1 * 0.125f, h1, l1);
                    *(uint32_t*)(o1h + oi) = (uint32_t)h0 | ((uint32_t)h1 << 16);
                    *(uint32_t*)(o1l + oi) = (uint32_t)l0 | ((uint32_t)l1 << 16);
                } else { // MODE 7: multi-layer cross-KV
                    int layer = col >> 11;
                    int c2 = col & 2047;
                    int kv = c2 >> 10;
                    int hd = (c2 >> 6) & 15, d = c2 & 63;
                    int b = row >> 8, stok = row & (S_ - 1);
                    size_t oi = (size_t)layer * CATN
                              + (((size_t)(b*H_ + hd)) * S_ + stok) * HD_ + d;
                    unsigned short h0, l0, h1, l1;
                    split1(c0, h0, l0); split1(c1, h1, l1);
                    __half* ph = kv ? o2h : o1h;
                    __half* pl = kv ? o2l : o1l;
                    *(uint32_t*)(ph + oi) = (uint32_t)h0 | ((uint32_t)h1 << 16);
                    *(uint32_t*)(pl + oi) = (uint32_t)l0 | ((uint32_t)l1 << 16);
                }
            }
        }
    }
}

// ---------------------------------------------------------------------------
// mma.sync flash self-attention (f16). P packed f16; P·V uses Ph·Vh + Ph·Vl.
// ---------------------------------------------------------------------------
#define AT_ROW  144
#define AT_ARR  (64*AT_ROW)
#define AT_KV0  (2*AT_ARR)
#define AT_STG  (4*AT_ARR)
#define AT_SMEM (2*AT_ARR + 2*AT_STG)

__global__ void __launch_bounds__(128, 2)
self_attn_mma(const __half* __restrict__ Qh, const __half* __restrict__ Ql,
              const __half* __restrict__ Kh, const __half* __restrict__ Kl,
              const __half* __restrict__ Vh, const __half* __restrict__ Vl,
              __half* __restrict__ out_hi, __half* __restrict__ out_lo) {
    extern __shared__ char smraw[];
    const uint32_t sb = (uint32_t)__cvta_generic_to_shared(smraw);
    const int tid = threadIdx.x, warp = tid >> 5, lane = tid & 31;
    const int h = blockIdx.y, b = blockIdx.z;
    const int qbi = (int)(gridDim.x - 1 - blockIdx.x);
    const int qb = qbi * 64;
    const int ntiles = qbi + 1;
    const size_t hb = ((size_t)(b*H_ + h)) * L_;

    #pragma unroll
    for (int i = 0; i < 8; i++) {
        int id = tid + i * 128;
        int arr = id >> 9;
        int rem = id & 511;
        int row = rem >> 3, kc = rem & 7;
        const __half* p = (arr ? Ql : Qh) + (hb + qb + row) * HD_ + kc * 8;
        uint32_t d = sb + (uint32_t)(arr * AT_ARR + row * AT_ROW + kc * 16);
        asm volatile("cp.async.cg.shared.global [%0], [%1], 16;" :: "r"(d), "l"(p) : "memory");
    }
    auto load_kv = [&](int t, int slot) {
        uint32_t base = sb + AT_KV0 + (uint32_t)(slot & 1) * AT_STG;
        int k0 = t * 64;
        #pragma unroll
        for (int i = 0; i < 16; i++) {
            int id = tid + i * 128;
            int arr = id >> 9;
            int rem = id & 511;
            int row = rem >> 3, kc = rem & 7;
            const __half* p = (arr==0?Kh:arr==1?Kl:arr==2?Vh:Vl) + (hb + k0 + row) * HD_ + kc * 8;
            uint32_t d = base + (uint32_t)(arr * AT_ARR + row * AT_ROW + kc * 16);
            asm volatile("cp.async.cg.shared.global [%0], [%1], 16;" :: "r"(d), "l"(p) : "memory");
        }
        asm volatile("cp.async.commit_group;" ::: "memory");
    };
    load_kv(0, 0);
    if (ntiles > 1) load_kv(1, 1);

    uint32_t qh[4][4], ql[4][4];
    float o[8][4];
    #pragma unroll
    for (int i = 0; i < 8; i++)
        #pragma unroll
        for (int j = 0; j < 4; j++) o[i][j] = 0.f;
    float mA = -1e30f, mB = -1e30f, lA = 0.f, lB = 0.f;

    for (int t = 0; t < ntiles; t++) {
        if (t + 1 < ntiles) { asm volatile("cp.async.wait_group 1;" ::: "memory"); }
        else                { asm volatile("cp.async.wait_group 0;" ::: "memory"); }
        __syncthreads();
        if (t == 0) {
            #pragma unroll
            for (int ks = 0; ks < 4; ks++) {
                uint32_t a = sb + (uint32_t)((warp*16 + (lane & 15)) * AT_ROW + ks*32 + (lane >> 4) * 16);
                ldsm_x4(qh[ks], a);
                ldsm_x4(ql[ks], a + AT_ARR);
            }
        }
        const uint32_t kvb = sb + AT_KV0 + (uint32_t)(t & 1) * AT_STG;

        float s[8][4];
        #pragma unroll
        for (int i = 0; i < 8; i++)
            #pragma unroll
            for (int j = 0; j < 4; j++) s[i][j] = 0.f;
        #pragma unroll
        for (int ks = 0; ks < 4; ks++) {
            uint32_t kh4[4][4], kl4[4][4];
            #pragma unroll
            for (int ntp = 0; ntp < 4; ntp++) {
                uint32_t a = kvb + (uint32_t)((ntp*16 + (lane & 7) + ((lane >> 4) << 3)) * AT_ROW
                                              + ks*32 + (((lane >> 3) & 1) << 4));
                ldsm_x4(kh4[ntp], a);
                ldsm_x4(kl4[ntp], a + AT_ARR);
            }
            #pragma unroll
            for (int ntp = 0; ntp < 4; ntp++) {
                mma_f16(s[2*ntp],   qh[ks], kh4[ntp]);
                mma_f16(s[2*ntp+1], qh[ks], kh4[ntp] + 2);
                mma_f16(s[2*ntp],   qh[ks], kl4[ntp]);
                mma_f16(s[2*ntp+1], qh[ks], kl4[ntp] + 2);
                mma_f16(s[2*ntp],   ql[ks], kh4[ntp]);
                mma_f16(s[2*ntp+1], ql[ks], kh4[ntp] + 2);
            }
        }
        if (t == ntiles - 1) {
            int rA = qb + warp*16 + (lane >> 2);
            int cbase = t*64 + 2*(lane & 3);
            #pragma unroll
            for (int nt = 0; nt < 8; nt++) {
                int c0 = cbase + nt*8, c1 = c0 + 1;
                if (c0 > rA)     s[nt][0] = -1e30f;
                if (c1 > rA)     s[nt][1] = -1e30f;
                if (c0 > rA + 8) s[nt][2] = -1e30f;
                if (c1 > rA + 8) s[nt][3] = -1e30f;
            }
        }
        float tmA = -1e30f, tmB = -1e30f;
        #pragma unroll
        for (int nt = 0; nt < 8; nt++) {
            tmA = fmaxf(tmA, fmaxf(s[nt][0], s[nt][1]));
            tmB = fmaxf(tmB, fmaxf(s[nt][2], s[nt][3]));
        }
        tmA = fmaxf(tmA, __shfl_xor_sync(0xffffffffu, tmA, 1));
        tmA = fmaxf(tmA, __shfl_xor_sync(0xffffffffu, tmA, 2));
        tmB = fmaxf(tmB, __shfl_xor_sync(0xffffffffu, tmB, 1));
        tmB = fmaxf(tmB, __shfl_xor_sync(0xffffffffu, tmB, 2));
        float nmA = fmaxf(mA, tmA), nmB = fmaxf(mB, tmB);
        float scA = __expf(mA - nmA), scB = __expf(mB - nmB);
        float tsA = 0.f, tsB = 0.f;
        #pragma unroll
        for (int nt = 0; nt < 8; nt++) {
            s[nt][0] = __expf(s[nt][0] - nmA);
            s[nt][1] = __expf(s[nt][1] - nmA);
            s[nt][2] = __expf(s[nt][2] - nmB);
            s[nt][3] = __expf(s[nt][3] - nmB);
            tsA += s[nt][0] + s[nt][1];
            tsB += s[nt][2] + s[nt][3];
        }
        tsA += __shfl_xor_sync(0xffffffffu, tsA, 1);
        tsA += __shfl_xor_sync(0xffffffffu, tsA, 2);
        tsB += __shfl_xor_sync(0xffffffffu, tsB, 1);
        tsB += __shfl_xor_sync(0xffffffffu, tsB, 2);
        lA = lA * scA + tsA;
        lB = lB * scB + tsB;
        #pragma unroll
        for (int nt = 0; nt < 8; nt++) {
            o[nt][0] *= scA; o[nt][1] *= scA;
            o[nt][2] *= scB; o[nt][3] *= scB;
        }
        mA = nmA; mB = nmB;
        #pragma unroll
        for (int kk = 0; kk < 4; kk++) {
            uint32_t ph[4];
            ph[0] = pack_h16x2(s[2*kk][0],   s[2*kk][1]);
            ph[1] = pack_h16x2(s[2*kk][2],   s[2*kk][3]);
            ph[2] = pack_h16x2(s[2*kk+1][0], s[2*kk+1][1]);
            ph[3] = pack_h16x2(s[2*kk+1][2], s[2*kk+1][3]);
            #pragma unroll
            for (int ntp = 0; ntp < 4; ntp++) {
                uint32_t vh4[4], vl4[4];
                uint32_t a = kvb + 2*AT_ARR + (uint32_t)((kk*16 + (lane & 15)) * AT_ROW
                                                        + ntp*32 + ((lane >> 4) << 4));
                ldsm_x4_t(vh4, a);
                ldsm_x4_t(vl4, a + AT_ARR);
                mma_f16(o[2*ntp],   ph, vh4);
                mma_f16(o[2*ntp+1], ph, vh4 + 2);
                mma_f16(o[2*ntp],   ph, vl4);
                mma_f16(o[2*ntp+1], ph, vl4 + 2);
            }
        }
        __syncthreads();
        if (t + 2 < ntiles) load_kv(t + 2, t + 2);
    }

    float iA = 1.0f / lA, iB = 1.0f / lB;
    int qA = qb + warp*16 + (lane >> 2);
    size_t rowA = ((size_t)(b*L_ + qA)) * D_;
    size_t rowB = rowA + 8 * D_;
    int cb = h*HD_ + 2*(lane & 3);
    #pragma unroll
    for (int nt = 0; nt < 8; nt++) {
        int c = cb + nt*8;
        float a0 = o[nt][0]*iA, a1 = o[nt][1]*iA;
        float b0 = o[nt][2]*iB, b1 = o[nt][3]*iB;
        unsigned short h0,l0,h1,l1;
        split1(a0,h0,l0); split1(a1,h1,l1);
        *(uint32_t*)(out_hi + rowA + c) = (uint32_t)h0 | ((uint32_t)h1 << 16);
        *(uint32_t*)(out_lo + rowA + c) = (uint32_t)l0 | ((uint32_t)l1 << 16);
        split1(b0,h0,l0); split1(b1,h1,l1);
        *(uint32_t*)(out_hi + rowB + c) = (uint32_t)h0 | ((uint32_t)h1 << 16);
        *(uint32_t*)(out_lo + rowB + c) = (uint32_t)l0 | ((uint32_t)l1 << 16);
    }
}

// ---------------------------------------------------------------------------
// mma.sync cross-attention with tile-range skipping (seg_ids sorted), f16.
// ---------------------------------------------------------------------------
__global__ void __launch_bounds__(128, 2)
cross_attn_mma(const __half* __restrict__ Qh, const __half* __restrict__ Ql,
               const __half* __restrict__ Kh, const __half* __restrict__ Kl,
               const __half* __restrict__ Vh, const __half* __restrict__ Vl,
               const int* __restrict__ seg_ids,
               __half* __restrict__ out_hi, __half* __restrict__ out_lo) {
    extern __shared__ char smraw[];
    const uint32_t sb = (uint32_t)__cvta_generic_to_shared(smraw);
    const int tid = threadIdx.x, warp = tid >> 5, lane = tid & 31;
    const int h = blockIdx.y, b = blockIdx.z;
    const int qb = (int)blockIdx.x * 64;
    const size_t hbQ = ((size_t)(b*H_ + h)) * L_;
    const size_t hbK = ((size_t)(b*H_ + h)) * S_;

    const int rA = qb + warp*16 + (lane >> 2);
    const int segA = seg_ids[b*L_ + rA];
    const int segB = seg_ids[b*L_ + rA + 8];

    const int segF = seg_ids[b*L_ + qb];
    const int segL = seg_ids[b*L_ + qb + 63];
    int t0 = (segF - 127) >> 6; if (t0 < 0) t0 = 0;
    int t1 = segL >> 6;
    const int nte = t1 - t0 + 1;

    #pragma unroll
    for (int i = 0; i < 8; i++) {
        int id = tid + i * 128;
        int arr = id >> 9;
        int rem = id & 511;
        int row = rem >> 3, kc = rem & 7;
        const __half* p = (arr ? Ql : Qh) + (hbQ + qb + row) * HD_ + kc * 8;
        uint32_t d = sb + (uint32_t)(arr * AT_ARR + row * AT_ROW + kc * 16);
        asm volatile("cp.async.cg.shared.global [%0], [%1], 16;" :: "r"(d), "l"(p) : "memory");
    }
    auto load_kv = [&](int t, int slot) {
        uint32_t base = sb + AT_KV0 + (uint32_t)(slot & 1) * AT_STG;
        int k0 = t * 64;
        #pragma unroll
        for (int i = 0; i < 16; i++) {
            int id = tid + i * 128;
            int arr = id >> 9;
            int rem = id & 511;
            int row = rem >> 3, kc = rem & 7;
            const __half* p = (arr==0?Kh:arr==1?Kl:arr==2?Vh:Vl) + (hbK + k0 + row) * HD_ + kc * 8;
            uint32_t d = base + (uint32_t)(arr * AT_ARR + row * AT_ROW + kc * 16);
            asm volatile("cp.async.cg.shared.global [%0], [%1], 16;" :: "r"(d), "l"(p) : "memory");
        }
        asm volatile("cp.async.commit_group;" ::: "memory");
    };
    load_kv(t0, 0);
    if (nte > 1) load_kv(t0 + 1, 1);

    uint32_t qh[4][4], ql[4][4];
    float o[8][4];
    #pragma unroll
    for (int i = 0; i < 8; i++)
        #pragma unroll
        for (int j = 0; j < 4; j++) o[i][j] = 0.f;
    float mA = -1e30f, mB = -1e30f, lA = 0.f, lB = 0.f;

    for (int tt = 0; tt < nte; tt++) {
        const int t = t0 + tt;
        if (tt + 1 < nte) { asm volatile("cp.async.wait_group 1;" ::: "memory"); }
        else              { asm volatile("cp.async.wait_group 0;" ::: "memory"); }
        __syncthreads();
        if (tt == 0) {
            #pragma unroll
            for (int ks = 0; ks < 4; ks++) {
                uint32_t a = sb + (uint32_t)((warp*16 + (lane & 15)) * AT_ROW + ks*32 + (lane >> 4) * 16);
                ldsm_x4(qh[ks], a);
                ldsm_x4(ql[ks], a + AT_ARR);
            }
        }
        const uint32_t kvb = sb + AT_KV0 + (uint32_t)(tt & 1) * AT_STG;

        float s[8][4];
        #pragma unroll
        for (int i = 0; i < 8; i++)
            #pragma unroll
            for (int j = 0; j < 4; j++) s[i][j] = 0.f;
        #pragma unroll
        for (int ks = 0; ks < 4; ks++) {
            uint32_t kh4[4][4], kl4[4][4];
            #pragma unroll
            for (int ntp = 0; ntp < 4; ntp++) {
                uint32_t a = kvb + (uint32_t)((ntp*16 + (lane & 7) + ((lane >> 4) << 3)) * AT_ROW
                                              + ks*32 + (((lane >> 3) & 1) << 4));
                ldsm_x4(kh4[ntp], a);
                ldsm_x4(kl4[ntp], a + AT_ARR);
            }
            #pragma unroll
            for (int ntp = 0; ntp < 4; ntp++) {
                mma_f16(s[2*ntp],   qh[ks], kh4[ntp]);
                mma_f16(s[2*ntp+1], qh[ks], kh4[ntp] + 2);
                mma_f16(s[2*ntp],   qh[ks], kl4[ntp]);
                mma_f16(s[2*ntp+1], qh[ks], kl4[ntp] + 2);
                mma_f16(s[2*ntp],   ql[ks], kh4[ntp]);
                mma_f16(s[2*ntp+1], ql[ks], kh4[ntp] + 2);
            }
        }
        {
            int cbase = t*64 + 2*(lane & 3);
            #pragma unroll
            for (int nt = 0; nt < 8; nt++) {
                int c0 = cbase + nt*8, c1 = c0 + 1;
                if (c0 > segA || c0 <= segA - 128) s[nt][0] = -1e30f;
                if (c1 > segA || c1 <= segA - 128) s[nt][1] = -1e30f;
                if (c0 > segB || c0 <= segB - 128) s[nt][2] = -1e30f;
                if (c1 > segB || c1 <= segB - 128) s[nt][3] = -1e30f;
            }
        }
        float tmA = -1e30f, tmB = -1e30f;
        #pragma unroll
        for (int nt = 0; nt < 8; nt++) {
            tmA = fmaxf(tmA, fmaxf(s[nt][0], s[nt][1]));
            tmB = fmaxf(tmB, fmaxf(s[nt][2], s[nt][3]));
        }
        tmA = fmaxf(tmA, __shfl_xor_sync(0xffffffffu, tmA, 1));
        tmA = fmaxf(tmA, __shfl_xor_sync(0xffffffffu, tmA, 2));
        tmB = fmaxf(tmB, __shfl_xor_sync(0xffffffffu, tmB, 1));
        tmB = fmaxf(tmB, __shfl_xor_sync(0xffffffffu, tmB, 2));
        float nmA = fmaxf(mA, tmA), nmB = fmaxf(mB, tmB);
        float scA = __expf(mA - nmA), scB = __expf(mB - nmB);
        float tsA = 0.f, tsB = 0.f;
        #pragma unroll
        for (int nt = 0; nt < 8; nt++) {
            s[nt][0] = __expf(s[nt][0] - nmA);
            s[nt][1] = __expf(s[nt][1] - nmA);
            s[nt][2] = __expf(s[nt][2] - nmB);
            s[nt][3] = __expf(s[nt][3] - nmB);
            tsA += s[nt][0] + s[nt][1];
            tsB += s[nt][2] + s[nt][3];
        }
        tsA += __shfl_xor_sync(0xffffffffu, tsA, 1);
        tsA += __shfl_xor_sync(0xffffffffu, tsA, 2);
        tsB += __shfl_xor_sync(0xffffffffu, tsB, 1);
        tsB += __shfl_xor_sync(0xffffffffu, tsB, 2);
        lA = lA * scA + tsA;
        lB = lB * scB + tsB;
        #pragma unroll
        for (int nt = 0; nt < 8; nt++) {
            o[nt][0] *= scA; o[nt][1] *= scA;
            o[nt][2] *= scB; o[nt][3] *= scB;
        }
        mA = nmA; mB = nmB;
        #pragma unroll
        for (int kk = 0; kk < 4; kk++) {
            uint32_t ph[4];
            ph[0] = pack_h16x2(s[2*kk][0],   s[2*kk][1]);
            ph[1] = pack_h16x2(s[2*kk][2],   s[2*kk][3]);
            ph[2] = pack_h16x2(s[2*kk+1][0], s[2*kk+1][1]);
            ph[3] = pack_h16x2(s[2*kk+1][2], s[2*kk+1][3]);
            #pragma unroll
            for (int ntp = 0; ntp < 4; ntp++) {
                uint32_t vh4[4], vl4[4];
                uint32_t a = kvb + 2*AT_ARR + (uint32_t)((kk*16 + (lane & 15)) * AT_ROW
                                                        + ntp*32 + ((lane >> 4) << 4));
                ldsm_x4_t(vh4, a);
                ldsm_x4_t(vl4, a + AT_ARR);
                mma_f16(o[2*ntp],   ph, vh4);
                mma_f16(o[2*ntp+1], ph, vh4 + 2);
                mma_f16(o[2*ntp],   ph, vl4);
                mma_f16(o[2*ntp+1], ph, vl4 + 2);
            }
        }
        __syncthreads();
        if (tt + 2 < nte) load_kv(t0 + tt + 2, tt + 2);
    }

    float iA = 1.0f / lA, iB = 1.0f / lB;
    size_t rowA = ((size_t)(b*L_ + rA)) * D_;
    size_t rowB = rowA + 8 * D_;
    int cb = h*HD_ + 2*(lane & 3);
    #pragma unroll
    for (int nt = 0; nt < 8; nt++) {
        int c = cb + nt*8;
        float a0 = o[nt][0]*iA, a1 = o[nt][1]*iA;
        float b0 = o[nt][2]*iB, b1 = o[nt][3]*iB;
        unsigned short h0,l0,h1,l1;
        split1(a0,h0,l0); split1(a1,h1,l1);
        *(uint32_t*)(out_hi + rowA + c) = (uint32_t)h0 | ((uint32_t)h1 << 16);
        *(uint32_t*)(out_lo + rowA + c) = (uint32_t)l0 | ((uint32_t)l1 << 16);
        split1(b0,h0,l0); split1(b1,h1,l1);
        *(uint32_t*)(out_hi + rowB + c) = (uint32_t)h0 | ((uint32_t)h1 << 16);
        *(uint32_t*)(out_lo + rowB + c) = (uint32_t)l0 | ((uint32_t)l1 << 16);
    }
}

// ---------------------------------------------------------------------------
// Launch
// ---------------------------------------------------------------------------
static inline void split_launch(const float* src, __half* hi, __half* lo, size_t n) {
    int n4 = (int)(n / 4);
    split_k<<<n4 / 1024, 256>>>(src, hi, lo);
}

extern "C" void kernel_launch(void* const* d_in, const int* in_sizes, int n_in,
                              void* d_out, int out_size) {
    const float* x      = (const float*)d_in[0];
    const float* memory = (const float*)d_in[1];
    const int*   seg    = (const int*)  d_in[2];
    const float* Wqkv   = (const float*)d_in[3];
    const float* bqkv   = (const float*)d_in[4];
    const float* Wo     = (const float*)d_in[5];
    const float* bo     = (const float*)d_in[6];
    const float* Wq_c   = (const float*)d_in[7];
    const float* Wkv_c  = (const float*)d_in[8];
    const float* Wo_c   = (const float*)d_in[9];
    const float* Wg     = (const float*)d_in[10];
    const float* Wu     = (const float*)d_in[11];
    const float* Wd     = (const float*)d_in[12];
    const float* n1     = (const float*)d_in[13];
    const float* n2     = (const float*)d_in[14];
    const float* n3     = (const float*)d_in[15];
    const float* nf     = (const float*)d_in[16];

    cudaFuncSetAttribute(gemm_f16s<1,false>, cudaFuncAttributeMaxDynamicSharedMemorySize, GSMEM);
    cudaFuncSetAttribute(gemm_f16s<2,false>, cudaFuncAttributeMaxDynamicSharedMemorySize, GSMEM);
    cudaFuncSetAttribute(gemm_f16s<3,false>, cudaFuncAttributeMaxDynamicSharedMemorySize, GSMEM);
    cudaFuncSetAttribute(gemm_f16s<4,true >, cudaFuncAttributeMaxDynamicSharedMemorySize, GSMEM);
    cudaFuncSetAttribute(gemm_f16s<6,true >, cudaFuncAttributeMaxDynamicSharedMemorySize, GSMEM);
    cudaFuncSetAttribute(gemm_f16s<7,true >, cudaFuncAttributeMaxDynamicSharedMemorySize, GSMEM);
    cudaFuncSetAttribute(self_attn_mma,  cudaFuncAttributeMaxDynamicSharedMemorySize, AT_SMEM);
    cudaFuncSetAttribute(cross_attn_mma, cudaFuncAttributeMaxDynamicSharedMemorySize, AT_SMEM);

    float *xb;
    __half *hhi, *hlo, *ahi, *alo, *chi, *clo, *gshi, *gslo, *mhi, *mlo, *whi, *wlo;
    __half *sqh, *sql, *skh, *skl, *svh, *svl;
    __half *ckh, *ckl, *cvh, *cvl;
    cudaGetSymbolAddress((void**)&xb,   g_x);
    cudaGetSymbolAddress((void**)&hhi,  g_h_hi);  cudaGetSymbolAddress((void**)&hlo,  g_h_lo);
    cudaGetSymbolAddress((void**)&ahi,  g_at_hi); cudaGetSymbolAddress((void**)&alo,  g_at_lo);
    cudaGetSymbolAddress((void**)&chi,  g_co_hi); cudaGetSymbolAddress((void**)&clo,  g_co_lo);
    cudaGetSymbolAddress((void**)&gshi, g_gs_hi); cudaGetSymbolAddress((void**)&gslo, g_gs_lo);
    cudaGetSymbolAddress((void**)&mhi,  g_m_hi);  cudaGetSymbolAddress((void**)&mlo,  g_m_lo);
    cudaGetSymbolAddress((void**)&whi,  g_w_hi);  cudaGetSymbolAddress((void**)&wlo,  g_w_lo);
    cudaGetSymbolAddress((void**)&sqh,  g_sqh);   cudaGetSymbolAddress((void**)&sql,  g_sql);
    cudaGetSymbolAddress((void**)&skh,  g_skh);   cudaGetSymbolAddress((void**)&skl,  g_skl);
    cudaGetSymbolAddress((void**)&svh,  g_svh);   cudaGetSymbolAddress((void**)&svl,  g_svl);
    cudaGetSymbolAddress((void**)&ckh,  g_ckh);   cudaGetSymbolAddress((void**)&ckl,  g_ckl);
    cudaGetSymbolAddress((void**)&cvh,  g_cvh);   cudaGetSymbolAddress((void**)&cvl,  g_cvl);

    rope_cache_k<<<256, 256>>>();

    split_launch(Wqkv,  whi + O_WQKV, wlo + O_WQKV, NL*SZ_WQKV);
    split_launch(Wo,    whi + O_WO,   wlo + O_WO,   NL*SZ_WO);
    split_launch(Wq_c,  whi + O_WQC,  wlo + O_WQC,  NL*SZ_WQC);
    split_launch(Wkv_c, whi + O_WKVC, wlo + O_WKVC, NL*SZ_WKVC);
    split_launch(Wo_c,  whi + O_WOC,  wlo + O_WOC,  NL*SZ_WOC);
    for (int l = 0; l < NL; l++) {
        int blocks = (int)((size_t)F_*D_/4/1024);
        split_ilv_k<<<blocks, 256>>>(Wg + (size_t)l*F_*D_,
            whi + O_WGU + l*SZ_WGU, wlo + O_WGU + l*SZ_WGU, 0);
        split_ilv_k<<<blocks, 256>>>(Wu + (size_t)l*F_*D_,
            whi + O_WGU + l*SZ_WGU, wlo + O_WGU + l*SZ_WGU, 1);
    }
    split_launch(Wd,    whi + O_WD,   wlo + O_WD,   NL*SZ_WD);
    split_launch(memory, mhi, mlo, (size_t)B_*S_*D_);

    // upfront: all 4 layers' cross K/V in one GEMM (layer-independent)
    gemm_f16s<7,true><<<dim3(NL*2*D_/128, (B_*S_)/256), 256, GSMEM>>>(
        mhi, mlo, whi + O_WKVC, wlo + O_WKVC, nullptr, nullptr, nullptr,
        ckh, ckl, cvh, cvl, nullptr, nullptr, NL*2*D_, D_);

    const dim3 self_grid(L_/64, H_, B_);
    const dim3 cross_grid(L_/64, H_, B_);

    for (int l = 0; l < NL; l++) {
        const __half* wqkv_h = whi + O_WQKV + l*SZ_WQKV;
        const __half* wqkv_l = wlo + O_WQKV + l*SZ_WQKV;
        const __half* wo_h   = whi + O_WO   + l*SZ_WO;
        const __half* wo_l   = wlo + O_WO   + l*SZ_WO;
        const __half* wqc_h  = whi + O_WQC  + l*SZ_WQC;
        const __half* wqc_l  = wlo + O_WQC  + l*SZ_WQC;
        const __half* woc_h  = whi + O_WOC  + l*SZ_WOC;
        const __half* woc_l  = wlo + O_WOC  + l*SZ_WOC;
        const __half* wgu_h  = whi + O_WGU  + l*SZ_WGU;
        const __half* wgu_l  = wlo + O_WGU  + l*SZ_WGU;
        const __half* wd_h   = whi + O_WD   + l*SZ_WD;
        const __half* wd_l   = wlo + O_WD   + l*SZ_WD;

        const float* xsrc = (l == 0) ? x : xb;    // residual stream source

        // --- self attention block (QKV GEMM fuses bias+RoPE+split; exp path, 3-term) ---
        rmsnorm_split_k<<<M_, 256>>>(xsrc, n1 + l*D_, hhi, hlo);
        gemm_f16s<6,true><<<dim3(3*D_/128, M_/256), 256, GSMEM>>>(
            hhi, hlo, wqkv_h, wqkv_l, bqkv + l*3*D_, nullptr, nullptr,
            sqh, sql, skh, skl, svh, svl, 3*D_, D_);
        self_attn_mma<<<self_grid, 128, AT_SMEM>>>(sqh, sql, skh, skl, svh, svl, ahi, alo);
        gemm_f16s<1,false><<<dim3(D_/128, M_/256), 256, GSMEM>>>(
            ahi, alo, wo_h, wo_l, bo + l*D_, xb, xsrc,
            nullptr, nullptr, nullptr, nullptr, nullptr, nullptr, D_, D_);

        // --- cross attention block (Wqc exp path 3-term; Wo_c linear 2-term) ---
        rmsnorm_split_k<<<M_, 256>>>(xb, n2 + l*D_, hhi, hlo);
        gemm_f16s<4,true><<<dim3(D_/128, M_/256), 256, GSMEM>>>(
            hhi, hlo, wqc_h, wqc_l, nullptr, nullptr, nullptr,
            sqh, sql, nullptr, nullptr, nullptr, nullptr, D_, D_);
        cross_attn_mma<<<cross_grid, 128, AT_SMEM>>>(
            sqh, sql, ckh + l*CATN, ckl + l*CATN, cvh + l*CATN, cvl + l*CATN,
            seg, chi, clo);
        gemm_f16s<2,false><<<dim3(D_/128, M_/256), 256, GSMEM>>>(
            chi, clo, woc_h, woc_l, nullptr, xb, xb,
            nullptr, nullptr, nullptr, nullptr, nullptr, nullptr, D_, D_);

        // --- MLP block (2-term f16 linear paths) ---
        rmsnorm_split_k<<<M_, 256>>>(xb, n3 + l*D_, hhi, hlo);
        gemm_f16s<3,false><<<dim3(2*F_/128, M_/256), 256, GSMEM>>>(
            hhi, hlo, wgu_h, wgu_l, nullptr, nullptr, nullptr,
            gshi, gslo, nullptr, nullptr, nullptr, nullptr, 2*F_, D_);
        gemm_f16s<2,false><<<dim3(D_/128, M_/256), 256, GSMEM>>>(
            gshi, gslo, wd_h, wd_l, nullptr, xb, xb,
            nullptr, nullptr, nullptr, nullptr, nullptr, nullptr, D_, F_);
    }

    rmsnorm_k<<<M_, 256>>>(xb, nf, (float*)d_out);
}

// round 16
// speedup vs baseline: 6.1314x; 1.0539x over previous
#include <cuda_runtime.h>
#include <cuda_fp16.h>
#include <math.h>
#include <stdint.h>

// Problem constants
#define NL 4
#define B_ 2
#define L_ 2048
#define S_ 256
#define D_ 1024
#define F_ 4096
#define H_ 16
#define HD_ 64
#define M_ (B_*L_)          // 4096 token rows

// Weight region sizes (elements) and offsets in the concatenated split buffer
#define SZ_WQKV ((size_t)3*D_*D_)
#define SZ_WO   ((size_t)D_*D_)
#define SZ_WQC  ((size_t)D_*D_)
#define SZ_WKVC ((size_t)2*D_*D_)
#define SZ_WOC  ((size_t)D_*D_)
#define SZ_WGU  ((size_t)2*F_*D_)     // interleaved [g0,u0,g1,u1,...] per layer
#define SZ_WD   ((size_t)D_*F_)
static const size_t O_WQKV = 0;
static const size_t O_WO   = O_WQKV + NL*SZ_WQKV;
static const size_t O_WQC  = O_WO   + NL*SZ_WO;
static const size_t O_WKVC = O_WQC  + NL*SZ_WQC;
static const size_t O_WOC  = O_WKVC + NL*SZ_WKVC;
static const size_t O_WGU  = O_WOC  + NL*SZ_WOC;
static const size_t O_WD   = O_WGU  + NL*SZ_WGU;
#define WTOT (O_WD + NL*SZ_WD)

// ---------------------------------------------------------------------------
// Scratch (device globals; no allocations allowed)
// ---------------------------------------------------------------------------
__device__ float g_x  [M_*D_];
__device__ float g_cos[L_*32];
__device__ float g_sin[L_*32];

__device__ __half g_h_hi [M_*D_],  g_h_lo [M_*D_];
__device__ __half g_at_hi[M_*D_],  g_at_lo[M_*D_];
__device__ __half g_co_hi[M_*D_],  g_co_lo[M_*D_];
__device__ __half g_gs_hi[M_*F_],  g_gs_lo[M_*F_];
__device__ __half g_m_hi [B_*S_*D_], g_m_lo[B_*S_*D_];
__device__ __half g_w_hi[WTOT], g_w_lo[WTOT];

// attention-layout split buffers: [B][H][L][64] (self q/k/v; cross q reuses q)
#define ATN ((size_t)B_*H_*L_*HD_)
__device__ __half g_sqh[ATN], g_sql[ATN];
__device__ __half g_skh[ATN], g_skl[ATN];
__device__ __half g_svh[ATN], g_svl[ATN];

// per-layer cross K/V: [NL][B][H][S][64]
#define CATN ((size_t)B_*H_*S_*HD_)
__device__ __half g_ckh[NL*CATN], g_ckl[NL*CATN];
__device__ __half g_cvh[NL*CATN], g_cvl[NL*CATN];

// ---------------------------------------------------------------------------
// f16 split helpers
// ---------------------------------------------------------------------------
__device__ __forceinline__ void split1(float v, unsigned short& h, unsigned short& l) {
    __half hb = __float2half_rn(v);
    float r = v - __half2float(hb);
    __half lb = __float2half_rn(r);
    h = __half_as_ushort(hb);
    l = __half_as_ushort(lb);
}
__device__ __forceinline__ void split_pack4(float4 v, uint2& ph, uint2& pl) {
    unsigned short h0,h1,h2,h3,l0,l1,l2,l3;
    split1(v.x,h0,l0); split1(v.y,h1,l1); split1(v.z,h2,l2); split1(v.w,h3,l3);
    ph.x = (uint32_t)h0 | ((uint32_t)h1 << 16);
    ph.y = (uint32_t)h2 | ((uint32_t)h3 << 16);
    pl.x = (uint32_t)l0 | ((uint32_t)l1 << 16);
    pl.y = (uint32_t)l2 | ((uint32_t)l3 << 16);
}

// 4-quad ILP split (exact grids: n4 multiple of 1024)
__global__ void split_k(const float* __restrict__ in, __half* __restrict__ hi,
                        __half* __restrict__ lo) {
    int i = blockIdx.x * 1024 + threadIdx.x;
    float4 v[4];
    #pragma unroll
    for (int j = 0; j < 4; j++) v[j] = ((const float4*)in)[i + 256*j];
    #pragma unroll
    for (int j = 0; j < 4; j++) {
        uint2 ph, pl; split_pack4(v[j], ph, pl);
        ((uint2*)hi)[i + 256*j] = ph;
        ((uint2*)lo)[i + 256*j] = pl;
    }
}

// Interleaving split for GU weights: src row r (256 quads/row) -> dst row 2r+off
__global__ void split_ilv_k(const float* __restrict__ in, __half* __restrict__ hi,
                            __half* __restrict__ lo, int off) {
    int i0 = blockIdx.x * 1024 + threadIdx.x;
    float4 v[4];
    #pragma unroll
    for (int j = 0; j < 4; j++) v[j] = ((const float4*)in)[i0 + 256*j];
    #pragma unroll
    for (int j = 0; j < 4; j++) {
        int i = i0 + 256*j;
        int r = i >> 8, c = i & 255;
        uint2 ph, pl; split_pack4(v[j], ph, pl);
        size_t oi = (size_t)(2*r + off) * 256 + c;
        ((uint2*)hi)[oi] = ph;
        ((uint2*)lo)[oi] = pl;
    }
}

// ---------------------------------------------------------------------------
// RoPE cache
// ---------------------------------------------------------------------------
__global__ void rope_cache_k() {
    int idx = blockIdx.x * blockDim.x + threadIdx.x;
    int l = idx >> 5, i = idx & 31;
    double inv = exp(-log(10000.0) * (double)i / 32.0);
    double f = (double)l * inv;
    g_cos[idx] = (float)cos(f);
    g_sin[idx] = (float)sin(f);
}

// ---------------------------------------------------------------------------
// RMSNorm kernels
// ---------------------------------------------------------------------------
__global__ void rmsnorm_split_k(const float* __restrict__ x, const float* __restrict__ w,
                                __half* __restrict__ hi, __half* __restrict__ lo) {
    int row = blockIdx.x;
    int t = threadIdx.x;
    const float4* xr = (const float4*)(x + (size_t)row * D_);
    float4 v = xr[t];
    float ss = v.x*v.x + v.y*v.y + v.z*v.z + v.w*v.w;
    #pragma unroll
    for (int off = 16; off; off >>= 1) ss += __shfl_xor_sync(0xffffffffu, ss, off);
    __shared__ float red[8];
    if ((t & 31) == 0) red[t >> 5] = ss;
    __syncthreads();
    float tot = red[0]+red[1]+red[2]+red[3]+red[4]+red[5]+red[6]+red[7];
    float rs = rsqrtf(tot * (1.0f / (float)D_) + 1e-6f);
    float4 wv = ((const float4*)w)[t];
    float4 o;
    o.x = v.x * rs * wv.x; o.y = v.y * rs * wv.y;
    o.z = v.z * rs * wv.z; o.w = v.w * rs * wv.w;
    uint2 ph, pl; split_pack4(o, ph, pl);
    ((uint2*)hi)[(size_t)row * 256 + t] = ph;
    ((uint2*)lo)[(size_t)row * 256 + t] = pl;
}

__global__ void rmsnorm_k(const float* __restrict__ x, const float* __restrict__ w,
                          float* __restrict__ o) {
    int row = blockIdx.x;
    int t = threadIdx.x;
    const float4* xr = (const float4*)(x + (size_t)row * D_);
    float4 v = xr[t];
    float ss = v.x*v.x + v.y*v.y + v.z*v.z + v.w*v.w;
    #pragma unroll
    for (int off = 16; off; off >>= 1) ss += __shfl_xor_sync(0xffffffffu, ss, off);
    __shared__ float red[8];
    if ((t & 31) == 0) red[t >> 5] = ss;
    __syncthreads();
    float tot = red[0]+red[1]+red[2]+red[3]+red[4]+red[5]+red[6]+red[7];
    float rs = rsqrtf(tot * (1.0f / (float)D_) + 1e-6f);
    float4 wv = ((const float4*)w)[t];
    float4 out;
    out.x = v.x * rs * wv.x; out.y = v.y * rs * wv.y;
    out.z = v.z * rs * wv.z; out.w = v.w * rs * wv.w;
    ((float4*)(o + (size_t)row * D_))[t] = out;
}

// ---------------------------------------------------------------------------
// mma / ldmatrix helpers (f16)
// ---------------------------------------------------------------------------
__device__ __forceinline__ void mma_f16(float* c, const uint32_t* a, const uint32_t* b) {
    asm volatile(
        "mma.sync.aligned.m16n8k16.row.col.f32.f16.f16.f32 "
        "{%0,%1,%2,%3}, {%4,%5,%6,%7}, {%8,%9}, {%0,%1,%2,%3};"
        : "+f"(c[0]), "+f"(c[1]), "+f"(c[2]), "+f"(c[3])
        : "r"(a[0]), "r"(a[1]), "r"(a[2]), "r"(a[3]), "r"(b[0]), "r"(b[1]));
}
__device__ __forceinline__ void ldsm_x4(uint32_t* r, uint32_t addr) {
    asm volatile("ldmatrix.sync.aligned.m8n8.x4.shared.b16 {%0,%1,%2,%3}, [%4];"
        : "=r"(r[0]), "=r"(r[1]), "=r"(r[2]), "=r"(r[3]) : "r"(addr));
}
__device__ __forceinline__ void ldsm_x4_t(uint32_t* r, uint32_t addr) {
    asm volatile("ldmatrix.sync.aligned.m8n8.x4.trans.shared.b16 {%0,%1,%2,%3}, [%4];"
        : "=r"(r[0]), "=r"(r[1]), "=r"(r[2]), "=r"(r[3]) : "r"(addr));
}
__device__ __forceinline__ uint32_t pack_h16x2(float lo, float hi) {
    return (uint32_t)__half_as_ushort(__float2half_rn(lo)) |
           ((uint32_t)__half_as_ushort(__float2half_rn(hi)) << 16);
}

// ---------------------------------------------------------------------------
// f16 split GEMM (NT), 256x128 CTA tile, warp tile 64x64 (8 warps, 4x2).
// THREE=true:  C = AhWh + AhWl + AlWh  (exp-feeding paths: QKV, Wqc, crossKV)
// THREE=false: C = AhWh + AhWl         (linear paths; ~1e-5 rel_err per site)
// MODE 1: +bias +residual(Rsrc) -> fp32 C   (Wo)
// MODE 2: +residual(Rsrc)       -> fp32 C   (Wo_c, Wd)
// MODE 3: swiglu (interleaved g|u cols) -> f16 hi/lo [M][F]
// MODE 4: attn-q layout, x0.125         -> f16 hi/lo [B][H][L][64]
// MODE 6: QKV: +bias, RoPE on q/k, q x0.125 -> q/k/v f16 hi/lo [B][H][L][64]
// MODE 7: multi-layer cross-KV           -> per-layer k/v [NL][B][H][S][64]
// ---------------------------------------------------------------------------
#define G2STAGE 61440
#define G2_AL   20480
#define G2_B0   40960
#define G2_B1   51200
#define GSMEM   (3*G2STAGE)

template <int MODE, bool THREE>
__global__ void __launch_bounds__(256, 1)
gemm_f16s(const __half* __restrict__ Ah, const __half* __restrict__ Al,
          const __half* __restrict__ Wh, const __half* __restrict__ Wl,
          const float* __restrict__ bias, float* __restrict__ C,
          const float* __restrict__ Rsrc,
          __half* __restrict__ o1h, __half* __restrict__ o1l,
          __half* __restrict__ o2h, __half* __restrict__ o2l,
          __half* __restrict__ o3h, __half* __restrict__ o3l,
          int N, int K) {
    extern __shared__ char smem[];
    const uint32_t sbase = (uint32_t)__cvta_generic_to_shared(smem);
    const int tid  = threadIdx.x;
    const int warp = tid >> 5, lane = tid & 31;
    const int wr = warp >> 1;      // 0..3 : 64-row slab
    const int wc = warp & 1;       // 0..1 : 64-col slab
    const int g  = lane >> 2;
    const int t  = lane & 3;
    const int bm = blockIdx.y, bn = blockIdx.x;

    // cp.async chunk tables: 3072 16B-chunks per stage, 12 per thread
    // chunks i=4..7 are the A-lo array (skipped when !THREE)
    const __half* src[12];
    uint32_t dst[12];
    #pragma unroll
    for (int i = 0; i < 12; i++) {
        int id = tid + (i << 8);
        const __half* bp;
        int grow; uint32_t off; int kc;
        if (id < 2048) {
            int arr = id >> 10, rem = id & 1023;
            int row = rem >> 2; kc = rem & 3;
            bp = arr ? Al : Ah;
            grow = bm * 256 + row;
            off = (uint32_t)(arr * G2_AL + row * 80 + kc * 16);
        } else {
            int id2 = id - 2048;
            int arr = id2 >> 9, rem = id2 & 511;
            int row = rem >> 2; kc = rem & 3;
            bp = arr ? Wl : Wh;
            grow = bn * 128 + row;
            off = (uint32_t)(G2_B0 + arr * 10240 + row * 80 + kc * 16);
        }
        src[i] = bp + (size_t)grow * K + kc * 8;
        dst[i] = off;
    }

    const uint32_t arow = (uint32_t)((wr * 64 + (lane & 15)) * 80 + (lane >> 4) * 16);
    const uint32_t brow = (uint32_t)((wc * 64 + (lane & 7) + ((lane >> 4) << 3)) * 80
                                     + (((lane >> 3) & 1) << 4));

    float acc[4][8][4];
    #pragma unroll
    for (int i = 0; i < 4; i++)
        #pragma unroll
        for (int j = 0; j < 8; j++)
            #pragma unroll
            for (int r = 0; r < 4; r++) acc[i][j][r] = 0.f;

    const int nk = K >> 5;

    #pragma unroll
    for (int st = 0; st < 2; st++) {
        uint32_t s = sbase + st * G2STAGE;
        #pragma unroll
        for (int i = 0; i < 12; i++) {
            if (!THREE && i >= 4 && i < 8) continue;
            const void* p = src[i] + st * 32;
            asm volatile("cp.async.cg.shared.global [%0], [%1], 16;"
                         :: "r"(s + dst[i]), "l"(p) : "memory");
        }
        asm volatile("cp.async.commit_group;" ::: "memory");
    }

    for (int it = 0; it < nk; it++) {
        asm volatile("cp.async.wait_group 1;" ::: "memory");
        __syncthreads();
        uint32_t s = sbase + (uint32_t)(it % 3) * G2STAGE;

        #pragma unroll
        for (int ks = 0; ks < 2; ks++) {
            const uint32_t ko = ks * 32;
            uint32_t af[16], bh[16], bl[16];
            #pragma unroll
            for (int mt = 0; mt < 4; mt++) ldsm_x4(af + 4*mt, s + arow + mt*1280 + ko);
            #pragma unroll
            for (int p = 0; p < 4; p++) ldsm_x4(bh + 4*p, s + G2_B0 + brow + p*1280 + ko);
            #pragma unroll
            for (int p = 0; p < 4; p++) ldsm_x4(bl + 4*p, s + G2_B1 + brow + p*1280 + ko);
            #pragma unroll
            for (int mt = 0; mt < 4; mt++)
                #pragma unroll
                for (int nt = 0; nt < 8; nt++) mma_f16(acc[mt][nt], af + 4*mt, bh + 2*nt);
            #pragma unroll
            for (int mt = 0; mt < 4; mt++)
                #pragma unroll
                for (int nt = 0; nt < 8; nt++) mma_f16(acc[mt][nt], af + 4*mt, bl + 2*nt);
            if (THREE) {
                #pragma unroll
                for (int mt = 0; mt < 4; mt++) ldsm_x4(af + 4*mt, s + G2_AL + arow + mt*1280 + ko);
                #pragma unroll
                for (int mt = 0; mt < 4; mt++)
                    #pragma unroll
                    for (int nt = 0; nt < 8; nt++) mma_f16(acc[mt][nt], af + 4*mt, bh + 2*nt);
            }
        }

        if (it + 2 < nk) {
            uint32_t s2 = sbase + (uint32_t)((it + 2) % 3) * G2STAGE;
            int k0 = (it + 2) * 32;
            #pragma unroll
            for (int i = 0; i < 12; i++) {
                if (!THREE && i >= 4 && i < 8) continue;
                const void* p = src[i] + k0;
                asm volatile("cp.async.cg.shared.global [%0], [%1], 16;"
                             :: "r"(s2 + dst[i]), "l"(p) : "memory");
            }
        }
        asm volatile("cp.async.commit_group;" ::: "memory");
    }

    if (MODE == 6) {
        // QKV epilogue: bias + RoPE (q,k) + split into attention layout.
        const int part = (bn * 128 + wc * 64) >> 10;
        #pragma unroll
        for (int mt = 0; mt < 4; mt++) {
            #pragma unroll
            for (int half = 0; half < 2; half++) {
                int row = bm * 256 + wr * 64 + mt * 16 + g + half * 8;
                int b = row >> 11, ltok = row & (L_ - 1);
                if (part < 2) {
                    #pragma unroll
                    for (int np = 0; np < 4; np++) {
                        int col = bn*128 + wc*64 + np*8 + 2*t;
                        int pcol = col & 1023;
                        int head = pcol >> 6;
                        int i = pcol & 31;
                        float c0 = g_cos[ltok*32 + i],     s0 = g_sin[ltok*32 + i];
                        float c1 = g_cos[ltok*32 + i + 1], s1 = g_sin[ltok*32 + i + 1];
                        float x1a = acc[mt][np  ][half*2+0] + bias[col];
                        float x1b = acc[mt][np  ][half*2+1] + bias[col+1];
                        float x2a = acc[mt][np+4][half*2+0] + bias[col+32];
                        float x2b = acc[mt][np+4][half*2+1] + bias[col+33];
                        float r1a = x1a*c0 - x2a*s0, r2a = x2a*c0 + x1a*s0;
                        float r1b = x1b*c1 - x2b*s1, r2b = x2b*c1 + x1b*s1;
                        __half *oh, *ol;
                        if (part == 0) {
                            r1a *= 0.125f; r1b *= 0.125f; r2a *= 0.125f; r2b *= 0.125f;
                            oh = o1h; ol = o1l;
                        } else { oh = o2h; ol = o2l; }
                        size_t oi = (((size_t)(b*H_ + head)) * L_ + ltok) * HD_ + i;
                        unsigned short h0, l0, h1, l1;
                        split1(r1a, h0, l0); split1(r1b, h1, l1);
                        *(uint32_t*)(oh + oi) = (uint32_t)h0 | ((uint32_t)h1 << 16);
                        *(uint32_t*)(ol + oi) = (uint32_t)l0 | ((uint32_t)l1 << 16);
                        split1(r2a, h0, l0); split1(r2b, h1, l1);
                        *(uint32_t*)(oh + oi + 32) = (uint32_t)h0 | ((uint32_t)h1 << 16);
                        *(uint32_t*)(ol + oi + 32) = (uint32_t)l0 | ((uint32_t)l1 << 16);
                    }
                } else {
                    #pragma unroll
                    for (int nt = 0; nt < 8; nt++) {
                        int col = bn*128 + wc*64 + nt*8 + 2*t;
                        int pcol = col & 1023;
                        int head = pcol >> 6, d = pcol & 63;
                        float c0 = acc[mt][nt][half*2+0] + bias[col];
                        float c1 = acc[mt][nt][half*2+1] + bias[col+1];
                        size_t oi = (((size_t)(b*H_ + head)) * L_ + ltok) * HD_ + d;
                        unsigned short h0, l0, h1, l1;
                        split1(c0, h0, l0); split1(c1, h1, l1);
                        *(uint32_t*)(o3h + oi) = (uint32_t)h0 | ((uint32_t)h1 << 16);
                        *(uint32_t*)(o3l + oi) = (uint32_t)l0 | ((uint32_t)l1 << 16);
                    }
                }
            }
        }
        return;
    }

    #pragma unroll
    for (int mt = 0; mt < 4; mt++) {
        #pragma unroll
        for (int half = 0; half < 2; half++) {
            int row = bm * 256 + wr * 64 + mt * 16 + g + half * 8;
            #pragma unroll
            for (int nt = 0; nt < 8; nt++) {
                int col = bn * 128 + wc * 64 + nt * 8 + 2 * t;
                float c0 = acc[mt][nt][half * 2 + 0];
                float c1 = acc[mt][nt][half * 2 + 1];
                if (MODE <= 2) {
                    float* dstp = C + (size_t)row * N + col;
                    const float* rp = Rsrc + (size_t)row * N + col;
                    if (MODE == 1) { c0 += bias[col]; c1 += bias[col + 1]; }
                    float2 r = *(const float2*)rp;
                    c0 += r.x; c1 += r.y;
                    *(float2*)dstp = make_float2(c0, c1);
                } else if (MODE == 3) {
                    float sg = c0 / (1.0f + expf(-c0)) * c1;
                    unsigned short hh, ll; split1(sg, hh, ll);
                    size_t oi = (size_t)row * F_ + (col >> 1);
                    o1h[oi] = __ushort_as_half(hh);
                    o1l[oi] = __ushort_as_half(ll);
                } else if (MODE == 4) {
                    int b = row >> 11, ltok = row & (L_ - 1);
                    int hd = col >> 6, d = col & 63;
                    size_t oi = (((size_t)(b*H_ + hd)) * L_ + ltok) * HD_ + d;
                    unsigned short h0, l0, h1, l1;
                    split1(c0 * 0.125f, h0, l0); split1(c1 * 0.125f, h1, l1);
                    *(uint32_t*)(o1h + oi) = (uint32_t)h0 | ((uint32_t)h1 << 16);
                    *(uint32_t*)(o1l + oi) = (uint32_t)l0 | ((uint32_t)l1 << 16);
                } else { // MODE 7: multi-layer cross-KV
                    int layer = col >> 11;
                    int c2 = col & 2047;
                    int kv = c2 >> 10;
                    int hd = (c2 >> 6) & 15, d = c2 & 63;
                    int b = row >> 8, stok = row & (S_ - 1);
                    size_t oi = (size_t)layer * CATN
                              + (((size_t)(b*H_ + hd)) * S_ + stok) * HD_ + d;
                    unsigned short h0, l0, h1, l1;
                    split1(c0, h0, l0); split1(c1, h1, l1);
                    __half* ph = kv ? o2h : o1h;
                    __half* pl = kv ? o2l : o1l;
                    *(uint32_t*)(ph + oi) = (uint32_t)h0 | ((uint32_t)h1 << 16);
                    *(uint32_t*)(pl + oi) = (uint32_t)l0 | ((uint32_t)l1 << 16);
                }
            }
        }
    }
}

// ---------------------------------------------------------------------------
// mma.sync flash self-attention (f16). K and V single-f16 (lo dropped; f16
// quantization noise calibrated benign). S = (Qh+Ql)·Kh; O += P·Vh.
// K/V stage = 2 arrays (half the loads/smem of the split version).
// ---------------------------------------------------------------------------
#define AT_ROW  144
#define AT_ARR  (64*AT_ROW)
#define AT_KV0  (2*AT_ARR)
#define AT_STG  (2*AT_ARR)
#define AT_SMEM (2*AT_ARR + 2*AT_STG)

__global__ void __launch_bounds__(128, 2)
self_attn_mma(const __half* __restrict__ Qh, const __half* __restrict__ Ql,
              const __half* __restrict__ Kh, const __half* __restrict__ Vh,
              __half* __restrict__ out_hi, __half* __restrict__ out_lo) {
    extern __shared__ char smraw[];
    const uint32_t sb = (uint32_t)__cvta_generic_to_shared(smraw);
    const int tid = threadIdx.x, warp = tid >> 5, lane = tid & 31;
    const int h = blockIdx.y, b = blockIdx.z;
    const int qbi = (int)(gridDim.x - 1 - blockIdx.x);
    const int qb = qbi * 64;
    const int ntiles = qbi + 1;
    const size_t hb = ((size_t)(b*H_ + h)) * L_;

    #pragma unroll
    for (int i = 0; i < 8; i++) {
        int id = tid + i * 128;
        int arr = id >> 9;
        int rem = id & 511;
        int row = rem >> 3, kc = rem & 7;
        const __half* p = (arr ? Ql : Qh) + (hb + qb + row) * HD_ + kc * 8;
        uint32_t d = sb + (uint32_t)(arr * AT_ARR + row * AT_ROW + kc * 16);
        asm volatile("cp.async.cg.shared.global [%0], [%1], 16;" :: "r"(d), "l"(p) : "memory");
    }
    auto load_kv = [&](int t, int slot) {
        uint32_t base = sb + AT_KV0 + (uint32_t)(slot & 1) * AT_STG;
        int k0 = t * 64;
        #pragma unroll
        for (int i = 0; i < 8; i++) {
            int id = tid + i * 128;          // 0..1023
            int arr = id >> 9;               // 0:Kh 1:Vh
            int rem = id & 511;
            int row = rem >> 3, kc = rem & 7;
            const __half* p = (arr ? Vh : Kh) + (hb + k0 + row) * HD_ + kc * 8;
            uint32_t d = base + (uint32_t)(arr * AT_ARR + row * AT_ROW + kc * 16);
            asm volatile("cp.async.cg.shared.global [%0], [%1], 16;" :: "r"(d), "l"(p) : "memory");
        }
        asm volatile("cp.async.commit_group;" ::: "memory");
    };
    load_kv(0, 0);
    if (ntiles > 1) load_kv(1, 1);

    uint32_t qh[4][4], ql[4][4];
    float o[8][4];
    #pragma unroll
    for (int i = 0; i < 8; i++)
        #pragma unroll
        for (int j = 0; j < 4; j++) o[i][j] = 0.f;
    float mA = -1e30f, mB = -1e30f, lA = 0.f, lB = 0.f;

    for (int t = 0; t < ntiles; t++) {
        if (t + 1 < ntiles) { asm volatile("cp.async.wait_group 1;" ::: "memory"); }
        else                { asm volatile("cp.async.wait_group 0;" ::: "memory"); }
        __syncthreads();
        if (t == 0) {
            #pragma unroll
            for (int ks = 0; ks < 4; ks++) {
                uint32_t a = sb + (uint32_t)((warp*16 + (lane & 15)) * AT_ROW + ks*32 + (lane >> 4) * 16);
                ldsm_x4(qh[ks], a);
                ldsm_x4(ql[ks], a + AT_ARR);
            }
        }
        const uint32_t kvb = sb + AT_KV0 + (uint32_t)(t & 1) * AT_STG;

        float s[8][4];
        #pragma unroll
        for (int i = 0; i < 8; i++)
            #pragma unroll
            for (int j = 0; j < 4; j++) s[i][j] = 0.f;
        #pragma unroll
        for (int ks = 0; ks < 4; ks++) {
            uint32_t kh4[4][4];
            #pragma unroll
            for (int ntp = 0; ntp < 4; ntp++) {
                uint32_t a = kvb + (uint32_t)((ntp*16 + (lane & 7) + ((lane >> 4) << 3)) * AT_ROW
                                              + ks*32 + (((lane >> 3) & 1) << 4));
                ldsm_x4(kh4[ntp], a);
            }
            #pragma unroll
            for (int ntp = 0; ntp < 4; ntp++) {
                mma_f16(s[2*ntp],   qh[ks], kh4[ntp]);
                mma_f16(s[2*ntp+1], qh[ks], kh4[ntp] + 2);
                mma_f16(s[2*ntp],   ql[ks], kh4[ntp]);
                mma_f16(s[2*ntp+1], ql[ks], kh4[ntp] + 2);
            }
        }
        if (t == ntiles - 1) {
            int rA = qb + warp*16 + (lane >> 2);
            int cbase = t*64 + 2*(lane & 3);
            #pragma unroll
            for (int nt = 0; nt < 8; nt++) {
                int c0 = cbase + nt*8, c1 = c0 + 1;
                if (c0 > rA)     s[nt][0] = -1e30f;
                if (c1 > rA)     s[nt][1] = -1e30f;
                if (c0 > rA + 8) s[nt][2] = -1e30f;
                if (c1 > rA + 8) s[nt][3] = -1e30f;
            }
        }
        float tmA = -1e30f, tmB = -1e30f;
        #pragma unroll
        for (int nt = 0; nt < 8; nt++) {
            tmA = fmaxf(tmA, fmaxf(s[nt][0], s[nt][1]));
            tmB = fmaxf(tmB, fmaxf(s[nt][2], s[nt][3]));
        }
        tmA = fmaxf(tmA, __shfl_xor_sync(0xffffffffu, tmA, 1));
        tmA = fmaxf(tmA, __shfl_xor_sync(0xffffffffu, tmA, 2));
        tmB = fmaxf(tmB, __shfl_xor_sync(0xffffffffu, tmB, 1));
        tmB = fmaxf(tmB, __shfl_xor_sync(0xffffffffu, tmB, 2));
        float nmA = fmaxf(mA, tmA), nmB = fmaxf(mB, tmB);
        float scA = __expf(mA - nmA), scB = __expf(mB - nmB);
        float tsA = 0.f, tsB = 0.f;
        #pragma unroll
        for (int nt = 0; nt < 8; nt++) {
            s[nt][0] = __expf(s[nt][0] - nmA);
            s[nt][1] = __expf(s[nt][1] - nmA);
            s[nt][2] = __expf(s[nt][2] - nmB);
            s[nt][3] = __expf(s[nt][3] - nmB);
            tsA += s[nt][0] + s[nt][1];
            tsB += s[nt][2] + s[nt][3];
        }
        tsA += __shfl_xor_sync(0xffffffffu, tsA, 1);
        tsA += __shfl_xor_sync(0xffffffffu, tsA, 2);
        tsB += __shfl_xor_sync(0xffffffffu, tsB, 1);
        tsB += __shfl_xor_sync(0xffffffffu, tsB, 2);
        lA = lA * scA + tsA;
        lB = lB * scB + tsB;
        #pragma unroll
        for (int nt = 0; nt < 8; nt++) {
            o[nt][0] *= scA; o[nt][1] *= scA;
            o[nt][2] *= scB; o[nt][3] *= scB;
        }
        mA = nmA; mB = nmB;
        #pragma unroll
        for (int kk = 0; kk < 4; kk++) {
            uint32_t ph[4];
            ph[0] = pack_h16x2(s[2*kk][0],   s[2*kk][1]);
            ph[1] = pack_h16x2(s[2*kk][2],   s[2*kk][3]);
            ph[2] = pack_h16x2(s[2*kk+1][0], s[2*kk+1][1]);
            ph[3] = pack_h16x2(s[2*kk+1][2], s[2*kk+1][3]);
            #pragma unroll
            for (int ntp = 0; ntp < 4; ntp++) {
                uint32_t vh4[4];
                uint32_t a = kvb + AT_ARR + (uint32_t)((kk*16 + (lane & 15)) * AT_ROW
                                                      + ntp*32 + ((lane >> 4) << 4));
                ldsm_x4_t(vh4, a);
                mma_f16(o[2*ntp],   ph, vh4);
                mma_f16(o[2*ntp+1], ph, vh4 + 2);
            }
        }
        __syncthreads();
        if (t + 2 < ntiles) load_kv(t + 2, t + 2);
    }

    float iA = 1.0f / lA, iB = 1.0f / lB;
    int qA = qb + warp*16 + (lane >> 2);
    size_t rowA = ((size_t)(b*L_ + qA)) * D_;
    size_t rowB = rowA + 8 * D_;
    int cb = h*HD_ + 2*(lane & 3);
    #pragma unroll
    for (int nt = 0; nt < 8; nt++) {
        int c = cb + nt*8;
        float a0 = o[nt][0]*iA, a1 = o[nt][1]*iA;
        float b0 = o[nt][2]*iB, b1 = o[nt][3]*iB;
        unsigned short h0,l0,h1,l1;
        split1(a0,h0,l0); split1(a1,h1,l1);
        *(uint32_t*)(out_hi + rowA + c) = (uint32_t)h0 | ((uint32_t)h1 << 16);
        *(uint32_t*)(out_lo + rowA + c) = (uint32_t)l0 | ((uint32_t)l1 << 16);
        split1(b0,h0,l0); split1(b1,h1,l1);
        *(uint32_t*)(out_hi + rowB + c) = (uint32_t)h0 | ((uint32_t)h1 << 16);
        *(uint32_t*)(out_lo + rowB + c) = (uint32_t)l0 | ((uint32_t)l1 << 16);
    }
}

// ---------------------------------------------------------------------------
// mma.sync cross-attention with tile-range skipping (seg_ids sorted), f16.
// K and V single-f16 (same budget analysis as self-attention).
// ---------------------------------------------------------------------------
__global__ void __launch_bounds__(128, 2)
cross_attn_mma(const __half* __restrict__ Qh, const __half* __restrict__ Ql,
               const __half* __restrict__ Kh, const __half* __restrict__ Vh,
               const int* __restrict__ seg_ids,
               __half* __restrict__ out_hi, __half* __restrict__ out_lo) {
    extern __shared__ char smraw[];
    const uint32_t sb = (uint32_t)__cvta_generic_to_shared(smraw);
    const int tid = threadIdx.x, warp = tid >> 5, lane = tid & 31;
    const int h = blockIdx.y, b = blockIdx.z;
    const int qb = (int)blockIdx.x * 64;
    const size_t hbQ = ((size_t)(b*H_ + h)) * L_;
    const size_t hbK = ((size_t)(b*H_ + h)) * S_;

    const int rA = qb + warp*16 + (lane >> 2);
    const int segA = seg_ids[b*L_ + rA];
    const int segB = seg_ids[b*L_ + rA + 8];

    const int segF = seg_ids[b*L_ + qb];
    const int segL = seg_ids[b*L_ + qb + 63];
    int t0 = (segF - 127) >> 6; if (t0 < 0) t0 = 0;
    int t1 = segL >> 6;
    const int nte = t1 - t0 + 1;

    #pragma unroll
    for (int i = 0; i < 8; i++) {
        int id = tid + i * 128;
        int arr = id >> 9;
        int rem = id & 511;
        int row = rem >> 3, kc = rem & 7;
        const __half* p = (arr ? Ql : Qh) + (hbQ + qb + row) * HD_ + kc * 8;
        uint32_t d = sb + (uint32_t)(arr * AT_ARR + row * AT_ROW + kc * 16);
        asm volatile("cp.async.cg.shared.global [%0], [%1], 16;" :: "r"(d), "l"(p) : "memory");
    }
    auto load_kv = [&](int t, int slot) {
        uint32_t base = sb + AT_KV0 + (uint32_t)(slot & 1) * AT_STG;
        int k0 = t * 64;
        #pragma unroll
        for (int i = 0; i < 8; i++) {
            int id = tid + i * 128;
            int arr = id >> 9;
            int rem = id & 511;
            int row = rem >> 3, kc = rem & 7;
            const __half* p = (arr ? Vh : Kh) + (hbK + k0 + row) * HD_ + kc * 8;
            uint32_t d = base + (uint32_t)(arr * AT_ARR + row * AT_ROW + kc * 16);
            asm volatile("cp.async.cg.shared.global [%0], [%1], 16;" :: "r"(d), "l"(p) : "memory");
        }
        asm volatile("cp.async.commit_group;" ::: "memory");
    };
    load_kv(t0, 0);
    if (nte > 1) load_kv(t0 + 1, 1);

    uint32_t qh[4][4], ql[4][4];
    float o[8][4];
    #pragma unroll
    for (int i = 0; i < 8; i++)
        #pragma unroll
        for (int j = 0; j < 4; j++) o[i][j] = 0.f;
    float mA = -1e30f, mB = -1e30f, lA = 0.f, lB = 0.f;

    for (int tt = 0; tt < nte; tt++) {
        const int t = t0 + tt;
        if (tt + 1 < nte) { asm volatile("cp.async.wait_group 1;" ::: "memory"); }
        else              { asm volatile("cp.async.wait_group 0;" ::: "memory"); }
        __syncthreads();
        if (tt == 0) {
            #pragma unroll
            for (int ks = 0; ks < 4; ks++) {
                uint32_t a = sb + (uint32_t)((warp*16 + (lane & 15)) * AT_ROW + ks*32 + (lane >> 4) * 16);
                ldsm_x4(qh[ks], a);
                ldsm_x4(ql[ks], a + AT_ARR);
            }
        }
        const uint32_t kvb = sb + AT_KV0 + (uint32_t)(tt & 1) * AT_STG;

        float s[8][4];
        #pragma unroll
        for (int i = 0; i < 8; i++)
            #pragma unroll
            for (int j = 0; j < 4; j++) s[i][j] = 0.f;
        #pragma unroll
        for (int ks = 0; ks < 4; ks++) {
            uint32_t kh4[4][4];
            #pragma unroll
            for (int ntp = 0; ntp < 4; ntp++) {
                uint32_t a = kvb + (uint32_t)((ntp*16 + (lane & 7) + ((lane >> 4) << 3)) * AT_ROW
                                              + ks*32 + (((lane >> 3) & 1) << 4));
                ldsm_x4(kh4[ntp], a);
            }
            #pragma unroll
            for (int ntp = 0; ntp < 4; ntp++) {
                mma_f16(s[2*ntp],   qh[ks], kh4[ntp]);
                mma_f16(s[2*ntp+1], qh[ks], kh4[ntp] + 2);
                mma_f16(s[2*ntp],   ql[ks], kh4[ntp]);
                mma_f16(s[2*ntp+1], ql[ks], kh4[ntp] + 2);
            }
        }
        {
            int cbase = t*64 + 2*(lane & 3);
            #pragma unroll
            for (int nt = 0; nt < 8; nt++) {
                int c0 = cbase + nt*8, c1 = c0 + 1;
                if (c0 > segA || c0 <= segA - 128) s[nt][0] = -1e30f;
                if (c1 > segA || c1 <= segA - 128) s[nt][1] = -1e30f;
                if (c0 > segB || c0 <= segB - 128) s[nt][2] = -1e30f;
                if (c1 > segB || c1 <= segB - 128) s[nt][3] = -1e30f;
            }
        }
        float tmA = -1e30f, tmB = -1e30f;
        #pragma unroll
        for (int nt = 0; nt < 8; nt++) {
            tmA = fmaxf(tmA, fmaxf(s[nt][0], s[nt][1]));
            tmB = fmaxf(tmB, fmaxf(s[nt][2], s[nt][3]));
        }
        tmA = fmaxf(tmA, __shfl_xor_sync(0xffffffffu, tmA, 1));
        tmA = fmaxf(tmA, __shfl_xor_sync(0xffffffffu, tmA, 2));
        tmB = fmaxf(tmB, __shfl_xor_sync(0xffffffffu, tmB, 1));
        tmB = fmaxf(tmB, __shfl_xor_sync(0xffffffffu, tmB, 2));
        float nmA = fmaxf(mA, tmA), nmB = fmaxf(mB, tmB);
        float scA = __expf(mA - nmA), scB = __expf(mB - nmB);
        float tsA = 0.f, tsB = 0.f;
        #pragma unroll
        for (int nt = 0; nt < 8; nt++) {
            s[nt][0] = __expf(s[nt][0] - nmA);
            s[nt][1] = __expf(s[nt][1] - nmA);
            s[nt][2] = __expf(s[nt][2] - nmB);
            s[nt][3] = __expf(s[nt][3] - nmB);
            tsA += s[nt][0] + s[nt][1];
            tsB += s[nt][2] + s[nt][3];
        }
        tsA += __shfl_xor_sync(0xffffffffu, tsA, 1);
        tsA += __shfl_xor_sync(0xffffffffu, tsA, 2);
        tsB += __shfl_xor_sync(0xffffffffu, tsB, 1);
        tsB += __shfl_xor_sync(0xffffffffu, tsB, 2);
        lA = lA * scA + tsA;
        lB = lB * scB + tsB;
        #pragma unroll
        for (int nt = 0; nt < 8; nt++) {
            o[nt][0] *= scA; o[nt][1] *= scA;
            o[nt][2] *= scB; o[nt][3] *= scB;
        }
        mA = nmA; mB = nmB;
        #pragma unroll
        for (int kk = 0; kk < 4; kk++) {
            uint32_t ph[4];
            ph[0] = pack_h16x2(s[2*kk][0],   s[2*kk][1]);
            ph[1] = pack_h16x2(s[2*kk][2],   s[2*kk][3]);
            ph[2] = pack_h16x2(s[2*kk+1][0], s[2*kk+1][1]);
            ph[3] = pack_h16x2(s[2*kk+1][2], s[2*kk+1][3]);
            #pragma unroll
            for (int ntp = 0; ntp < 4; ntp++) {
                uint32_t vh4[4];
                uint32_t a = kvb + AT_ARR + (uint32_t)((kk*16 + (lane & 15)) * AT_ROW
                                                      + ntp*32 + ((lane >> 4) << 4));
                ldsm_x4_t(vh4, a);
                mma_f16(o[2*ntp],   ph, vh4);
                mma_f16(o[2*ntp+1], ph, vh4 + 2);
            }
        }
        __syncthreads();
        if (tt + 2 < nte) load_kv(t0 + tt + 2, tt + 2);
    }

    float iA = 1.0f / lA, iB = 1.0f / lB;
    size_t rowA = ((size_t)(b*L_ + rA)) * D_;
    size_t rowB = rowA + 8 * D_;
    int cb = h*HD_ + 2*(lane & 3);
    #pragma unroll
    for (int nt = 0; nt < 8; nt++) {
        int c = cb + nt*8;
        float a0 = o[nt][0]*iA, a1 = o[nt][1]*iA;
        float b0 = o[nt][2]*iB, b1 = o[nt][3]*iB;
        unsigned short h0,l0,h1,l1;
        split1(a0,h0,l0); split1(a1,h1,l1);
        *(uint32_t*)(out_hi + rowA + c) = (uint32_t)h0 | ((uint32_t)h1 << 16);
        *(uint32_t*)(out_lo + rowA + c) = (uint32_t)l0 | ((uint32_t)l1 << 16);
        split1(b0,h0,l0); split1(b1,h1,l1);
        *(uint32_t*)(out_hi + rowB + c) = (uint32_t)h0 | ((uint32_t)h1 << 16);
        *(uint32_t*)(out_lo + rowB + c) = (uint32_t)l0 | ((uint32_t)l1 << 16);
    }
}

// ---------------------------------------------------------------------------
// Launch
// ---------------------------------------------------------------------------
static inline void split_launch(const float* src, __half* hi, __half* lo, size_t n) {
    int n4 = (int)(n / 4);
    split_k<<<n4 / 1024, 256>>>(src, hi, lo);
}

extern "C" void kernel_launch(void* const* d_in, const int* in_sizes, int n_in,
                              void* d_out, int out_size) {
    const float* x      = (const float*)d_in[0];
    const float* memory = (const float*)d_in[1];
    const int*   seg    = (const int*)  d_in[2];
    const float* Wqkv   = (const float*)d_in[3];
    const float* bqkv   = (const float*)d_in[4];
    const float* Wo     = (const float*)d_in[5];
    const float* bo     = (const float*)d_in[6];
    const float* Wq_c   = (const float*)d_in[7];
    const float* Wkv_c  = (const float*)d_in[8];
    const float* Wo_c   = (const float*)d_in[9];
    const float* Wg     = (const float*)d_in[10];
    const float* Wu     = (const float*)d_in[11];
    const float* Wd     = (const float*)d_in[12];
    const float* n1     = (const float*)d_in[13];
    const float* n2     = (const float*)d_in[14];
    const float* n3     = (const float*)d_in[15];
    const float* nf     = (const float*)d_in[16];

    cudaFuncSetAttribute(gemm_f16s<1,false>, cudaFuncAttributeMaxDynamicSharedMemorySize, GSMEM);
    cudaFuncSetAttribute(gemm_f16s<2,false>, cudaFuncAttributeMaxDynamicSharedMemorySize, GSMEM);
    cudaFuncSetAttribute(gemm_f16s<3,false>, cudaFuncAttributeMaxDynamicSharedMemorySize, GSMEM);
    cudaFuncSetAttribute(gemm_f16s<4,true >, cudaFuncAttributeMaxDynamicSharedMemorySize, GSMEM);
    cudaFuncSetAttribute(gemm_f16s<6,true >, cudaFuncAttributeMaxDynamicSharedMemorySize, GSMEM);
    cudaFuncSetAttribute(gemm_f16s<7,true >, cudaFuncAttributeMaxDynamicSharedMemorySize, GSMEM);
    cudaFuncSetAttribute(self_attn_mma,  cudaFuncAttributeMaxDynamicSharedMemorySize, AT_SMEM);
    cudaFuncSetAttribute(cross_attn_mma, cudaFuncAttributeMaxDynamicSharedMemorySize, AT_SMEM);

    float *xb;
    __half *hhi, *hlo, *ahi, *alo, *chi, *clo, *gshi, *gslo, *mhi, *mlo, *whi, *wlo;
    __half *sqh, *sql, *skh, *skl, *svh, *svl;
    __half *ckh, *ckl, *cvh, *cvl;
    cudaGetSymbolAddress((void**)&xb,   g_x);
    cudaGetSymbolAddress((void**)&hhi,  g_h_hi);  cudaGetSymbolAddress((void**)&hlo,  g_h_lo);
    cudaGetSymbolAddress((void**)&ahi,  g_at_hi); cudaGetSymbolAddress((void**)&alo,  g_at_lo);
    cudaGetSymbolAddress((void**)&chi,  g_co_hi); cudaGetSymbolAddress((void**)&clo,  g_co_lo);
    cudaGetSymbolAddress((void**)&gshi, g_gs_hi); cudaGetSymbolAddress((void**)&gslo, g_gs_lo);
    cudaGetSymbolAddress((void**)&mhi,  g_m_hi);  cudaGetSymbolAddress((void**)&mlo,  g_m_lo);
    cudaGetSymbolAddress((void**)&whi,  g_w_hi);  cudaGetSymbolAddress((void**)&wlo,  g_w_lo);
    cudaGetSymbolAddress((void**)&sqh,  g_sqh);   cudaGetSymbolAddress((void**)&sql,  g_sql);
    cudaGetSymbolAddress((void**)&skh,  g_skh);   cudaGetSymbolAddress((void**)&skl,  g_skl);
    cudaGetSymbolAddress((void**)&svh,  g_svh);   cudaGetSymbolAddress((void**)&svl,  g_svl);
    cudaGetSymbolAddress((void**)&ckh,  g_ckh);   cudaGetSymbolAddress((void**)&ckl,  g_ckl);
    cudaGetSymbolAddress((void**)&cvh,  g_cvh);   cudaGetSymbolAddress((void**)&cvl,  g_cvl);

    rope_cache_k<<<256, 256>>>();

    split_launch(Wqkv,  whi + O_WQKV, wlo + O_WQKV, NL*SZ_WQKV);
    split_launch(Wo,    whi + O_WO,   wlo + O_WO,   NL*SZ_WO);
    split_launch(Wq_c,  whi + O_WQC,  wlo + O_WQC,  NL*SZ_WQC);
    split_launch(Wkv_c, whi + O_WKVC, wlo + O_WKVC, NL*SZ_WKVC);
    split_launch(Wo_c,  whi + O_WOC,  wlo + O_WOC,  NL*SZ_WOC);
    for (int l = 0; l < NL; l++) {
        int blocks = (int)((size_t)F_*D_/4/1024);
        split_ilv_k<<<blocks, 256>>>(Wg + (size_t)l*F_*D_,
            whi + O_WGU + l*SZ_WGU, wlo + O_WGU + l*SZ_WGU, 0);
        split_ilv_k<<<blocks, 256>>>(Wu + (size_t)l*F_*D_,
            whi + O_WGU + l*SZ_WGU, wlo + O_WGU + l*SZ_WGU, 1);
    }
    split_launch(Wd,    whi + O_WD,   wlo + O_WD,   NL*SZ_WD);
    split_launch(memory, mhi, mlo, (size_t)B_*S_*D_);

    // upfront: all 4 layers' cross K/V in one GEMM (layer-independent)
    gemm_f16s<7,true><<<dim3(NL*2*D_/128, (B_*S_)/256), 256, GSMEM>>>(
        mhi, mlo, whi + O_WKVC, wlo + O_WKVC, nullptr, nullptr, nullptr,
        ckh, ckl, cvh, cvl, nullptr, nullptr, NL*2*D_, D_);

    const dim3 self_grid(L_/64, H_, B_);
    const dim3 cross_grid(L_/64, H_, B_);

    for (int l = 0; l < NL; l++) {
        const __half* wqkv_h = whi + O_WQKV + l*SZ_WQKV;
        const __half* wqkv_l = wlo + O_WQKV + l*SZ_WQKV;
        const __half* wo_h   = whi + O_WO   + l*SZ_WO;
        const __half* wo_l   = wlo + O_WO   + l*SZ_WO;
        const __half* wqc_h  = whi + O_WQC  + l*SZ_WQC;
        const __half* wqc_l  = wlo + O_WQC  + l*SZ_WQC;
        const __half* woc_h  = whi + O_WOC  + l*SZ_WOC;
        const __half* woc_l  = wlo + O_WOC  + l*SZ_WOC;
        const __half* wgu_h  = whi + O_WGU  + l*SZ_WGU;
        const __half* wgu_l  = wlo + O_WGU  + l*SZ_WGU;
        const __half* wd_h   = whi + O_WD   + l*SZ_WD;
        const __half* wd_l   = wlo + O_WD   + l*SZ_WD;

        const float* xsrc = (l == 0) ? x : xb;    // residual stream source

        // --- self attention block (QKV GEMM fuses bias+RoPE+split; exp path, 3-term) ---
        rmsnorm_split_k<<<M_, 256>>>(xsrc, n1 + l*D_, hhi, hlo);
        gemm_f16s<6,true><<<dim3(3*D_/128, M_/256), 256, GSMEM>>>(
            hhi, hlo, wqkv_h, wqkv_l, bqkv + l*3*D_, nullptr, nullptr,
            sqh, sql, skh, skl, svh, svl, 3*D_, D_);
        self_attn_mma<<<self_grid, 128, AT_SMEM>>>(sqh, sql, skh, svh, ahi, alo);
        gemm_f16s<1,false><<<dim3(D_/128, M_/256), 256, GSMEM>>>(
            ahi, alo, wo_h, wo_l, bo + l*D_, xb, xsrc,
            nullptr, nullptr, nullptr, nullptr, nullptr, nullptr, D_, D_);

        // --- cross attention block (Wqc exp path 3-term; Wo_c linear 2-term) ---
        rmsnorm_split_k<<<M_, 256>>>(xb, n2 + l*D_, hhi, hlo);
        gemm_f16s<4,true><<<dim3(D_/128, M_/256), 256, GSMEM>>>(
            hhi, hlo, wqc_h, wqc_l, nullptr, nullptr, nullptr,
            sqh, sql, nullptr, nullptr, nullptr, nullptr, D_, D_);
        cross_attn_mma<<<cross_grid, 128, AT_SMEM>>>(
            sqh, sql, ckh + l*CATN, cvh + l*CATN, seg, chi, clo);
        gemm_f16s<2,false><<<dim3(D_/128, M_/256), 256, GSMEM>>>(
            chi, clo, woc_h, woc_l, nullptr, xb, xb,
            nullptr, nullptr, nullptr, nullptr, nullptr, nullptr, D_, D_);

        // --- MLP block (2-term f16 linear paths) ---
        rmsnorm_split_k<<<M_, 256>>>(xb, n3 + l*D_, hhi, hlo);
        gemm_f16s<3,false><<<dim3(2*F_/128, M_/256), 256, GSMEM>>>(
            hhi, hlo, wgu_h, wgu_l, nullptr, nullptr, nullptr,
            gshi, gslo, nullptr, nullptr, nullptr, nullptr, 2*F_, D_);
        gemm_f16s<2,false><<<dim3(D_/128, M_/256), 256, GSMEM>>>(
            gshi, gslo, wd_h, wd_l, nullptr, xb, xb,
            nullptr, nullptr, nullptr, nullptr, nullptr, nullptr, D_, F_);
    }

    rmsnorm_k<<<M_, 256>>>(xb, nf, (float*)d_out);
}

// round 17
// speedup vs baseline: 6.6249x; 1.0805x over previous
#include <cuda_runtime.h>
#include <cuda_fp16.h>
#include <math.h>
#include <stdint.h>

// Problem constants
#define NL 4
#define B_ 2
#define L_ 2048
#define S_ 256
#define D_ 1024
#define F_ 4096
#define H_ 16
#define HD_ 64
#define M_ (B_*L_)          // 4096 token rows

// Weight region sizes (elements) and offsets in the concatenated split buffer
#define SZ_WQKV ((size_t)3*D_*D_)
#define SZ_WO   ((size_t)D_*D_)
#define SZ_WQC  ((size_t)D_*D_)
#define SZ_WKVC ((size_t)2*D_*D_)
#define SZ_WOC  ((size_t)D_*D_)
#define SZ_WGU  ((size_t)2*F_*D_)     // interleaved [g0,u0,g1,u1,...] per layer
#define SZ_WD   ((size_t)D_*F_)
static const size_t O_WQKV = 0;
static const size_t O_WO   = O_WQKV + NL*SZ_WQKV;
static const size_t O_WQC  = O_WO   + NL*SZ_WO;
static const size_t O_WKVC = O_WQC  + NL*SZ_WQC;
static const size_t O_WOC  = O_WKVC + NL*SZ_WKVC;
static const size_t O_WGU  = O_WOC  + NL*SZ_WOC;
static const size_t O_WD   = O_WGU  + NL*SZ_WGU;
#define WTOT (O_WD + NL*SZ_WD)

// ---------------------------------------------------------------------------
// Scratch (device globals; no allocations allowed)
// ---------------------------------------------------------------------------
__device__ float g_x  [M_*D_];
__device__ float g_cos[L_*32];
__device__ float g_sin[L_*32];

__device__ __half g_h_hi [M_*D_],  g_h_lo [M_*D_];
__device__ __half g_at_hi[M_*D_],  g_at_lo[M_*D_];
__device__ __half g_co_hi[M_*D_],  g_co_lo[M_*D_];
__device__ __half g_gs_hi[M_*F_],  g_gs_lo[M_*F_];
__device__ __half g_m_hi [B_*S_*D_], g_m_lo[B_*S_*D_];
__device__ __half g_w_hi[WTOT], g_w_lo[WTOT];

// attention-layout split buffers: [B][H][L][64] (self q/k/v; cross q reuses q)
#define ATN ((size_t)B_*H_*L_*HD_)
__device__ __half g_sqh[ATN], g_sql[ATN];
__device__ __half g_skh[ATN], g_skl[ATN];
__device__ __half g_svh[ATN], g_svl[ATN];

// per-layer cross K/V: [NL][B][H][S][64]
#define CATN ((size_t)B_*H_*S_*HD_)
__device__ __half g_ckh[NL*CATN], g_ckl[NL*CATN];
__device__ __half g_cvh[NL*CATN], g_cvl[NL*CATN];

// ---------------------------------------------------------------------------
// f16 split helpers
// ---------------------------------------------------------------------------
__device__ __forceinline__ void split1(float v, unsigned short& h, unsigned short& l) {
    __half hb = __float2half_rn(v);
    float r = v - __half2float(hb);
    __half lb = __float2half_rn(r);
    h = __half_as_ushort(hb);
    l = __half_as_ushort(lb);
}
__device__ __forceinline__ void split_pack4(float4 v, uint2& ph, uint2& pl) {
    unsigned short h0,h1,h2,h3,l0,l1,l2,l3;
    split1(v.x,h0,l0); split1(v.y,h1,l1); split1(v.z,h2,l2); split1(v.w,h3,l3);
    ph.x = (uint32_t)h0 | ((uint32_t)h1 << 16);
    ph.y = (uint32_t)h2 | ((uint32_t)h3 << 16);
    pl.x = (uint32_t)l0 | ((uint32_t)l1 << 16);
    pl.y = (uint32_t)l2 | ((uint32_t)l3 << 16);
}

// 4-quad ILP split (exact grids: n4 multiple of 1024)
__global__ void split_k(const float* __restrict__ in, __half* __restrict__ hi,
                        __half* __restrict__ lo) {
    int i = blockIdx.x * 1024 + threadIdx.x;
    float4 v[4];
    #pragma unroll
    for (int j = 0; j < 4; j++) v[j] = ((const float4*)in)[i + 256*j];
    #pragma unroll
    for (int j = 0; j < 4; j++) {
        uint2 ph, pl; split_pack4(v[j], ph, pl);
        ((uint2*)hi)[i + 256*j] = ph;
        ((uint2*)lo)[i + 256*j] = pl;
    }
}

// Interleaving split for GU weights: src row r (256 quads/row) -> dst row 2r+off
__global__ void split_ilv_k(const float* __restrict__ in, __half* __restrict__ hi,
                            __half* __restrict__ lo, int off) {
    int i0 = blockIdx.x * 1024 + threadIdx.x;
    float4 v[4];
    #pragma unroll
    for (int j = 0; j < 4; j++) v[j] = ((const float4*)in)[i0 + 256*j];
    #pragma unroll
    for (int j = 0; j < 4; j++) {
        int i = i0 + 256*j;
        int r = i >> 8, c = i & 255;
        uint2 ph, pl; split_pack4(v[j], ph, pl);
        size_t oi = (size_t)(2*r + off) * 256 + c;
        ((uint2*)hi)[oi] = ph;
        ((uint2*)lo)[oi] = pl;
    }
}

// ---------------------------------------------------------------------------
// RoPE cache
// ---------------------------------------------------------------------------
__global__ void rope_cache_k() {
    int idx = blockIdx.x * blockDim.x + threadIdx.x;
    int l = idx >> 5, i = idx & 31;
    double inv = exp(-log(10000.0) * (double)i / 32.0);
    double f = (double)l * inv;
    g_cos[idx] = (float)cos(f);
    g_sin[idx] = (float)sin(f);
}

// ---------------------------------------------------------------------------
// RMSNorm kernels
// ---------------------------------------------------------------------------
__global__ void rmsnorm_split_k(const float* __restrict__ x, const float* __restrict__ w,
                                __half* __restrict__ hi, __half* __restrict__ lo) {
    int row = blockIdx.x;
    int t = threadIdx.x;
    const float4* xr = (const float4*)(x + (size_t)row * D_);
    float4 v = xr[t];
    float ss = v.x*v.x + v.y*v.y + v.z*v.z + v.w*v.w;
    #pragma unroll
    for (int off = 16; off; off >>= 1) ss += __shfl_xor_sync(0xffffffffu, ss, off);
    __shared__ float red[8];
    if ((t & 31) == 0) red[t >> 5] = ss;
    __syncthreads();
    float tot = red[0]+red[1]+red[2]+red[3]+red[4]+red[5]+red[6]+red[7];
    float rs = rsqrtf(tot * (1.0f / (float)D_) + 1e-6f);
    float4 wv = ((const float4*)w)[t];
    float4 o;
    o.x = v.x * rs * wv.x; o.y = v.y * rs * wv.y;
    o.z = v.z * rs * wv.z; o.w = v.w * rs * wv.w;
    uint2 ph, pl; split_pack4(o, ph, pl);
    ((uint2*)hi)[(size_t)row * 256 + t] = ph;
    ((uint2*)lo)[(size_t)row * 256 + t] = pl;
}

__global__ void rmsnorm_k(const float* __restrict__ x, const float* __restrict__ w,
                          float* __restrict__ o) {
    int row = blockIdx.x;
    int t = threadIdx.x;
    const float4* xr = (const float4*)(x + (size_t)row * D_);
    float4 v = xr[t];
    float ss = v.x*v.x + v.y*v.y + v.z*v.z + v.w*v.w;
    #pragma unroll
    for (int off = 16; off; off >>= 1) ss += __shfl_xor_sync(0xffffffffu, ss, off);
    __shared__ float red[8];
    if ((t & 31) == 0) red[t >> 5] = ss;
    __syncthreads();
    float tot = red[0]+red[1]+red[2]+red[3]+red[4]+red[5]+red[6]+red[7];
    float rs = rsqrtf(tot * (1.0f / (float)D_) + 1e-6f);
    float4 wv = ((const float4*)w)[t];
    float4 out;
    out.x = v.x * rs * wv.x; out.y = v.y * rs * wv.y;
    out.z = v.z * rs * wv.z; out.w = v.w * rs * wv.w;
    ((float4*)(o + (size_t)row * D_))[t] = out;
}

// ---------------------------------------------------------------------------
// mma / ldmatrix helpers (f16)
// ---------------------------------------------------------------------------
__device__ __forceinline__ void mma_f16(float* c, const uint32_t* a, const uint32_t* b) {
    asm volatile(
        "mma.sync.aligned.m16n8k16.row.col.f32.f16.f16.f32 "
        "{%0,%1,%2,%3}, {%4,%5,%6,%7}, {%8,%9}, {%0,%1,%2,%3};"
        : "+f"(c[0]), "+f"(c[1]), "+f"(c[2]), "+f"(c[3])
        : "r"(a[0]), "r"(a[1]), "r"(a[2]), "r"(a[3]), "r"(b[0]), "r"(b[1]));
}
__device__ __forceinline__ void ldsm_x4(uint32_t* r, uint32_t addr) {
    asm volatile("ldmatrix.sync.aligned.m8n8.x4.shared.b16 {%0,%1,%2,%3}, [%4];"
        : "=r"(r[0]), "=r"(r[1]), "=r"(r[2]), "=r"(r[3]) : "r"(addr));
}
__device__ __forceinline__ void ldsm_x4_t(uint32_t* r, uint32_t addr) {
    asm volatile("ldmatrix.sync.aligned.m8n8.x4.trans.shared.b16 {%0,%1,%2,%3}, [%4];"
        : "=r"(r[0]), "=r"(r[1]), "=r"(r[2]), "=r"(r[3]) : "r"(addr));
}
__device__ __forceinline__ uint32_t pack_h16x2(float lo, float hi) {
    return (uint32_t)__half_as_ushort(__float2half_rn(lo)) |
           ((uint32_t)__half_as_ushort(__float2half_rn(hi)) << 16);
}

// ---------------------------------------------------------------------------
// f16 split GEMM (NT), 256x128 CTA tile, warp tile 64x64 (8 warps, 4x2).
// THREE=true:  C = AhWh + AhWl + AlWh
// THREE=false: C = AhWh + AhWl   (f16 activation-lo drop; calibrated benign
//              on all paths incl. softmax inputs — R16 measurement)
// MODE 1: +bias +residual(Rsrc) -> fp32 C   (Wo)
// MODE 2: +residual(Rsrc)       -> fp32 C   (Wo_c, Wd)
// MODE 3: swiglu (interleaved g|u cols) -> f16 hi/lo [M][F]
// MODE 4: attn-q layout, x0.125         -> f16 hi/lo [B][H][L][64]
// MODE 6: QKV: +bias, RoPE on q/k, q x0.125 -> q/k/v f16 hi/lo [B][H][L][64]
// MODE 7: multi-layer cross-KV           -> per-layer k/v [NL][B][H][S][64]
// ---------------------------------------------------------------------------
#define G2STAGE 61440
#define G2_AL   20480
#define G2_B0   40960
#define G2_B1   51200
#define GSMEM   (3*G2STAGE)

template <int MODE, bool THREE>
__global__ void __launch_bounds__(256, 1)
gemm_f16s(const __half* __restrict__ Ah, const __half* __restrict__ Al,
          const __half* __restrict__ Wh, const __half* __restrict__ Wl,
          const float* __restrict__ bias, float* __restrict__ C,
          const float* __restrict__ Rsrc,
          __half* __restrict__ o1h, __half* __restrict__ o1l,
          __half* __restrict__ o2h, __half* __restrict__ o2l,
          __half* __restrict__ o3h, __half* __restrict__ o3l,
          int N, int K) {
    extern __shared__ char smem[];
    const uint32_t sbase = (uint32_t)__cvta_generic_to_shared(smem);
    const int tid  = threadIdx.x;
    const int warp = tid >> 5, lane = tid & 31;
    const int wr = warp >> 1;      // 0..3 : 64-row slab
    const int wc = warp & 1;       // 0..1 : 64-col slab
    const int g  = lane >> 2;
    const int t  = lane & 3;
    const int bm = blockIdx.y, bn = blockIdx.x;

    // cp.async chunk tables: 3072 16B-chunks per stage, 12 per thread
    // chunks i=4..7 are the A-lo array (skipped when !THREE)
    const __half* src[12];
    uint32_t dst[12];
    #pragma unroll
    for (int i = 0; i < 12; i++) {
        int id = tid + (i << 8);
        const __half* bp;
        int grow; uint32_t off; int kc;
        if (id < 2048) {
            int arr = id >> 10, rem = id & 1023;
            int row = rem >> 2; kc = rem & 3;
            bp = arr ? Al : Ah;
            grow = bm * 256 + row;
            off = (uint32_t)(arr * G2_AL + row * 80 + kc * 16);
        } else {
            int id2 = id - 2048;
            int arr = id2 >> 9, rem = id2 & 511;
            int row = rem >> 2; kc = rem & 3;
            bp = arr ? Wl : Wh;
            grow = bn * 128 + row;
            off = (uint32_t)(G2_B0 + arr * 10240 + row * 80 + kc * 16);
        }
        src[i] = bp + (size_t)grow * K + kc * 8;
        dst[i] = off;
    }

    const uint32_t arow = (uint32_t)((wr * 64 + (lane & 15)) * 80 + (lane >> 4) * 16);
    const uint32_t brow = (uint32_t)((wc * 64 + (lane & 7) + ((lane >> 4) << 3)) * 80
                                     + (((lane >> 3) & 1) << 4));

    float acc[4][8][4];
    #pragma unroll
    for (int i = 0; i < 4; i++)
        #pragma unroll
        for (int j = 0; j < 8; j++)
            #pragma unroll
            for (int r = 0; r < 4; r++) acc[i][j][r] = 0.f;

    const int nk = K >> 5;

    #pragma unroll
    for (int st = 0; st < 2; st++) {
        uint32_t s = sbase + st * G2STAGE;
        #pragma unroll
        for (int i = 0; i < 12; i++) {
            if (!THREE && i >= 4 && i < 8) continue;
            const void* p = src[i] + st * 32;
            asm volatile("cp.async.cg.shared.global [%0], [%1], 16;"
                         :: "r"(s + dst[i]), "l"(p) : "memory");
        }
        asm volatile("cp.async.commit_group;" ::: "memory");
    }

    for (int it = 0; it < nk; it++) {
        asm volatile("cp.async.wait_group 1;" ::: "memory");
        __syncthreads();
        uint32_t s = sbase + (uint32_t)(it % 3) * G2STAGE;

        #pragma unroll
        for (int ks = 0; ks < 2; ks++) {
            const uint32_t ko = ks * 32;
            uint32_t af[16], bh[16], bl[16];
            #pragma unroll
            for (int mt = 0; mt < 4; mt++) ldsm_x4(af + 4*mt, s + arow + mt*1280 + ko);
            #pragma unroll
            for (int p = 0; p < 4; p++) ldsm_x4(bh + 4*p, s + G2_B0 + brow + p*1280 + ko);
            #pragma unroll
            for (int p = 0; p < 4; p++) ldsm_x4(bl + 4*p, s + G2_B1 + brow + p*1280 + ko);
            #pragma unroll
            for (int mt = 0; mt < 4; mt++)
                #pragma unroll
                for (int nt = 0; nt < 8; nt++) mma_f16(acc[mt][nt], af + 4*mt, bh + 2*nt);
            #pragma unroll
            for (int mt = 0; mt < 4; mt++)
                #pragma unroll
                for (int nt = 0; nt < 8; nt++) mma_f16(acc[mt][nt], af + 4*mt, bl + 2*nt);
            if (THREE) {
                #pragma unroll
                for (int mt = 0; mt < 4; mt++) ldsm_x4(af + 4*mt, s + G2_AL + arow + mt*1280 + ko);
                #pragma unroll
                for (int mt = 0; mt < 4; mt++)
                    #pragma unroll
                    for (int nt = 0; nt < 8; nt++) mma_f16(acc[mt][nt], af + 4*mt, bh + 2*nt);
            }
        }

        if (it + 2 < nk) {
            uint32_t s2 = sbase + (uint32_t)((it + 2) % 3) * G2STAGE;
            int k0 = (it + 2) * 32;
            #pragma unroll
            for (int i = 0; i < 12; i++) {
                if (!THREE && i >= 4 && i < 8) continue;
                const void* p = src[i] + k0;
                asm volatile("cp.async.cg.shared.global [%0], [%1], 16;"
                             :: "r"(s2 + dst[i]), "l"(p) : "memory");
            }
        }
        asm volatile("cp.async.commit_group;" ::: "memory");
    }

    if (MODE == 6) {
        // QKV epilogue: bias + RoPE (q,k) + split into attention layout.
        const int part = (bn * 128 + wc * 64) >> 10;
        #pragma unroll
        for (int mt = 0; mt < 4; mt++) {
            #pragma unroll
            for (int half = 0; half < 2; half++) {
                int row = bm * 256 + wr * 64 + mt * 16 + g + half * 8;
                int b = row >> 11, ltok = row & (L_ - 1);
                if (part < 2) {
                    #pragma unroll
                    for (int np = 0; np < 4; np++) {
                        int col = bn*128 + wc*64 + np*8 + 2*t;
                        int pcol = col & 1023;
                        int head = pcol >> 6;
                        int i = pcol & 31;
                        float c0 = g_cos[ltok*32 + i],     s0 = g_sin[ltok*32 + i];
                        float c1 = g_cos[ltok*32 + i + 1], s1 = g_sin[ltok*32 + i + 1];
                        float x1a = acc[mt][np  ][half*2+0] + bias[col];
                        float x1b = acc[mt][np  ][half*2+1] + bias[col+1];
                        float x2a = acc[mt][np+4][half*2+0] + bias[col+32];
                        float x2b = acc[mt][np+4][half*2+1] + bias[col+33];
                        float r1a = x1a*c0 - x2a*s0, r2a = x2a*c0 + x1a*s0;
                        float r1b = x1b*c1 - x2b*s1, r2b = x2b*c1 + x1b*s1;
                        __half *oh, *ol;
                        if (part == 0) {
                            r1a *= 0.125f; r1b *= 0.125f; r2a *= 0.125f; r2b *= 0.125f;
                            oh = o1h; ol = o1l;
                        } else { oh = o2h; ol = o2l; }
                        size_t oi = (((size_t)(b*H_ + head)) * L_ + ltok) * HD_ + i;
                        unsigned short h0, l0, h1, l1;
                        split1(r1a, h0, l0); split1(r1b, h1, l1);
                        *(uint32_t*)(oh + oi) = (uint32_t)h0 | ((uint32_t)h1 << 16);
                        *(uint32_t*)(ol + oi) = (uint32_t)l0 | ((uint32_t)l1 << 16);
                        split1(r2a, h0, l0); split1(r2b, h1, l1);
                        *(uint32_t*)(oh + oi + 32) = (uint32_t)h0 | ((uint32_t)h1 << 16);
                        *(uint32_t*)(ol + oi + 32) = (uint32_t)l0 | ((uint32_t)l1 << 16);
                    }
                } else {
                    #pragma unroll
                    for (int nt = 0; nt < 8; nt++) {
                        int col = bn*128 + wc*64 + nt*8 + 2*t;
                        int pcol = col & 1023;
                        int head = pcol >> 6, d = pcol & 63;
                        float c0 = acc[mt][nt][half*2+0] + bias[col];
                        float c1 = acc[mt][nt][half*2+1] + bias[col+1];
                        size_t oi = (((size_t)(b*H_ + head)) * L_ + ltok) * HD_ + d;
                        unsigned short h0, l0, h1, l1;
                        split1(c0, h0, l0); split1(c1, h1, l1);
                        *(uint32_t*)(o3h + oi) = (uint32_t)h0 | ((uint32_t)h1 << 16);
                        *(uint32_t*)(o3l + oi) = (uint32_t)l0 | ((uint32_t)l1 << 16);
                    }
                }
            }
        }
        return;
    }

    #pragma unroll
    for (int mt = 0; mt < 4; mt++) {
        #pragma unroll
        for (int half = 0; half < 2; half++) {
            int row = bm * 256 + wr * 64 + mt * 16 + g + half * 8;
            #pragma unroll
            for (int nt = 0; nt < 8; nt++) {
                int col = bn * 128 + wc * 64 + nt * 8 + 2 * t;
                float c0 = acc[mt][nt][half * 2 + 0];
                float c1 = acc[mt][nt][half * 2 + 1];
                if (MODE <= 2) {
                    float* dstp = C + (size_t)row * N + col;
                    const float* rp = Rsrc + (size_t)row * N + col;
                    if (MODE == 1) { c0 += bias[col]; c1 += bias[col + 1]; }
                    float2 r = *(const float2*)rp;
                    c0 += r.x; c1 += r.y;
                    *(float2*)dstp = make_float2(c0, c1);
                } else if (MODE == 3) {
                    float sg = c0 / (1.0f + expf(-c0)) * c1;
                    unsigned short hh, ll; split1(sg, hh, ll);
                    size_t oi = (size_t)row * F_ + (col >> 1);
                    o1h[oi] = __ushort_as_half(hh);
                    o1l[oi] = __ushort_as_half(ll);
                } else if (MODE == 4) {
                    int b = row >> 11, ltok = row & (L_ - 1);
                    int hd = col >> 6, d = col & 63;
                    size_t oi = (((size_t)(b*H_ + hd)) * L_ + ltok) * HD_ + d;
                    unsigned short h0, l0, h1, l1;
                    split1(c0 * 0.125f, h0, l0); split1(c1 * 0.125f, h1, l1);
                    *(uint32_t*)(o1h + oi) = (uint32_t)h0 | ((uint32_t)h1 << 16);
                    *(uint32_t*)(o1l + oi) = (uint32_t)l0 | ((uint32_t)l1 << 16);
                } else { // MODE 7: multi-layer cross-KV
                    int layer = col >> 11;
                    int c2 = col & 2047;
                    int kv = c2 >> 10;
                    int hd = (c2 >> 6) & 15, d = c2 & 63;
                    int b = row >> 8, stok = row & (S_ - 1);
                    size_t oi = (size_t)layer * CATN
                              + (((size_t)(b*H_ + hd)) * S_ + stok) * HD_ + d;
                    unsigned short h0, l0, h1, l1;
                    split1(c0, h0, l0); split1(c1, h1, l1);
                    __half* ph = kv ? o2h : o1h;
                    __half* pl = kv ? o2l : o1l;
                    *(uint32_t*)(ph + oi) = (uint32_t)h0 | ((uint32_t)h1 << 16);
                    *(uint32_t*)(pl + oi) = (uint32_t)l0 | ((uint32_t)l1 << 16);
                }
            }
        }
    }
}

// ---------------------------------------------------------------------------
// mma.sync flash self-attention (f16). K and V single-f16; S = (Qh+Ql)·Kh;
// O += P·Vh. K/V stage = 2 arrays.
// ---------------------------------------------------------------------------
#define AT_ROW  144
#define AT_ARR  (64*AT_ROW)
#define AT_KV0  (2*AT_ARR)
#define AT_STG  (2*AT_ARR)
#define AT_SMEM (2*AT_ARR + 2*AT_STG)

__global__ void __launch_bounds__(128, 2)
self_attn_mma(const __half* __restrict__ Qh, const __half* __restrict__ Ql,
              const __half* __restrict__ Kh, const __half* __restrict__ Vh,
              __half* __restrict__ out_hi, __half* __restrict__ out_lo) {
    extern __shared__ char smraw[];
    const uint32_t sb = (uint32_t)__cvta_generic_to_shared(smraw);
    const int tid = threadIdx.x, warp = tid >> 5, lane = tid & 31;
    const int h = blockIdx.y, b = blockIdx.z;
    const int qbi = (int)(gridDim.x - 1 - blockIdx.x);
    const int qb = qbi * 64;
    const int ntiles = qbi + 1;
    const size_t hb = ((size_t)(b*H_ + h)) * L_;

    #pragma unroll
    for (int i = 0; i < 8; i++) {
        int id = tid + i * 128;
        int arr = id >> 9;
        int rem = id & 511;
        int row = rem >> 3, kc = rem & 7;
        const __half* p = (arr ? Ql : Qh) + (hb + qb + row) * HD_ + kc * 8;
        uint32_t d = sb + (uint32_t)(arr * AT_ARR + row * AT_ROW + kc * 16);
        asm volatile("cp.async.cg.shared.global [%0], [%1], 16;" :: "r"(d), "l"(p) : "memory");
    }
    auto load_kv = [&](int t, int slot) {
        uint32_t base = sb + AT_KV0 + (uint32_t)(slot & 1) * AT_STG;
        int k0 = t * 64;
        #pragma unroll
        for (int i = 0; i < 8; i++) {
            int id = tid + i * 128;          // 0..1023
            int arr = id >> 9;               // 0:Kh 1:Vh
            int rem = id & 511;
            int row = rem >> 3, kc = rem & 7;
            const __half* p = (arr ? Vh : Kh) + (hb + k0 + row) * HD_ + kc * 8;
            uint32_t d = base + (uint32_t)(arr * AT_ARR + row * AT_ROW + kc * 16);
            asm volatile("cp.async.cg.shared.global [%0], [%1], 16;" :: "r"(d), "l"(p) : "memory");
        }
        asm volatile("cp.async.commit_group;" ::: "memory");
    };
    load_kv(0, 0);
    if (ntiles > 1) load_kv(1, 1);

    uint32_t qh[4][4], ql[4][4];
    float o[8][4];
    #pragma unroll
    for (int i = 0; i < 8; i++)
        #pragma unroll
        for (int j = 0; j < 4; j++) o[i][j] = 0.f;
    float mA = -1e30f, mB = -1e30f, lA = 0.f, lB = 0.f;

    for (int t = 0; t < ntiles; t++) {
        if (t + 1 < ntiles) { asm volatile("cp.async.wait_group 1;" ::: "memory"); }
        else                { asm volatile("cp.async.wait_group 0;" ::: "memory"); }
        __syncthreads();
        if (t == 0) {
            #pragma unroll
            for (int ks = 0; ks < 4; ks++) {
                uint32_t a = sb + (uint32_t)((warp*16 + (lane & 15)) * AT_ROW + ks*32 + (lane >> 4) * 16);
                ldsm_x4(qh[ks], a);
                ldsm_x4(ql[ks], a + AT_ARR);
            }
        }
        const uint32_t kvb = sb + AT_KV0 + (uint32_t)(t & 1) * AT_STG;

        float s[8][4];
        #pragma unroll
        for (int i = 0; i < 8; i++)
            #pragma unroll
            for (int j = 0; j < 4; j++) s[i][j] = 0.f;
        #pragma unroll
        for (int ks = 0; ks < 4; ks++) {
            uint32_t kh4[4][4];
            #pragma unroll
            for (int ntp = 0; ntp < 4; ntp++) {
                uint32_t a = kvb + (uint32_t)((ntp*16 + (lane & 7) + ((lane >> 4) << 3)) * AT_ROW
                                              + ks*32 + (((lane >> 3) & 1) << 4));
                ldsm_x4(kh4[ntp], a);
            }
            #pragma unroll
            for (int ntp = 0; ntp < 4; ntp++) {
                mma_f16(s[2*ntp],   qh[ks], kh4[ntp]);
                mma_f16(s[2*ntp+1], qh[ks], kh4[ntp] + 2);
                mma_f16(s[2*ntp],   ql[ks], kh4[ntp]);
                mma_f16(s[2*ntp+1], ql[ks], kh4[ntp] + 2);
            }
        }
        if (t == ntiles - 1) {
            int rA = qb + warp*16 + (lane >> 2);
            int cbase = t*64 + 2*(lane & 3);
            #pragma unroll
            for (int nt = 0; nt < 8; nt++) {
                int c0 = cbase + nt*8, c1 = c0 + 1;
                if (c0 > rA)     s[nt][0] = -1e30f;
                if (c1 > rA)     s[nt][1] = -1e30f;
                if (c0 > rA + 8) s[nt][2] = -1e30f;
                if (c1 > rA + 8) s[nt][3] = -1e30f;
            }
        }
        float tmA = -1e30f, tmB = -1e30f;
        #pragma unroll
        for (int nt = 0; nt < 8; nt++) {
            tmA = fmaxf(tmA, fmaxf(s[nt][0], s[nt][1]));
            tmB = fmaxf(tmB, fmaxf(s[nt][2], s[nt][3]));
        }
        tmA = fmaxf(tmA, __shfl_xor_sync(0xffffffffu, tmA, 1));
        tmA = fmaxf(tmA, __shfl_xor_sync(0xffffffffu, tmA, 2));
        tmB = fmaxf(tmB, __shfl_xor_sync(0xffffffffu, tmB, 1));
        tmB = fmaxf(tmB, __shfl_xor_sync(0xffffffffu, tmB, 2));
        float nmA = fmaxf(mA, tmA), nmB = fmaxf(mB, tmB);
        float scA = __expf(mA - nmA), scB = __expf(mB - nmB);
        float tsA = 0.f, tsB = 0.f;
        #pragma unroll
        for (int nt = 0; nt < 8; nt++) {
            s[nt][0] = __expf(s[nt][0] - nmA);
            s[nt][1] = __expf(s[nt][1] - nmA);
            s[nt][2] = __expf(s[nt][2] - nmB);
            s[nt][3] = __expf(s[nt][3] - nmB);
            tsA += s[nt][0] + s[nt][1];
            tsB += s[nt][2] + s[nt][3];
        }
        tsA += __shfl_xor_sync(0xffffffffu, tsA, 1);
        tsA += __shfl_xor_sync(0xffffffffu, tsA, 2);
        tsB += __shfl_xor_sync(0xffffffffu, tsB, 1);
        tsB += __shfl_xor_sync(0xffffffffu, tsB, 2);
        lA = lA * scA + tsA;
        lB = lB * scB + tsB;
        #pragma unroll
        for (int nt = 0; nt < 8; nt++) {
            o[nt][0] *= scA; o[nt][1] *= scA;
            o[nt][2] *= scB; o[nt][3] *= scB;
        }
        mA = nmA; mB = nmB;
        #pragma unroll
        for (int kk = 0; kk < 4; kk++) {
            uint32_t ph[4];
            ph[0] = pack_h16x2(s[2*kk][0],   s[2*kk][1]);
            ph[1] = pack_h16x2(s[2*kk][2],   s[2*kk][3]);
            ph[2] = pack_h16x2(s[2*kk+1][0], s[2*kk+1][1]);
            ph[3] = pack_h16x2(s[2*kk+1][2], s[2*kk+1][3]);
            #pragma unroll
            for (int ntp = 0; ntp < 4; ntp++) {
                uint32_t vh4[4];
                uint32_t a = kvb + AT_ARR + (uint32_t)((kk*16 + (lane & 15)) * AT_ROW
                                                      + ntp*32 + ((lane >> 4) << 4));
                ldsm_x4_t(vh4, a);
                mma_f16(o[2*ntp],   ph, vh4);
                mma_f16(o[2*ntp+1], ph, vh4 + 2);
            }
        }
        __syncthreads();
        if (t + 2 < ntiles) load_kv(t + 2, t + 2);
    }

    float iA = 1.0f / lA, iB = 1.0f / lB;
    int qA = qb + warp*16 + (lane >> 2);
    size_t rowA = ((size_t)(b*L_ + qA)) * D_;
    size_t rowB = rowA + 8 * D_;
    int cb = h*HD_ + 2*(lane & 3);
    #pragma unroll
    for (int nt = 0; nt < 8; nt++) {
        int c = cb + nt*8;
        float a0 = o[nt][0]*iA, a1 = o[nt][1]*iA;
        float b0 = o[nt][2]*iB, b1 = o[nt][3]*iB;
        unsigned short h0,l0,h1,l1;
        split1(a0,h0,l0); split1(a1,h1,l1);
        *(uint32_t*)(out_hi + rowA + c) = (uint32_t)h0 | ((uint32_t)h1 << 16);
        *(uint32_t*)(out_lo + rowA + c) = (uint32_t)l0 | ((uint32_t)l1 << 16);
        split1(b0,h0,l0); split1(b1,h1,l1);
        *(uint32_t*)(out_hi + rowB + c) = (uint32_t)h0 | ((uint32_t)h1 << 16);
        *(uint32_t*)(out_lo + rowB + c) = (uint32_t)l0 | ((uint32_t)l1 << 16);
    }
}

// ---------------------------------------------------------------------------
// mma.sync cross-attention with tile-range skipping (seg_ids sorted), f16.
// K and V single-f16.
// ---------------------------------------------------------------------------
__global__ void __launch_bounds__(128, 2)
cross_attn_mma(const __half* __restrict__ Qh, const __half* __restrict__ Ql,
               const __half* __restrict__ Kh, const __half* __restrict__ Vh,
               const int* __restrict__ seg_ids,
               __half* __restrict__ out_hi, __half* __restrict__ out_lo) {
    extern __shared__ char smraw[];
    const uint32_t sb = (uint32_t)__cvta_generic_to_shared(smraw);
    const int tid = threadIdx.x, warp = tid >> 5, lane = tid & 31;
    const int h = blockIdx.y, b = blockIdx.z;
    const int qb = (int)blockIdx.x * 64;
    const size_t hbQ = ((size_t)(b*H_ + h)) * L_;
    const size_t hbK = ((size_t)(b*H_ + h)) * S_;

    const int rA = qb + warp*16 + (lane >> 2);
    const int segA = seg_ids[b*L_ + rA];
    const int segB = seg_ids[b*L_ + rA + 8];

    const int segF = seg_ids[b*L_ + qb];
    const int segL = seg_ids[b*L_ + qb + 63];
    int t0 = (segF - 127) >> 6; if (t0 < 0) t0 = 0;
    int t1 = segL >> 6;
    const int nte = t1 - t0 + 1;

    #pragma unroll
    for (int i = 0; i < 8; i++) {
        int id = tid + i * 128;
        int arr = id >> 9;
        int rem = id & 511;
        int row = rem >> 3, kc = rem & 7;
        const __half* p = (arr ? Ql : Qh) + (hbQ + qb + row) * HD_ + kc * 8;
        uint32_t d = sb + (uint32_t)(arr * AT_ARR + row * AT_ROW + kc * 16);
        asm volatile("cp.async.cg.shared.global [%0], [%1], 16;" :: "r"(d), "l"(p) : "memory");
    }
    auto load_kv = [&](int t, int slot) {
        uint32_t base = sb + AT_KV0 + (uint32_t)(slot & 1) * AT_STG;
        int k0 = t * 64;
        #pragma unroll
        for (int i = 0; i < 8; i++) {
            int id = tid + i * 128;
            int arr = id >> 9;
            int rem = id & 511;
            int row = rem >> 3, kc = rem & 7;
            const __half* p = (arr ? Vh : Kh) + (hbK + k0 + row) * HD_ + kc * 8;
            uint32_t d = base + (uint32_t)(arr * AT_ARR + row * AT_ROW + kc * 16);
            asm volatile("cp.async.cg.shared.global [%0], [%1], 16;" :: "r"(d), "l"(p) : "memory");
        }
        asm volatile("cp.async.commit_group;" ::: "memory");
    };
    load_kv(t0, 0);
    if (nte > 1) load_kv(t0 + 1, 1);

    uint32_t qh[4][4], ql[4][4];
    float o[8][4];
    #pragma unroll
    for (int i = 0; i < 8; i++)
        #pragma unroll
        for (int j = 0; j < 4; j++) o[i][j] = 0.f;
    float mA = -1e30f, mB = -1e30f, lA = 0.f, lB = 0.f;

    for (int tt = 0; tt < nte; tt++) {
        const int t = t0 + tt;
        if (tt + 1 < nte) { asm volatile("cp.async.wait_group 1;" ::: "memory"); }
        else              { asm volatile("cp.async.wait_group 0;" ::: "memory"); }
        __syncthreads();
        if (tt == 0) {
            #pragma unroll
            for (int ks = 0; ks < 4; ks++) {
                uint32_t a = sb + (uint32_t)((warp*16 + (lane & 15)) * AT_ROW + ks*32 + (lane >> 4) * 16);
                ldsm_x4(qh[ks], a);
                ldsm_x4(ql[ks], a + AT_ARR);
            }
        }
        const uint32_t kvb = sb + AT_KV0 + (uint32_t)(tt & 1) * AT_STG;

        float s[8][4];
        #pragma unroll
        for (int i = 0; i < 8; i++)
            #pragma unroll
            for (int j = 0; j < 4; j++) s[i][j] = 0.f;
        #pragma unroll
        for (int ks = 0; ks < 4; ks++) {
            uint32_t kh4[4][4];
            #pragma unroll
            for (int ntp = 0; ntp < 4; ntp++) {
                uint32_t a = kvb + (uint32_t)((ntp*16 + (lane & 7) + ((lane >> 4) << 3)) * AT_ROW
                                              + ks*32 + (((lane >> 3) & 1) << 4));
                ldsm_x4(kh4[ntp], a);
            }
            #pragma unroll
            for (int ntp = 0; ntp < 4; ntp++) {
                mma_f16(s[2*ntp],   qh[ks], kh4[ntp]);
                mma_f16(s[2*ntp+1], qh[ks], kh4[ntp] + 2);
                mma_f16(s[2*ntp],   ql[ks], kh4[ntp]);
                mma_f16(s[2*ntp+1], ql[ks], kh4[ntp] + 2);
            }
        }
        {
            int cbase = t*64 + 2*(lane & 3);
            #pragma unroll
            for (int nt = 0; nt < 8; nt++) {
                int c0 = cbase + nt*8, c1 = c0 + 1;
                if (c0 > segA || c0 <= segA - 128) s[nt][0] = -1e30f;
                if (c1 > segA || c1 <= segA - 128) s[nt][1] = -1e30f;
                if (c0 > segB || c0 <= segB - 128) s[nt][2] = -1e30f;
                if (c1 > segB || c1 <= segB - 128) s[nt][3] = -1e30f;
            }
        }
        float tmA = -1e30f, tmB = -1e30f;
        #pragma unroll
        for (int nt = 0; nt < 8; nt++) {
            tmA = fmaxf(tmA, fmaxf(s[nt][0], s[nt][1]));
            tmB = fmaxf(tmB, fmaxf(s[nt][2], s[nt][3]));
        }
        tmA = fmaxf(tmA, __shfl_xor_sync(0xffffffffu, tmA, 1));
        tmA = fmaxf(tmA, __shfl_xor_sync(0xffffffffu, tmA, 2));
        tmB = fmaxf(tmB, __shfl_xor_sync(0xffffffffu, tmB, 1));
        tmB = fmaxf(tmB, __shfl_xor_sync(0xffffffffu, tmB, 2));
        float nmA = fmaxf(mA, tmA), nmB = fmaxf(mB, tmB);
        float scA = __expf(mA - nmA), scB = __expf(mB - nmB);
        float tsA = 0.f, tsB = 0.f;
        #pragma unroll
        for (int nt = 0; nt < 8; nt++) {
            s[nt][0] = __expf(s[nt][0] - nmA);
            s[nt][1] = __expf(s[nt][1] - nmA);
            s[nt][2] = __expf(s[nt][2] - nmB);
            s[nt][3] = __expf(s[nt][3] - nmB);
            tsA += s[nt][0] + s[nt][1];
            tsB += s[nt][2] + s[nt][3];
        }
        tsA += __shfl_xor_sync(0xffffffffu, tsA, 1);
        tsA += __shfl_xor_sync(0xffffffffu, tsA, 2);
        tsB += __shfl_xor_sync(0xffffffffu, tsB, 1);
        tsB += __shfl_xor_sync(0xffffffffu, tsB, 2);
        lA = lA * scA + tsA;
        lB = lB * scB + tsB;
        #pragma unroll
        for (int nt = 0; nt < 8; nt++) {
            o[nt][0] *= scA; o[nt][1] *= scA;
            o[nt][2] *= scB; o[nt][3] *= scB;
        }
        mA = nmA; mB = nmB;
        #pragma unroll
        for (int kk = 0; kk < 4; kk++) {
            uint32_t ph[4];
            ph[0] = pack_h16x2(s[2*kk][0],   s[2*kk][1]);
            ph[1] = pack_h16x2(s[2*kk][2],   s[2*kk][3]);
            ph[2] = pack_h16x2(s[2*kk+1][0], s[2*kk+1][1]);
            ph[3] = pack_h16x2(s[2*kk+1][2], s[2*kk+1][3]);
            #pragma unroll
            for (int ntp = 0; ntp < 4; ntp++) {
                uint32_t vh4[4];
                uint32_t a = kvb + AT_ARR + (uint32_t)((kk*16 + (lane & 15)) * AT_ROW
                                                      + ntp*32 + ((lane >> 4) << 4));
                ldsm_x4_t(vh4, a);
                mma_f16(o[2*ntp],   ph, vh4);
                mma_f16(o[2*ntp+1], ph, vh4 + 2);
            }
        }
        __syncthreads();
        if (tt + 2 < nte) load_kv(t0 + tt + 2, tt + 2);
    }

    float iA = 1.0f / lA, iB = 1.0f / lB;
    size_t rowA = ((size_t)(b*L_ + rA)) * D_;
    size_t rowB = rowA + 8 * D_;
    int cb = h*HD_ + 2*(lane & 3);
    #pragma unroll
    for (int nt = 0; nt < 8; nt++) {
        int c = cb + nt*8;
        float a0 = o[nt][0]*iA, a1 = o[nt][1]*iA;
        float b0 = o[nt][2]*iB, b1 = o[nt][3]*iB;
        unsigned short h0,l0,h1,l1;
        split1(a0,h0,l0); split1(a1,h1,l1);
        *(uint32_t*)(out_hi + rowA + c) = (uint32_t)h0 | ((uint32_t)h1 << 16);
        *(uint32_t*)(out_lo + rowA + c) = (uint32_t)l0 | ((uint32_t)l1 << 16);
        split1(b0,h0,l0); split1(b1,h1,l1);
        *(uint32_t*)(out_hi + rowB + c) = (uint32_t)h0 | ((uint32_t)h1 << 16);
        *(uint32_t*)(out_lo + rowB + c) = (uint32_t)l0 | ((uint32_t)l1 << 16);
    }
}

// ---------------------------------------------------------------------------
// Launch
// ---------------------------------------------------------------------------
static inline void split_launch(const float* src, __half* hi, __half* lo, size_t n) {
    int n4 = (int)(n / 4);
    split_k<<<n4 / 1024, 256>>>(src, hi, lo);
}

extern "C" void kernel_launch(void* const* d_in, const int* in_sizes, int n_in,
                              void* d_out, int out_size) {
    const float* x      = (const float*)d_in[0];
    const float* memory = (const float*)d_in[1];
    const int*   seg    = (const int*)  d_in[2];
    const float* Wqkv   = (const float*)d_in[3];
    const float* bqkv   = (const float*)d_in[4];
    const float* Wo     = (const float*)d_in[5];
    const float* bo     = (const float*)d_in[6];
    const float* Wq_c   = (const float*)d_in[7];
    const float* Wkv_c  = (const float*)d_in[8];
    const float* Wo_c   = (const float*)d_in[9];
    const float* Wg     = (const float*)d_in[10];
    const float* Wu     = (const float*)d_in[11];
    const float* Wd     = (const float*)d_in[12];
    const float* n1     = (const float*)d_in[13];
    const float* n2     = (const float*)d_in[14];
    const float* n3     = (const float*)d_in[15];
    const float* nf     = (const float*)d_in[16];

    cudaFuncSetAttribute(gemm_f16s<1,false>, cudaFuncAttributeMaxDynamicSharedMemorySize, GSMEM);
    cudaFuncSetAttribute(gemm_f16s<2,false>, cudaFuncAttributeMaxDynamicSharedMemorySize, GSMEM);
    cudaFuncSetAttribute(gemm_f16s<3,false>, cudaFuncAttributeMaxDynamicSharedMemorySize, GSMEM);
    cudaFuncSetAttribute(gemm_f16s<4,false>, cudaFuncAttributeMaxDynamicSharedMemorySize, GSMEM);
    cudaFuncSetAttribute(gemm_f16s<6,false>, cudaFuncAttributeMaxDynamicSharedMemorySize, GSMEM);
    cudaFuncSetAttribute(gemm_f16s<7,false>, cudaFuncAttributeMaxDynamicSharedMemorySize, GSMEM);
    cudaFuncSetAttribute(self_attn_mma,  cudaFuncAttributeMaxDynamicSharedMemorySize, AT_SMEM);
    cudaFuncSetAttribute(cross_attn_mma, cudaFuncAttributeMaxDynamicSharedMemorySize, AT_SMEM);

    float *xb;
    __half *hhi, *hlo, *ahi, *alo, *chi, *clo, *gshi, *gslo, *mhi, *mlo, *whi, *wlo;
    __half *sqh, *sql, *skh, *skl, *svh, *svl;
    __half *ckh, *ckl, *cvh, *cvl;
    cudaGetSymbolAddress((void**)&xb,   g_x);
    cudaGetSymbolAddress((void**)&hhi,  g_h_hi);  cudaGetSymbolAddress((void**)&hlo,  g_h_lo);
    cudaGetSymbolAddress((void**)&ahi,  g_at_hi); cudaGetSymbolAddress((void**)&alo,  g_at_lo);
    cudaGetSymbolAddress((void**)&chi,  g_co_hi); cudaGetSymbolAddress((void**)&clo,  g_co_lo);
    cudaGetSymbolAddress((void**)&gshi, g_gs_hi); cudaGetSymbolAddress((void**)&gslo, g_gs_lo);
    cudaGetSymbolAddress((void**)&mhi,  g_m_hi);  cudaGetSymbolAddress((void**)&mlo,  g_m_lo);
    cudaGetSymbolAddress((void**)&whi,  g_w_hi);  cudaGetSymbolAddress((void**)&wlo,  g_w_lo);
    cudaGetSymbolAddress((void**)&sqh,  g_sqh);   cudaGetSymbolAddress((void**)&sql,  g_sql);
    cudaGetSymbolAddress((void**)&skh,  g_skh);   cudaGetSymbolAddress((void**)&skl,  g_skl);
    cudaGetSymbolAddress((void**)&svh,  g_svh);   cudaGetSymbolAddress((void**)&svl,  g_svl);
    cudaGetSymbolAddress((void**)&ckh,  g_ckh);   cudaGetSymbolAddress((void**)&ckl,  g_ckl);
    cudaGetSymbolAddress((void**)&cvh,  g_cvh);   cudaGetSymbolAddress((void**)&cvl,  g_cvl);

    rope_cache_k<<<256, 256>>>();

    split_launch(Wqkv,  whi + O_WQKV, wlo + O_WQKV, NL*SZ_WQKV);
    split_launch(Wo,    whi + O_WO,   wlo + O_WO,   NL*SZ_WO);
    split_launch(Wq_c,  whi + O_WQC,  wlo + O_WQC,  NL*SZ_WQC);
    split_launch(Wkv_c, whi + O_WKVC, wlo + O_WKVC, NL*SZ_WKVC);
    split_launch(Wo_c,  whi + O_WOC,  wlo + O_WOC,  NL*SZ_WOC);
    for (int l = 0; l < NL; l++) {
        int blocks = (int)((size_t)F_*D_/4/1024);
        split_ilv_k<<<blocks, 256>>>(Wg + (size_t)l*F_*D_,
            whi + O_WGU + l*SZ_WGU, wlo + O_WGU + l*SZ_WGU, 0);
        split_ilv_k<<<blocks, 256>>>(Wu + (size_t)l*F_*D_,
            whi + O_WGU + l*SZ_WGU, wlo + O_WGU + l*SZ_WGU, 1);
    }
    split_launch(Wd,    whi + O_WD,   wlo + O_WD,   NL*SZ_WD);
    split_launch(memory, mhi, mlo, (size_t)B_*S_*D_);

    // upfront: all 4 layers' cross K/V in one GEMM (layer-independent)
    gemm_f16s<7,false><<<dim3(NL*2*D_/128, (B_*S_)/256), 256, GSMEM>>>(
        mhi, mlo, whi + O_WKVC, wlo + O_WKVC, nullptr, nullptr, nullptr,
        ckh, ckl, cvh, cvl, nullptr, nullptr, NL*2*D_, D_);

    const dim3 self_grid(L_/64, H_, B_);
    const dim3 cross_grid(L_/64, H_, B_);

    for (int l = 0; l < NL; l++) {
        const __half* wqkv_h = whi + O_WQKV + l*SZ_WQKV;
        const __half* wqkv_l = wlo + O_WQKV + l*SZ_WQKV;
        const __half* wo_h   = whi + O_WO   + l*SZ_WO;
        const __half* wo_l   = wlo + O_WO   + l*SZ_WO;
        const __half* wqc_h  = whi + O_WQC  + l*SZ_WQC;
        const __half* wqc_l  = wlo + O_WQC  + l*SZ_WQC;
        const __half* woc_h  = whi + O_WOC  + l*SZ_WOC;
        const __half* woc_l  = wlo + O_WOC  + l*SZ_WOC;
        const __half* wgu_h  = whi + O_WGU  + l*SZ_WGU;
        const __half* wgu_l  = wlo + O_WGU  + l*SZ_WGU;
        const __half* wd_h   = whi + O_WD   + l*SZ_WD;
        const __half* wd_l   = wlo + O_WD   + l*SZ_WD;

        const float* xsrc = (l == 0) ? x : xb;    // residual stream source

        // --- self attention block (QKV GEMM 2-term; fuses bias+RoPE+split) ---
        rmsnorm_split_k<<<M_, 256>>>(xsrc, n1 + l*D_, hhi, hlo);
        gemm_f16s<6,false><<<dim3(3*D_/128, M_/256), 256, GSMEM>>>(
            hhi, hlo, wqkv_h, wqkv_l, bqkv + l*3*D_, nullptr, nullptr,
            sqh, sql, skh, skl, svh, svl, 3*D_, D_);
        self_attn_mma<<<self_grid, 128, AT_SMEM>>>(sqh, sql, skh, svh, ahi, alo);
        gemm_f16s<1,false><<<dim3(D_/128, M_/256), 256, GSMEM>>>(
            ahi, alo, wo_h, wo_l, bo + l*D_, xb, xsrc,
            nullptr, nullptr, nullptr, nullptr, nullptr, nullptr, D_, D_);

        // --- cross attention block (all 2-term) ---
        rmsnorm_split_k<<<M_, 256>>>(xb, n2 + l*D_, hhi, hlo);
        gemm_f16s<4,false><<<dim3(D_/128, M_/256), 256, GSMEM>>>(
            hhi, hlo, wqc_h, wqc_l, nullptr, nullptr, nullptr,
            sqh, sql, nullptr, nullptr, nullptr, nullptr, D_, D_);
        cross_attn_mma<<<cross_grid, 128, AT_SMEM>>>(
            sqh, sql, ckh + l*CATN, cvh + l*CATN, seg, chi, clo);
        gemm_f16s<2,false><<<dim3(D_/128, M_/256), 256, GSMEM>>>(
            chi, clo, woc_h, woc_l, nullptr, xb, xb,
            nullptr, nullptr, nullptr, nullptr, nullptr, nullptr, D_, D_);

        // --- MLP block (2-term f16 linear paths) ---
        rmsnorm_split_k<<<M_, 256>>>(xb, n3 + l*D_, hhi, hlo);
        gemm_f16s<3,false><<<dim3(2*F_/128, M_/256), 256, GSMEM>>>(
            hhi, hlo, wgu_h, wgu_l, nullptr, nullptr, nullptr,
            gshi, gslo, nullptr, nullptr, nullptr, nullptr, 2*F_, D_);
        gemm_f16s<2,false><<<dim3(D_/128, M_/256), 256, GSMEM>>>(
            gshi, gslo, wd_h, wd_l, nullptr, xb, xb,
            nullptr, nullptr, nullptr, nullptr, nullptr, nullptr, D_, F_);
    }

    rmsnorm_k<<<M_, 256>>>(xb, nf, (float*)d_out);
}